// round 1
// baseline (speedup 1.0000x reference)
#include <cuda_runtime.h>
#include <cuda_bf16.h>
#include <math.h>

// Problem constants
#define BB    8192
#define DIN   2048
#define MM    1600
#define CC    20
#define SS    80
#define OUTN  3000

// ---------------------------------------------------------------------------
// Scratch (static device globals: allocation-free per harness rules)
// ---------------------------------------------------------------------------
__device__ float g_h0[(size_t)BB * MM];
__device__ float g_h1[(size_t)BB * MM];
__device__ float g_z [(size_t)BB * MM];

// ---------------------------------------------------------------------------
// Kernel A: C[M,N] = A[M,K] * B[N,K]^T + bias[N]   (NT GEMM, fp32)
// Tiles: 128x128x16, 256 threads, 8x8 per thread.
// M divisible by 128, K divisible by 16 for all call sites; N may be ragged.
// ---------------------------------------------------------------------------
__global__ __launch_bounds__(256)
void gemm_nt_bias(const float* __restrict__ A, const float* __restrict__ B,
                  const float* __restrict__ bias, float* __restrict__ C,
                  int M, int N, int K)
{
    __shared__ float As[16][132];
    __shared__ float Bs[16][132];

    const int tid = threadIdx.x;
    const int tx  = tid % 16;           // 16 col groups * 8 = 128
    const int ty  = tid / 16;           // 16 row groups * 8 = 128
    const int m0  = blockIdx.y * 128;
    const int n0  = blockIdx.x * 128;

    const int lrow = tid >> 2;          // 0..63
    const int lc4  = tid & 3;           // 0..3  (k offset = lc4*4)

    float acc[8][8];
#pragma unroll
    for (int i = 0; i < 8; ++i)
#pragma unroll
        for (int j = 0; j < 8; ++j) acc[i][j] = 0.0f;

    for (int k0 = 0; k0 < K; k0 += 16) {
        // load A tile (always in-bounds)
#pragma unroll
        for (int r = 0; r < 2; ++r) {
            int row = lrow + r * 64;
            float4 v = *(const float4*)&A[(size_t)(m0 + row) * K + k0 + lc4 * 4];
            As[lc4 * 4 + 0][row] = v.x;
            As[lc4 * 4 + 1][row] = v.y;
            As[lc4 * 4 + 2][row] = v.z;
            As[lc4 * 4 + 3][row] = v.w;
        }
        // load B tile (guard ragged N)
#pragma unroll
        for (int r = 0; r < 2; ++r) {
            int row = lrow + r * 64;
            int n = n0 + row;
            float4 v = make_float4(0.f, 0.f, 0.f, 0.f);
            if (n < N)
                v = *(const float4*)&B[(size_t)n * K + k0 + lc4 * 4];
            Bs[lc4 * 4 + 0][row] = v.x;
            Bs[lc4 * 4 + 1][row] = v.y;
            Bs[lc4 * 4 + 2][row] = v.z;
            Bs[lc4 * 4 + 3][row] = v.w;
        }
        __syncthreads();

#pragma unroll
        for (int kk = 0; kk < 16; ++kk) {
            float a[8], b[8];
            float4 a0 = *(const float4*)&As[kk][ty * 8];
            float4 a1 = *(const float4*)&As[kk][ty * 8 + 4];
            float4 b0 = *(const float4*)&Bs[kk][tx * 8];
            float4 b1 = *(const float4*)&Bs[kk][tx * 8 + 4];
            a[0]=a0.x; a[1]=a0.y; a[2]=a0.z; a[3]=a0.w;
            a[4]=a1.x; a[5]=a1.y; a[6]=a1.z; a[7]=a1.w;
            b[0]=b0.x; b[1]=b0.y; b[2]=b0.z; b[3]=b0.w;
            b[4]=b1.x; b[5]=b1.y; b[6]=b1.z; b[7]=b1.w;
#pragma unroll
            for (int i = 0; i < 8; ++i)
#pragma unroll
                for (int j = 0; j < 8; ++j)
                    acc[i][j] = fmaf(a[i], b[j], acc[i][j]);
        }
        __syncthreads();
    }

#pragma unroll
    for (int i = 0; i < 8; ++i) {
        int m = m0 + ty * 8 + i;
#pragma unroll
        for (int j = 0; j < 8; ++j) {
            int n = n0 + tx * 8 + j;
            if (n < N)
                C[(size_t)m * N + n] = acc[i][j] + bias[n];
        }
    }
}

// ---------------------------------------------------------------------------
// Kernel B: fused bilinear + signed-sqrt + per-chunk L2 normalize.
//   z[b,c,q] = sum_{s,t} h0[b,c,s] * Wb[c,q,s,t] * h1[b,c,t] + bb[c,q]
//   zs = sign(z)*sqrt(|z|);  out = zs / max(||zs||_2 over q, 1e-12)
// One CTA = 128 batch rows x 1 chunk c. 320 threads: tx in [0,20) (q groups
// of 4), ty in [0,16) (b groups of 8). K-loop: s outer (80), t inner (80).
// Per s: acc2[i][j] += h1[b_i,t]*Wb[q_j,s,t]; then acc[i][j] += h0[b_i,s]*acc2.
// ---------------------------------------------------------------------------
#define BIL_THREADS 320
#define H1_PITCH 132   // 128 rows + pad, multiple of 4 for float4 reads
#define WS_PITCH 84    // 80 q + pad, multiple of 4
#define ZB_PITCH 84    // 80 q + pad, multiple of 4

__global__ __launch_bounds__(BIL_THREADS)
void bilinear_kernel(const float* __restrict__ h0g, const float* __restrict__ h1g,
                     const float* __restrict__ Wb, const float* __restrict__ bbv,
                     float* __restrict__ zg)
{
    extern __shared__ float smem[];
    float* h0s  = smem;                    // [128][80]
    float* h1sT = h0s  + 128 * 80;         // [80][H1_PITCH]  h1sT[t][b]
    float* wsT  = h1sT + 80 * H1_PITCH;    // [80][WS_PITCH]  wsT[t][q]
    float* zbuf = wsT  + 80 * WS_PITCH;    // [128][ZB_PITCH]
    float* scl  = zbuf + 128 * ZB_PITCH;   // [128]

    const int tid   = threadIdx.x;
    const int c     = blockIdx.y;
    const int mbase = blockIdx.x * 128;

    // ---- load h0 tile (row-major) and h1 tile (transposed) ----
#pragma unroll
    for (int k = 0; k < 8; ++k) {
        int idx = tid + k * BIL_THREADS;   // 0..2559
        int b = idx / 20;
        int f = idx % 20;                  // float4 index along s
        size_t goff = (size_t)(mbase + b) * MM + c * SS + f * 4;
        float4 v0 = *(const float4*)&h0g[goff];
        *(float4*)&h0s[b * 80 + f * 4] = v0;
        float4 v1 = *(const float4*)&h1g[goff];
        h1sT[(f * 4 + 0) * H1_PITCH + b] = v1.x;
        h1sT[(f * 4 + 1) * H1_PITCH + b] = v1.y;
        h1sT[(f * 4 + 2) * H1_PITCH + b] = v1.z;
        h1sT[(f * 4 + 3) * H1_PITCH + b] = v1.w;
    }

    const int tx = tid % 20;   // q = tx*4 + j
    const int ty = tid / 20;   // b = ty*8 + i

    float acc[8][4];
#pragma unroll
    for (int i = 0; i < 8; ++i)
#pragma unroll
        for (int j = 0; j < 4; ++j) acc[i][j] = 0.0f;

    const float* WbC = Wb + (size_t)c * SS * SS * SS;

    for (int s = 0; s < SS; ++s) {
        __syncthreads();   // previous wsT fully consumed (also covers initial tile loads)
        // load wsT[t][q] = Wb[c, q, s, t]
#pragma unroll
        for (int k = 0; k < 5; ++k) {
            int idx = tid + k * BIL_THREADS; // 0..1599
            int q = idx / 20;
            int f = idx % 20;
            float4 w = *(const float4*)&WbC[(size_t)q * (SS * SS) + s * SS + f * 4];
            wsT[(f * 4 + 0) * WS_PITCH + q] = w.x;
            wsT[(f * 4 + 1) * WS_PITCH + q] = w.y;
            wsT[(f * 4 + 2) * WS_PITCH + q] = w.z;
            wsT[(f * 4 + 3) * WS_PITCH + q] = w.w;
        }
        __syncthreads();

        float acc2[8][4];
#pragma unroll
        for (int i = 0; i < 8; ++i)
#pragma unroll
            for (int j = 0; j < 4; ++j) acc2[i][j] = 0.0f;

#pragma unroll 2
        for (int t = 0; t < SS; ++t) {
            float4 w4 = *(const float4*)&wsT[t * WS_PITCH + tx * 4];
            float4 hA = *(const float4*)&h1sT[t * H1_PITCH + ty * 8];
            float4 hB = *(const float4*)&h1sT[t * H1_PITCH + ty * 8 + 4];
            float hv[8];
            hv[0]=hA.x; hv[1]=hA.y; hv[2]=hA.z; hv[3]=hA.w;
            hv[4]=hB.x; hv[5]=hB.y; hv[6]=hB.z; hv[7]=hB.w;
            float wv[4];
            wv[0]=w4.x; wv[1]=w4.y; wv[2]=w4.z; wv[3]=w4.w;
#pragma unroll
            for (int i = 0; i < 8; ++i)
#pragma unroll
                for (int j = 0; j < 4; ++j)
                    acc2[i][j] = fmaf(hv[i], wv[j], acc2[i][j]);
        }

        // fold in h0[b, s]
        float h0v[8];
#pragma unroll
        for (int i = 0; i < 8; ++i) h0v[i] = h0s[(ty * 8 + i) * 80 + s];
#pragma unroll
        for (int i = 0; i < 8; ++i)
#pragma unroll
            for (int j = 0; j < 4; ++j)
                acc[i][j] = fmaf(h0v[i], acc2[i][j], acc[i][j]);
    }

    __syncthreads();
    // write raw z (+bias) to smem
#pragma unroll
    for (int i = 0; i < 8; ++i)
#pragma unroll
        for (int j = 0; j < 4; ++j)
            zbuf[(ty * 8 + i) * ZB_PITCH + tx * 4 + j] =
                acc[i][j] + bbv[c * SS + tx * 4 + j];
    __syncthreads();

    // per-row scale: ||signed_sqrt(z)||^2 == sum(|z|)
    if (tid < 128) {
        float ssum = 0.0f;
#pragma unroll 4
        for (int q = 0; q < SS; ++q) ssum += fabsf(zbuf[tid * ZB_PITCH + q]);
        float nrm = sqrtf(ssum);
        scl[tid] = 1.0f / fmaxf(nrm, 1e-12f);
    }
    __syncthreads();

    // apply signed sqrt + normalize, write out (coalesced float4)
#pragma unroll
    for (int k = 0; k < 8; ++k) {
        int idx = tid + k * BIL_THREADS;
        int b = idx / 20;
        int f = idx % 20;
        float sc = scl[b];
        float4 v = *(const float4*)&zbuf[b * ZB_PITCH + f * 4];
        float4 o;
        o.x = copysignf(sqrtf(fabsf(v.x)), v.x) * sc;
        o.y = copysignf(sqrtf(fabsf(v.y)), v.y) * sc;
        o.z = copysignf(sqrtf(fabsf(v.z)), v.z) * sc;
        o.w = copysignf(sqrtf(fabsf(v.w)), v.w) * sc;
        *(float4*)&zg[(size_t)(mbase + b) * MM + c * SS + f * 4] = o;
    }
}

// ---------------------------------------------------------------------------
// launch
// ---------------------------------------------------------------------------
extern "C" void kernel_launch(void* const* d_in, const int* in_sizes, int n_in,
                              void* d_out, int out_size)
{
    (void)in_sizes; (void)n_in; (void)out_size;
    const float* x0   = (const float*)d_in[0];
    const float* x1   = (const float*)d_in[1];
    const float* W0   = (const float*)d_in[2];
    const float* b0   = (const float*)d_in[3];
    const float* W1   = (const float*)d_in[4];
    const float* b1   = (const float*)d_in[5];
    const float* Wb   = (const float*)d_in[6];
    const float* bb   = (const float*)d_in[7];
    const float* Wout = (const float*)d_in[8];
    const float* bout = (const float*)d_in[9];
    float* out = (float*)d_out;

    float *h0p, *h1p, *zp;
    cudaGetSymbolAddress((void**)&h0p, g_h0);
    cudaGetSymbolAddress((void**)&h1p, g_h1);
    cudaGetSymbolAddress((void**)&zp,  g_z);

    // h0 = x0 @ W0^T + b0 ; h1 = x1 @ W1^T + b1
    {
        dim3 grid((MM + 127) / 128, BB / 128);
        gemm_nt_bias<<<grid, 256>>>(x0, W0, b0, h0p, BB, MM, DIN);
        gemm_nt_bias<<<grid, 256>>>(x1, W1, b1, h1p, BB, MM, DIN);
    }

    // fused bilinear + signed sqrt + per-chunk normalize
    {
        const int smem_floats = 128 * 80 + 80 * H1_PITCH + 80 * WS_PITCH
                              + 128 * ZB_PITCH + 128;
        const size_t smem_bytes = (size_t)smem_floats * sizeof(float);
        cudaFuncSetAttribute(bilinear_kernel,
                             cudaFuncAttributeMaxDynamicSharedMemorySize,
                             (int)smem_bytes);
        dim3 grid(BB / 128, CC);
        bilinear_kernel<<<grid, BIL_THREADS, smem_bytes>>>(h0p, h1p, Wb, bb, zp);
    }

    // out = z @ Wout^T + bout
    {
        dim3 grid((OUTN + 127) / 128, BB / 128);
        gemm_nt_bias<<<grid, 256>>>(zp, Wout, bout, out, BB, OUTN, MM);
    }
}

// round 3
// speedup vs baseline: 1.3989x; 1.3989x over previous
#include <cuda_runtime.h>
#include <cuda_bf16.h>
#include <math.h>
#include <stdint.h>

// Problem constants
#define BB    8192
#define DIN   2048
#define MM    1600
#define CC    20
#define SS    80
#define OUTN  3000

// ---------------------------------------------------------------------------
// Scratch (static device globals: allocation-free per harness rules)
// ---------------------------------------------------------------------------
__device__ float g_h0[(size_t)BB * MM];
__device__ float g_h1[(size_t)BB * MM];
__device__ float g_z [(size_t)BB * MM];

__device__ __nv_bfloat16 g_x0hi[(size_t)BB * DIN];
__device__ __nv_bfloat16 g_x0lo[(size_t)BB * DIN];
__device__ __nv_bfloat16 g_x1hi[(size_t)BB * DIN];
__device__ __nv_bfloat16 g_x1lo[(size_t)BB * DIN];
__device__ __nv_bfloat16 g_W0hi[(size_t)MM * DIN];
__device__ __nv_bfloat16 g_W0lo[(size_t)MM * DIN];
__device__ __nv_bfloat16 g_W1hi[(size_t)MM * DIN];
__device__ __nv_bfloat16 g_W1lo[(size_t)MM * DIN];
__device__ __nv_bfloat16 g_Wouthi[(size_t)OUTN * MM];
__device__ __nv_bfloat16 g_Woutlo[(size_t)OUTN * MM];
__device__ __nv_bfloat16 g_zhi[(size_t)BB * MM];
__device__ __nv_bfloat16 g_zlo[(size_t)BB * MM];

// ---------------------------------------------------------------------------
// Low-level helpers (portable ISA only: cp.async / ldmatrix / mma.sync)
// ---------------------------------------------------------------------------
__device__ __forceinline__ uint32_t smem_u32(const void* p) {
    uint32_t a;
    asm("{ .reg .u64 t; cvta.to.shared.u64 t, %1; cvt.u32.u64 %0, t; }"
        : "=r"(a) : "l"(p));
    return a;
}

#define CP16(dst, src) \
    asm volatile("cp.async.cg.shared.global [%0], [%1], 16;" \
                 :: "r"(dst), "l"(src) : "memory")
#define CP16P(dst, src, nbytes) \
    asm volatile("cp.async.cg.shared.global [%0], [%1], 16, %2;" \
                 :: "r"(dst), "l"(src), "r"(nbytes) : "memory")
#define CP_COMMIT() asm volatile("cp.async.commit_group;" ::: "memory")
#define CP_WAIT0()  asm volatile("cp.async.wait_group 0;" ::: "memory")
#define CP_WAIT1()  asm volatile("cp.async.wait_group 1;" ::: "memory")

#define LDX4(r0, r1, r2, r3, addr) \
    asm volatile("ldmatrix.sync.aligned.m8n8.x4.shared.b16 {%0,%1,%2,%3}, [%4];" \
                 : "=r"(r0), "=r"(r1), "=r"(r2), "=r"(r3) : "r"(addr))

#define MMA16816(d0, d1, d2, d3, a0, a1, a2, a3, b0, b1) \
    asm volatile("mma.sync.aligned.m16n8k16.row.col.f32.bf16.bf16.f32 " \
                 "{%0,%1,%2,%3}, {%4,%5,%6,%7}, {%8,%9}, {%0,%1,%2,%3};" \
                 : "+f"(d0), "+f"(d1), "+f"(d2), "+f"(d3) \
                 : "r"(a0), "r"(a1), "r"(a2), "r"(a3), "r"(b0), "r"(b1))

// ---------------------------------------------------------------------------
// Split fp32 -> bf16 hi + bf16 lo (a = hi + lo + O(2^-17 a))
// ---------------------------------------------------------------------------
__global__ __launch_bounds__(256)
void split_bf16(const float* __restrict__ in, __nv_bfloat16* __restrict__ hi,
                __nv_bfloat16* __restrict__ lo, int n4)
{
    int i = blockIdx.x * blockDim.x + threadIdx.x;
    if (i >= n4) return;
    float4 v = ((const float4*)in)[i];
    __nv_bfloat16 h0 = __float2bfloat16(v.x);
    __nv_bfloat16 h1 = __float2bfloat16(v.y);
    __nv_bfloat16 h2 = __float2bfloat16(v.z);
    __nv_bfloat16 h3 = __float2bfloat16(v.w);
    __nv_bfloat16 l0 = __float2bfloat16(v.x - __bfloat162float(h0));
    __nv_bfloat16 l1 = __float2bfloat16(v.y - __bfloat162float(h1));
    __nv_bfloat16 l2 = __float2bfloat16(v.z - __bfloat162float(h2));
    __nv_bfloat16 l3 = __float2bfloat16(v.w - __bfloat162float(h3));
    __nv_bfloat162 hv0 = __nv_bfloat162(h0, h1), hv1 = __nv_bfloat162(h2, h3);
    __nv_bfloat162 lv0 = __nv_bfloat162(l0, l1), lv1 = __nv_bfloat162(l2, l3);
    uint2 hp, lp;
    hp.x = *(uint32_t*)&hv0; hp.y = *(uint32_t*)&hv1;
    lp.x = *(uint32_t*)&lv0; lp.y = *(uint32_t*)&lv1;
    ((uint2*)hi)[i] = hp;
    ((uint2*)lo)[i] = lp;
}

// ---------------------------------------------------------------------------
// mma.sync NT GEMM: C[M,N] = A[M,K] * B[N,K]^T + bias[N], fp32 out.
// A,B given as bf16 hi/lo pairs; 3-product fp32 emulation.
// CTA tile 128x128, BK=64, 2-stage cp.async pipeline, 256 thr (8 warps 64x32).
// ---------------------------------------------------------------------------
#define BK 64
#define STAGE_BYTES 65536   // 4 tiles (Ahi,Alo,Bhi,Blo) * 128 rows * 128 B
#define GEMM_SMEM   (2 * STAGE_BYTES)

struct GemmPtrs {
    const __nv_bfloat16 *Ahi, *Alo, *Bhi, *Blo;
};

__device__ __forceinline__ void issue_stage(
    uint32_t sbase, int stage, GemmPtrs p,
    int m0, int n0, int k0, int N, int K, int tid)
{
    uint32_t st = sbase + stage * STAGE_BYTES;
#pragma unroll
    for (int i = 0; i < 4; ++i) {
        int idx = tid + i * 256;           // 0..1023
        int r = idx >> 3;                  // row 0..127
        int c = idx & 7;                   // 16B chunk 0..7
        uint32_t dst = (uint32_t)(r * 128 + ((c ^ (r & 7)) << 4));
        size_t aoff = (size_t)(m0 + r) * K + k0 + c * 8;
        CP16(st + dst,         (const char*)(p.Ahi + aoff));
        CP16(st + 16384 + dst, (const char*)(p.Alo + aoff));
        int n = n0 + r;
        int pred = (n < N) ? 16 : 0;
        int ncl = (n < N) ? n : (N - 1);
        size_t boff = (size_t)ncl * K + k0 + c * 8;
        CP16P(st + 32768 + dst, (const char*)(p.Bhi + boff), pred);
        CP16P(st + 49152 + dst, (const char*)(p.Blo + boff), pred);
    }
    CP_COMMIT();
}

__global__ __launch_bounds__(256, 1)
void tc_gemm_nt(const __nv_bfloat16* __restrict__ Ahi,
                const __nv_bfloat16* __restrict__ Alo,
                const __nv_bfloat16* __restrict__ Bhi,
                const __nv_bfloat16* __restrict__ Blo,
                const float* __restrict__ bias,
                float* __restrict__ C,
                int N, int K)
{
    extern __shared__ __align__(128) char smem[];
    const uint32_t sb = smem_u32(smem);

    const int tid = threadIdx.x;
    const int l   = tid & 31;
    const int wid = tid >> 5;
    const int wm  = wid & 1;     // 0..1 -> 64-row half
    const int wn  = wid >> 1;    // 0..3 -> 32-col quarter
    const int m0  = blockIdx.y * 128;
    const int n0  = blockIdx.x * 128;
    const int niter = K / BK;

    GemmPtrs p; p.Ahi = Ahi; p.Alo = Alo; p.Bhi = Bhi; p.Blo = Blo;

    // per-lane ldmatrix addressing (swizzle: chunk ^= row&7)
    const uint32_t aRow  = (uint32_t)(wm * 64 + (l & 15));
    const uint32_t aXor  = aRow & 7;
    const uint32_t aHalf = (uint32_t)(l >> 4);           // k 16B-chunk offset
    const uint32_t bRow  = (uint32_t)(wn * 32 + (l & 7) + ((l >> 4) << 3));
    const uint32_t bXor  = bRow & 7;
    const uint32_t bHalf = (uint32_t)((l >> 3) & 1);

    float d[4][4][4];
#pragma unroll
    for (int mg = 0; mg < 4; ++mg)
#pragma unroll
        for (int ng = 0; ng < 4; ++ng)
#pragma unroll
            for (int k = 0; k < 4; ++k) d[mg][ng][k] = 0.0f;

    issue_stage(sb, 0, p, m0, n0, 0, N, K, tid);

    for (int it = 0; it < niter; ++it) {
        if (it + 1 < niter) {
            issue_stage(sb, (it + 1) & 1, p, m0, n0, (it + 1) * BK, N, K, tid);
            CP_WAIT1();
        } else {
            CP_WAIT0();
        }
        __syncthreads();

        const uint32_t st = sb + (it & 1) * STAGE_BYTES;
        const uint32_t sAhi = st;
        const uint32_t sAlo = st + 16384;
        const uint32_t sBhi = st + 32768;
        const uint32_t sBlo = st + 49152;

#pragma unroll
        for (int kk = 0; kk < 4; ++kk) {
            // fragment loads
            uint32_t ahi[4][4], alo[4][4], bhi[2][4], blo[2][4];
            const uint32_t ach = (((2 * kk + aHalf) ^ aXor) << 4);
            const uint32_t bch = (((2 * kk + bHalf) ^ bXor) << 4);
#pragma unroll
            for (int mg = 0; mg < 4; ++mg) {
                uint32_t off = (aRow + mg * 16) * 128 + ach;
                LDX4(ahi[mg][0], ahi[mg][1], ahi[mg][2], ahi[mg][3], sAhi + off);
                LDX4(alo[mg][0], alo[mg][1], alo[mg][2], alo[mg][3], sAlo + off);
            }
#pragma unroll
            for (int bq = 0; bq < 2; ++bq) {
                uint32_t off = (bRow + bq * 16) * 128 + bch;
                LDX4(bhi[bq][0], bhi[bq][1], bhi[bq][2], bhi[bq][3], sBhi + off);
                LDX4(blo[bq][0], blo[bq][1], blo[bq][2], blo[bq][3], sBlo + off);
            }
            // 3-product fp32-emulated MMAs
#pragma unroll
            for (int mg = 0; mg < 4; ++mg) {
#pragma unroll
                for (int bq = 0; bq < 2; ++bq) {
#pragma unroll
                    for (int hh = 0; hh < 2; ++hh) {
                        int ng = bq * 2 + hh;
                        float* dd = d[mg][ng];
                        MMA16816(dd[0], dd[1], dd[2], dd[3],
                                 ahi[mg][0], ahi[mg][1], ahi[mg][2], ahi[mg][3],
                                 bhi[bq][2 * hh], bhi[bq][2 * hh + 1]);
                        MMA16816(dd[0], dd[1], dd[2], dd[3],
                                 ahi[mg][0], ahi[mg][1], ahi[mg][2], ahi[mg][3],
                                 blo[bq][2 * hh], blo[bq][2 * hh + 1]);
                        MMA16816(dd[0], dd[1], dd[2], dd[3],
                                 alo[mg][0], alo[mg][1], alo[mg][2], alo[mg][3],
                                 bhi[bq][2 * hh], bhi[bq][2 * hh + 1]);
                    }
                }
            }
        }
        __syncthreads();
    }

    // epilogue: d frag (m = l/4 [+8], n = 2*(l%4) [+1])
#pragma unroll
    for (int mg = 0; mg < 4; ++mg) {
#pragma unroll
        for (int ng = 0; ng < 4; ++ng) {
            int m = m0 + wm * 64 + mg * 16 + (l >> 2);
            int n = n0 + wn * 32 + ng * 8 + 2 * (l & 3);
            if (n < N) {
                float2 v0, v1;
                v0.x = d[mg][ng][0] + bias[n];
                v0.y = d[mg][ng][1] + bias[n + 1];
                v1.x = d[mg][ng][2] + bias[n];
                v1.y = d[mg][ng][3] + bias[n + 1];
                *(float2*)&C[(size_t)m * N + n] = v0;
                *(float2*)&C[(size_t)(m + 8) * N + n] = v1;
            }
        }
    }
}

// ---------------------------------------------------------------------------
// Kernel B: fused bilinear + signed-sqrt + per-chunk L2 normalize (unchanged)
// ---------------------------------------------------------------------------
#define BIL_THREADS 320
#define H1_PITCH 132
#define WS_PITCH 84
#define ZB_PITCH 84

__global__ __launch_bounds__(BIL_THREADS)
void bilinear_kernel(const float* __restrict__ h0g, const float* __restrict__ h1g,
                     const float* __restrict__ Wb, const float* __restrict__ bbv,
                     float* __restrict__ zg)
{
    extern __shared__ float smemf[];
    float* h0s  = smemf;
    float* h1sT = h0s  + 128 * 80;
    float* wsT  = h1sT + 80 * H1_PITCH;
    float* zbuf = wsT  + 80 * WS_PITCH;
    float* scl  = zbuf + 128 * ZB_PITCH;

    const int tid   = threadIdx.x;
    const int c     = blockIdx.y;
    const int mbase = blockIdx.x * 128;

#pragma unroll
    for (int k = 0; k < 8; ++k) {
        int idx = tid + k * BIL_THREADS;
        int b = idx / 20;
        int f = idx % 20;
        size_t goff = (size_t)(mbase + b) * MM + c * SS + f * 4;
        float4 v0 = *(const float4*)&h0g[goff];
        *(float4*)&h0s[b * 80 + f * 4] = v0;
        float4 v1 = *(const float4*)&h1g[goff];
        h1sT[(f * 4 + 0) * H1_PITCH + b] = v1.x;
        h1sT[(f * 4 + 1) * H1_PITCH + b] = v1.y;
        h1sT[(f * 4 + 2) * H1_PITCH + b] = v1.z;
        h1sT[(f * 4 + 3) * H1_PITCH + b] = v1.w;
    }

    const int tx = tid % 20;
    const int ty = tid / 20;

    float acc[8][4];
#pragma unroll
    for (int i = 0; i < 8; ++i)
#pragma unroll
        for (int j = 0; j < 4; ++j) acc[i][j] = 0.0f;

    const float* WbC = Wb + (size_t)c * SS * SS * SS;

    for (int s = 0; s < SS; ++s) {
        __syncthreads();
#pragma unroll
        for (int k = 0; k < 5; ++k) {
            int idx = tid + k * BIL_THREADS;
            int q = idx / 20;
            int f = idx % 20;
            float4 w = *(const float4*)&WbC[(size_t)q * (SS * SS) + s * SS + f * 4];
            wsT[(f * 4 + 0) * WS_PITCH + q] = w.x;
            wsT[(f * 4 + 1) * WS_PITCH + q] = w.y;
            wsT[(f * 4 + 2) * WS_PITCH + q] = w.z;
            wsT[(f * 4 + 3) * WS_PITCH + q] = w.w;
        }
        __syncthreads();

        float acc2[8][4];
#pragma unroll
        for (int i = 0; i < 8; ++i)
#pragma unroll
            for (int j = 0; j < 4; ++j) acc2[i][j] = 0.0f;

#pragma unroll 2
        for (int t = 0; t < SS; ++t) {
            float4 w4 = *(const float4*)&wsT[t * WS_PITCH + tx * 4];
            float4 hA = *(const float4*)&h1sT[t * H1_PITCH + ty * 8];
            float4 hB = *(const float4*)&h1sT[t * H1_PITCH + ty * 8 + 4];
            float hv[8];
            hv[0]=hA.x; hv[1]=hA.y; hv[2]=hA.z; hv[3]=hA.w;
            hv[4]=hB.x; hv[5]=hB.y; hv[6]=hB.z; hv[7]=hB.w;
            float wv[4];
            wv[0]=w4.x; wv[1]=w4.y; wv[2]=w4.z; wv[3]=w4.w;
#pragma unroll
            for (int i = 0; i < 8; ++i)
#pragma unroll
                for (int j = 0; j < 4; ++j)
                    acc2[i][j] = fmaf(hv[i], wv[j], acc2[i][j]);
        }

        float h0v[8];
#pragma unroll
        for (int i = 0; i < 8; ++i) h0v[i] = h0s[(ty * 8 + i) * 80 + s];
#pragma unroll
        for (int i = 0; i < 8; ++i)
#pragma unroll
            for (int j = 0; j < 4; ++j)
                acc[i][j] = fmaf(h0v[i], acc2[i][j], acc[i][j]);
    }

    __syncthreads();
#pragma unroll
    for (int i = 0; i < 8; ++i)
#pragma unroll
        for (int j = 0; j < 4; ++j)
            zbuf[(ty * 8 + i) * ZB_PITCH + tx * 4 + j] =
                acc[i][j] + bbv[c * SS + tx * 4 + j];
    __syncthreads();

    if (tid < 128) {
        float ssum = 0.0f;
#pragma unroll 4
        for (int q = 0; q < SS; ++q) ssum += fabsf(zbuf[tid * ZB_PITCH + q]);
        float nrm = sqrtf(ssum);
        scl[tid] = 1.0f / fmaxf(nrm, 1e-12f);
    }
    __syncthreads();

#pragma unroll
    for (int k = 0; k < 8; ++k) {
        int idx = tid + k * BIL_THREADS;
        int b = idx / 20;
        int f = idx % 20;
        float sc = scl[b];
        float4 v = *(const float4*)&zbuf[b * ZB_PITCH + f * 4];
        float4 o;
        o.x = copysignf(sqrtf(fabsf(v.x)), v.x) * sc;
        o.y = copysignf(sqrtf(fabsf(v.y)), v.y) * sc;
        o.z = copysignf(sqrtf(fabsf(v.z)), v.z) * sc;
        o.w = copysignf(sqrtf(fabsf(v.w)), v.w) * sc;
        *(float4*)&zg[(size_t)(mbase + b) * MM + c * SS + f * 4] = o;
    }
}

// ---------------------------------------------------------------------------
// launch
// ---------------------------------------------------------------------------
extern "C" void kernel_launch(void* const* d_in, const int* in_sizes, int n_in,
                              void* d_out, int out_size)
{
    (void)in_sizes; (void)n_in; (void)out_size;
    const float* x0   = (const float*)d_in[0];
    const float* x1   = (const float*)d_in[1];
    const float* W0   = (const float*)d_in[2];
    const float* b0   = (const float*)d_in[3];
    const float* W1   = (const float*)d_in[4];
    const float* b1   = (const float*)d_in[5];
    const float* Wb   = (const float*)d_in[6];
    const float* bb   = (const float*)d_in[7];
    const float* Wout = (const float*)d_in[8];
    const float* bout = (const float*)d_in[9];
    float* out = (float*)d_out;

    float *h0p, *h1p, *zp;
    cudaGetSymbolAddress((void**)&h0p, g_h0);
    cudaGetSymbolAddress((void**)&h1p, g_h1);
    cudaGetSymbolAddress((void**)&zp,  g_z);
    void *x0hi, *x0lo, *x1hi, *x1lo, *W0hi, *W0lo, *W1hi, *W1lo;
    void *Wohi, *Wolo, *zhi, *zlo;
    cudaGetSymbolAddress(&x0hi, g_x0hi); cudaGetSymbolAddress(&x0lo, g_x0lo);
    cudaGetSymbolAddress(&x1hi, g_x1hi); cudaGetSymbolAddress(&x1lo, g_x1lo);
    cudaGetSymbolAddress(&W0hi, g_W0hi); cudaGetSymbolAddress(&W0lo, g_W0lo);
    cudaGetSymbolAddress(&W1hi, g_W1hi); cudaGetSymbolAddress(&W1lo, g_W1lo);
    cudaGetSymbolAddress(&Wohi, g_Wouthi); cudaGetSymbolAddress(&Wolo, g_Woutlo);
    cudaGetSymbolAddress(&zhi, g_zhi); cudaGetSymbolAddress(&zlo, g_zlo);

    // 1) split inputs to bf16 hi/lo
    {
        int n4;
        n4 = BB * DIN / 4;
        split_bf16<<<(n4 + 255) / 256, 256>>>(x0, (__nv_bfloat16*)x0hi, (__nv_bfloat16*)x0lo, n4);
        split_bf16<<<(n4 + 255) / 256, 256>>>(x1, (__nv_bfloat16*)x1hi, (__nv_bfloat16*)x1lo, n4);
        n4 = MM * DIN / 4;
        split_bf16<<<(n4 + 255) / 256, 256>>>(W0, (__nv_bfloat16*)W0hi, (__nv_bfloat16*)W0lo, n4);
        split_bf16<<<(n4 + 255) / 256, 256>>>(W1, (__nv_bfloat16*)W1hi, (__nv_bfloat16*)W1lo, n4);
        n4 = OUTN * MM / 4;
        split_bf16<<<(n4 + 255) / 256, 256>>>(Wout, (__nv_bfloat16*)Wohi, (__nv_bfloat16*)Wolo, n4);
    }

    cudaFuncSetAttribute(tc_gemm_nt, cudaFuncAttributeMaxDynamicSharedMemorySize, GEMM_SMEM);

    // 2) h0 = x0 @ W0^T + b0 ; h1 = x1 @ W1^T + b1
    {
        dim3 grid((MM + 127) / 128, BB / 128);
        tc_gemm_nt<<<grid, 256, GEMM_SMEM>>>(
            (const __nv_bfloat16*)x0hi, (const __nv_bfloat16*)x0lo,
            (const __nv_bfloat16*)W0hi, (const __nv_bfloat16*)W0lo, b0, h0p, MM, DIN);
        tc_gemm_nt<<<grid, 256, GEMM_SMEM>>>(
            (const __nv_bfloat16*)x1hi, (const __nv_bfloat16*)x1lo,
            (const __nv_bfloat16*)W1hi, (const __nv_bfloat16*)W1lo, b1, h1p, MM, DIN);
    }

    // 3) fused bilinear + signed sqrt + per-chunk normalize
    {
        const int smem_floats = 128 * 80 + 80 * H1_PITCH + 80 * WS_PITCH
                              + 128 * ZB_PITCH + 128;
        const size_t smem_bytes = (size_t)smem_floats * sizeof(float);
        cudaFuncSetAttribute(bilinear_kernel,
                             cudaFuncAttributeMaxDynamicSharedMemorySize,
                             (int)smem_bytes);
        dim3 grid(BB / 128, CC);
        bilinear_kernel<<<grid, BIL_THREADS, smem_bytes>>>(h0p, h1p, Wb, bb, zp);
    }

    // 4) split z to bf16 hi/lo
    {
        int n4 = BB * MM / 4;
        split_bf16<<<(n4 + 255) / 256, 256>>>(zp, (__nv_bfloat16*)zhi, (__nv_bfloat16*)zlo, n4);
    }

    // 5) out = z @ Wout^T + bout
    {
        dim3 grid((OUTN + 127) / 128, BB / 128);
        tc_gemm_nt<<<grid, 256, GEMM_SMEM>>>(
            (const __nv_bfloat16*)zhi, (const __nv_bfloat16*)zlo,
            (const __nv_bfloat16*)Wohi, (const __nv_bfloat16*)Wolo, bout, out, OUTN, MM);
    }
}

// round 4
// speedup vs baseline: 3.4294x; 2.4515x over previous
#include <cuda_runtime.h>
#include <cuda_bf16.h>
#include <math.h>
#include <stdint.h>

// Problem constants
#define BB    8192
#define DIN   2048
#define MM    1600
#define CC    20
#define SS    80
#define OUTN  3000

// ---------------------------------------------------------------------------
// Scratch (static device globals)
// ---------------------------------------------------------------------------
__device__ float g_h0[(size_t)BB * MM];
__device__ float g_h1[(size_t)BB * MM];
__device__ float g_zT[(size_t)MM * BB];     // z transposed: [feat][b]

__device__ __nv_bfloat16 g_x0hi[(size_t)BB * DIN];
__device__ __nv_bfloat16 g_x0lo[(size_t)BB * DIN];
__device__ __nv_bfloat16 g_x1hi[(size_t)BB * DIN];
__device__ __nv_bfloat16 g_x1lo[(size_t)BB * DIN];
__device__ __nv_bfloat16 g_W0hi[(size_t)MM * DIN];
__device__ __nv_bfloat16 g_W0lo[(size_t)MM * DIN];
__device__ __nv_bfloat16 g_W1hi[(size_t)MM * DIN];
__device__ __nv_bfloat16 g_W1lo[(size_t)MM * DIN];
__device__ __nv_bfloat16 g_Wouthi[(size_t)OUTN * MM];
__device__ __nv_bfloat16 g_Woutlo[(size_t)OUTN * MM];
__device__ __nv_bfloat16 g_Wbhi[(size_t)CC * SS * SS * SS];
__device__ __nv_bfloat16 g_Wblo[(size_t)CC * SS * SS * SS];
__device__ __nv_bfloat16 g_h1hi[(size_t)BB * MM];
__device__ __nv_bfloat16 g_h1lo[(size_t)BB * MM];
__device__ __nv_bfloat16 g_zhi[(size_t)BB * MM];
__device__ __nv_bfloat16 g_zlo[(size_t)BB * MM];

// ---------------------------------------------------------------------------
// Low-level helpers (portable ISA: cp.async / ldmatrix / mma.sync)
// ---------------------------------------------------------------------------
__device__ __forceinline__ uint32_t smem_u32(const void* p) {
    uint32_t a;
    asm("{ .reg .u64 t; cvta.to.shared.u64 t, %1; cvt.u32.u64 %0, t; }"
        : "=r"(a) : "l"(p));
    return a;
}

#define CP16(dst, src) \
    asm volatile("cp.async.cg.shared.global [%0], [%1], 16;" \
                 :: "r"(dst), "l"(src) : "memory")
#define CP16P(dst, src, nbytes) \
    asm volatile("cp.async.cg.shared.global [%0], [%1], 16, %2;" \
                 :: "r"(dst), "l"(src), "r"(nbytes) : "memory")
#define CP_COMMIT() asm volatile("cp.async.commit_group;" ::: "memory")
#define CP_WAIT0()  asm volatile("cp.async.wait_group 0;" ::: "memory")
#define CP_WAIT1()  asm volatile("cp.async.wait_group 1;" ::: "memory")

#define LDX4(r0, r1, r2, r3, addr) \
    asm volatile("ldmatrix.sync.aligned.m8n8.x4.shared.b16 {%0,%1,%2,%3}, [%4];" \
                 : "=r"(r0), "=r"(r1), "=r"(r2), "=r"(r3) : "r"(addr))

#define MMA16816(d0, d1, d2, d3, a0, a1, a2, a3, b0, b1) \
    asm volatile("mma.sync.aligned.m16n8k16.row.col.f32.bf16.bf16.f32 " \
                 "{%0,%1,%2,%3}, {%4,%5,%6,%7}, {%8,%9}, {%0,%1,%2,%3};" \
                 : "+f"(d0), "+f"(d1), "+f"(d2), "+f"(d3) \
                 : "r"(a0), "r"(a1), "r"(a2), "r"(a3), "r"(b0), "r"(b1))

// ---------------------------------------------------------------------------
// Split fp32 -> bf16 hi + bf16 lo
// ---------------------------------------------------------------------------
__global__ __launch_bounds__(256)
void split_bf16(const float* __restrict__ in, __nv_bfloat16* __restrict__ hi,
                __nv_bfloat16* __restrict__ lo, int n4)
{
    int i = blockIdx.x * blockDim.x + threadIdx.x;
    if (i >= n4) return;
    float4 v = ((const float4*)in)[i];
    __nv_bfloat16 h0 = __float2bfloat16(v.x);
    __nv_bfloat16 h1 = __float2bfloat16(v.y);
    __nv_bfloat16 h2 = __float2bfloat16(v.z);
    __nv_bfloat16 h3 = __float2bfloat16(v.w);
    __nv_bfloat16 l0 = __float2bfloat16(v.x - __bfloat162float(h0));
    __nv_bfloat16 l1 = __float2bfloat16(v.y - __bfloat162float(h1));
    __nv_bfloat16 l2 = __float2bfloat16(v.z - __bfloat162float(h2));
    __nv_bfloat16 l3 = __float2bfloat16(v.w - __bfloat162float(h3));
    __nv_bfloat162 hv0 = __nv_bfloat162(h0, h1), hv1 = __nv_bfloat162(h2, h3);
    __nv_bfloat162 lv0 = __nv_bfloat162(l0, l1), lv1 = __nv_bfloat162(l2, l3);
    uint2 hp, lp;
    hp.x = *(uint32_t*)&hv0; hp.y = *(uint32_t*)&hv1;
    lp.x = *(uint32_t*)&lv0; lp.y = *(uint32_t*)&lv1;
    ((uint2*)hi)[i] = hp;
    ((uint2*)lo)[i] = lp;
}

// ---------------------------------------------------------------------------
// mma.sync NT GEMM, 3-stage cp.async pipeline, 128x128xBK64 tiles, 256 thr.
// ---------------------------------------------------------------------------
#define BK 64
#define STAGE_BYTES 65536
#define GEMM_SMEM   (3 * STAGE_BYTES)

struct GemmPtrs {
    const __nv_bfloat16 *Ahi, *Alo, *Bhi, *Blo;
};

__device__ __forceinline__ void issue_stage(
    uint32_t sbase, int stage, GemmPtrs p,
    int m0, int n0, int k0, int N, int K, int tid)
{
    uint32_t st = sbase + stage * STAGE_BYTES;
#pragma unroll
    for (int i = 0; i < 4; ++i) {
        int idx = tid + i * 256;
        int r = idx >> 3;
        int c = idx & 7;
        uint32_t dst = (uint32_t)(r * 128 + ((c ^ (r & 7)) << 4));
        size_t aoff = (size_t)(m0 + r) * K + k0 + c * 8;
        CP16(st + dst,         (const char*)(p.Ahi + aoff));
        CP16(st + 16384 + dst, (const char*)(p.Alo + aoff));
        int n = n0 + r;
        int pred = (n < N) ? 16 : 0;
        int ncl = (n < N) ? n : (N - 1);
        size_t boff = (size_t)ncl * K + k0 + c * 8;
        CP16P(st + 32768 + dst, (const char*)(p.Bhi + boff), pred);
        CP16P(st + 49152 + dst, (const char*)(p.Blo + boff), pred);
    }
    CP_COMMIT();
}

__global__ __launch_bounds__(256, 1)
void tc_gemm_nt(const __nv_bfloat16* __restrict__ Ahi,
                const __nv_bfloat16* __restrict__ Alo,
                const __nv_bfloat16* __restrict__ Bhi,
                const __nv_bfloat16* __restrict__ Blo,
                const float* __restrict__ bias,
                float* __restrict__ C,
                int N, int K)
{
    extern __shared__ __align__(128) char smem[];
    const uint32_t sb = smem_u32(smem);

    const int tid = threadIdx.x;
    const int l   = tid & 31;
    const int wid = tid >> 5;
    const int wm  = wid & 1;
    const int wn  = wid >> 1;
    const int m0  = blockIdx.y * 128;
    const int n0  = blockIdx.x * 128;
    const int niter = K / BK;

    GemmPtrs p; p.Ahi = Ahi; p.Alo = Alo; p.Bhi = Bhi; p.Blo = Blo;

    const uint32_t aRow  = (uint32_t)(wm * 64 + (l & 15));
    const uint32_t aXor  = aRow & 7;
    const uint32_t aHalf = (uint32_t)(l >> 4);
    const uint32_t bRow  = (uint32_t)(wn * 32 + (l & 7) + ((l >> 4) << 3));
    const uint32_t bXor  = bRow & 7;
    const uint32_t bHalf = (uint32_t)((l >> 3) & 1);

    float d[4][4][4];
#pragma unroll
    for (int mg = 0; mg < 4; ++mg)
#pragma unroll
        for (int ng = 0; ng < 4; ++ng)
#pragma unroll
            for (int k = 0; k < 4; ++k) d[mg][ng][k] = 0.0f;

    issue_stage(sb, 0, p, m0, n0, 0, N, K, tid);
    if (niter > 1) issue_stage(sb, 1, p, m0, n0, BK, N, K, tid);

    for (int it = 0; it < niter; ++it) {
        if (it < niter - 1) CP_WAIT1(); else CP_WAIT0();
        __syncthreads();
        if (it + 2 < niter)
            issue_stage(sb, (it + 2) % 3, p, m0, n0, (it + 2) * BK, N, K, tid);

        const uint32_t st = sb + (it % 3) * STAGE_BYTES;
        const uint32_t sAhi = st;
        const uint32_t sAlo = st + 16384;
        const uint32_t sBhi = st + 32768;
        const uint32_t sBlo = st + 49152;

#pragma unroll
        for (int kk = 0; kk < 4; ++kk) {
            uint32_t ahi[4][4], alo[4][4], bhi[2][4], blo[2][4];
            const uint32_t ach = (((2 * kk + aHalf) ^ aXor) << 4);
            const uint32_t bch = (((2 * kk + bHalf) ^ bXor) << 4);
#pragma unroll
            for (int mg = 0; mg < 4; ++mg) {
                uint32_t off = (aRow + mg * 16) * 128 + ach;
                LDX4(ahi[mg][0], ahi[mg][1], ahi[mg][2], ahi[mg][3], sAhi + off);
                LDX4(alo[mg][0], alo[mg][1], alo[mg][2], alo[mg][3], sAlo + off);
            }
#pragma unroll
            for (int bq = 0; bq < 2; ++bq) {
                uint32_t off = (bRow + bq * 16) * 128 + bch;
                LDX4(bhi[bq][0], bhi[bq][1], bhi[bq][2], bhi[bq][3], sBhi + off);
                LDX4(blo[bq][0], blo[bq][1], blo[bq][2], blo[bq][3], sBlo + off);
            }
#pragma unroll
            for (int mg = 0; mg < 4; ++mg) {
#pragma unroll
                for (int bq = 0; bq < 2; ++bq) {
#pragma unroll
                    for (int hh = 0; hh < 2; ++hh) {
                        int ng = bq * 2 + hh;
                        float* dd = d[mg][ng];
                        MMA16816(dd[0], dd[1], dd[2], dd[3],
                                 ahi[mg][0], ahi[mg][1], ahi[mg][2], ahi[mg][3],
                                 bhi[bq][2 * hh], bhi[bq][2 * hh + 1]);
                        MMA16816(dd[0], dd[1], dd[2], dd[3],
                                 ahi[mg][0], ahi[mg][1], ahi[mg][2], ahi[mg][3],
                                 blo[bq][2 * hh], blo[bq][2 * hh + 1]);
                        MMA16816(dd[0], dd[1], dd[2], dd[3],
                                 alo[mg][0], alo[mg][1], alo[mg][2], alo[mg][3],
                                 bhi[bq][2 * hh], bhi[bq][2 * hh + 1]);
                    }
                }
            }
        }
        __syncthreads();
    }

#pragma unroll
    for (int mg = 0; mg < 4; ++mg) {
#pragma unroll
        for (int ng = 0; ng < 4; ++ng) {
            int m = m0 + wm * 64 + mg * 16 + (l >> 2);
            int n = n0 + wn * 32 + ng * 8 + 2 * (l & 3);
            if (n < N) {
                float2 v0, v1;
                v0.x = d[mg][ng][0] + bias[n];
                v0.y = d[mg][ng][1] + bias[n + 1];
                v1.x = d[mg][ng][2] + bias[n];
                v1.y = d[mg][ng][3] + bias[n + 1];
                *(float2*)&C[(size_t)m * N + n] = v0;
                *(float2*)&C[(size_t)(m + 8) * N + n] = v1;
            }
        }
    }
}

// ---------------------------------------------------------------------------
// Fused bilinear as GEMM:  zT[c*80+q][b] = sum_s h0[b,s] * (Wb[c,q,s,:] . h1[b,:])
// CTA: 2 q's (Mtile=160 = 2x80 s-rows) x 128 b. A = Wb (CTA-resident),
// B = h1 (2-stage), h0 fp32 (2-stage). K=80. 8 warps: wm(q) x 4 wn.
// 3-product bf16 hi/lo MMA, fused fp32 s-contraction epilogue.
// ---------------------------------------------------------------------------
#define A_PITCH 176        // bytes per A row (80 bf16 used of 88)
#define B_PITCH 176
#define H0_PITCHF 84       // floats per h0 row
#define SA_HI   0
#define SA_LO   28160      // 160*176
#define SB_BASE 56320
#define SB_STAGE 45056     // (hi+lo) * 128*176
#define SB_LOOFF 22528
#define SH0_BASE 146432
#define SH0_STAGE 43008    // 128*84*4
#define BIL_SMEM 232448
#define BSPLIT 2

__global__ __launch_bounds__(256, 1)
void bilq_kernel(const __nv_bfloat16* __restrict__ Wbhi,
                 const __nv_bfloat16* __restrict__ Wblo,
                 const __nv_bfloat16* __restrict__ h1hi,
                 const __nv_bfloat16* __restrict__ h1lo,
                 const float* __restrict__ h0g,
                 float* __restrict__ zT)
{
    extern __shared__ __align__(128) char smem[];
    const uint32_t sb = smem_u32(smem);
    const int tid = threadIdx.x;
    const int l   = tid & 31;
    const int wid = tid >> 5;
    const int wm  = wid >> 2;      // 0..1  -> local q
    const int wn  = wid & 3;       // 0..3  -> 32-b column group
    const int c     = blockIdx.z;
    const int q0    = blockIdx.y * 2;
    const int bhalf = blockIdx.x;
    const int NB = 64 / BSPLIT;    // 32 b-tiles per CTA

    // ---- issue A (Wb rows, hi+lo), resident for whole CTA ----
    {
        const size_t wb_base = (size_t)c * (SS * SS * SS) + (size_t)q0 * (SS * SS);
#pragma unroll
        for (int i = 0; i < 7; ++i) {
            int idx = tid + i * 256;
            if (idx < 1600) {
                int row = idx / 10, ch = idx % 10;   // row = ql*80 + s
                size_t src = wb_base + (size_t)(row / 80) * (SS * SS)
                           + (size_t)(row % 80) * SS + ch * 8;
                uint32_t dst = sb + SA_HI + row * A_PITCH + ch * 16;
                CP16(dst, (const char*)(Wbhi + src));
                CP16(dst + SA_LO, (const char*)(Wblo + src));
            }
        }
    }

    // ---- per-btile load issuer ----
    auto issue_bt = [&](int st, int b0) {
        uint32_t sB = sb + SB_BASE + st * SB_STAGE;
#pragma unroll
        for (int i = 0; i < 5; ++i) {
            int idx = tid + i * 256;      // < 1280
            int r = idx / 10, ch = idx % 10;
            size_t src = (size_t)(b0 + r) * MM + c * SS + ch * 8;
            uint32_t dst = sB + r * B_PITCH + ch * 16;
            CP16(dst, (const char*)(h1hi + src));
            CP16(dst + SB_LOOFF, (const char*)(h1lo + src));
        }
        uint32_t sH = sb + SH0_BASE + st * SH0_STAGE;
#pragma unroll
        for (int i = 0; i < 10; ++i) {
            int idx = tid + i * 256;      // < 2560
            int r = idx / 20, ch = idx % 20;
            size_t src = (size_t)(b0 + r) * MM + c * SS + ch * 4;
            CP16(sH + r * (H0_PITCHF * 4) + ch * 16, (const char*)(h0g + src));
        }
        CP_COMMIT();
    };

    issue_bt(0, (bhalf * NB + 0) * 128);   // A rides in group 0

    const uint32_t aRowOff  = (uint32_t)(wm * 80 + (l & 15)) * A_PITCH;
    const uint32_t aHalf    = (uint32_t)(l >> 4);
    const uint32_t bRowOff  = (uint32_t)((l & 7) + ((l >> 4) << 3)) * B_PITCH;
    const uint32_t bHalf    = (uint32_t)((l >> 3) & 1);

    for (int nIt = 0; nIt < NB; ++nIt) {
        const int b0 = (bhalf * NB + nIt) * 128;
        if (nIt + 1 < NB) {
            issue_bt((nIt + 1) & 1, (bhalf * NB + nIt + 1) * 128);
            CP_WAIT1();
        } else {
            CP_WAIT0();
        }
        __syncthreads();

        const int st = nIt & 1;
        const uint32_t sAhi = sb + SA_HI;
        const uint32_t sAlo = sb + SA_LO;
        const uint32_t sBhi = sb + SB_BASE + st * SB_STAGE;
        const uint32_t sBlo = sBhi + SB_LOOFF;
        const float* h0s = (const float*)(smem + SH0_BASE + st * SH0_STAGE);

        float d[5][4][4];
#pragma unroll
        for (int mt = 0; mt < 5; ++mt)
#pragma unroll
            for (int nt = 0; nt < 4; ++nt)
#pragma unroll
                for (int e = 0; e < 4; ++e) d[mt][nt][e] = 0.0f;

#pragma unroll
        for (int kk = 0; kk < 5; ++kk) {
            uint32_t ah[5][4], al[5][4], bh[2][4], bl[2][4];
            const uint32_t aco = ((2 * kk + aHalf) << 4);
            const uint32_t bco = ((2 * kk + bHalf) << 4);
#pragma unroll
            for (int mt = 0; mt < 5; ++mt) {
                uint32_t off = aRowOff + mt * 16 * A_PITCH + aco;
                LDX4(ah[mt][0], ah[mt][1], ah[mt][2], ah[mt][3], sAhi + off);
                LDX4(al[mt][0], al[mt][1], al[mt][2], al[mt][3], sAlo + off);
            }
#pragma unroll
            for (int pr = 0; pr < 2; ++pr) {
                uint32_t off = (uint32_t)(wn * 32 + pr * 16) * B_PITCH + bRowOff + bco;
                LDX4(bh[pr][0], bh[pr][1], bh[pr][2], bh[pr][3], sBhi + off);
                LDX4(bl[pr][0], bl[pr][1], bl[pr][2], bl[pr][3], sBlo + off);
            }
#pragma unroll
            for (int mt = 0; mt < 5; ++mt) {
#pragma unroll
                for (int pr = 0; pr < 2; ++pr) {
#pragma unroll
                    for (int hh = 0; hh < 2; ++hh) {
                        int nt = pr * 2 + hh;
                        float* dd = d[mt][nt];
                        MMA16816(dd[0], dd[1], dd[2], dd[3],
                                 ah[mt][0], ah[mt][1], ah[mt][2], ah[mt][3],
                                 bh[pr][2 * hh], bh[pr][2 * hh + 1]);
                        MMA16816(dd[0], dd[1], dd[2], dd[3],
                                 ah[mt][0], ah[mt][1], ah[mt][2], ah[mt][3],
                                 bl[pr][2 * hh], bl[pr][2 * hh + 1]);
                        MMA16816(dd[0], dd[1], dd[2], dd[3],
                                 al[mt][0], al[mt][1], al[mt][2], al[mt][3],
                                 bh[pr][2 * hh], bh[pr][2 * hh + 1]);
                    }
                }
            }
        }

        // ---- fused epilogue: contract over s with fp32 h0 ----
        float p8[8];
#pragma unroll
        for (int i = 0; i < 8; ++i) p8[i] = 0.0f;
#pragma unroll
        for (int mt = 0; mt < 5; ++mt) {
#pragma unroll
            for (int e = 0; e < 4; ++e) {
                int s = mt * 16 + (l >> 2) + 8 * (e >> 1);
#pragma unroll
                for (int nt = 0; nt < 4; ++nt) {
                    int bl_ = wn * 32 + nt * 8 + 2 * (l & 3) + (e & 1);
                    p8[nt * 2 + (e & 1)] += d[mt][nt][e] * h0s[bl_ * H0_PITCHF + s];
                }
            }
        }
#pragma unroll
        for (int pi = 0; pi < 8; ++pi) {
            float v = p8[pi];
            v += __shfl_xor_sync(0xffffffffu, v, 4);
            v += __shfl_xor_sync(0xffffffffu, v, 8);
            v += __shfl_xor_sync(0xffffffffu, v, 16);
            p8[pi] = v;
        }
        if (l < 4) {
            int feat = c * SS + q0 + wm;
            float* dst = zT + (size_t)feat * BB + b0 + wn * 32 + 2 * l;
#pragma unroll
            for (int nt = 0; nt < 4; ++nt)
                *(float2*)(dst + nt * 8) = make_float2(p8[nt * 2], p8[nt * 2 + 1]);
        }
        __syncthreads();
    }
}

// ---------------------------------------------------------------------------
// norm: z = signed_sqrt(zT + bb); per-chunk L2 normalize; emit bf16 hi/lo.
// ---------------------------------------------------------------------------
__global__ __launch_bounds__(256)
void norm_kernel(const float* __restrict__ zT, const float* __restrict__ bbv,
                 __nv_bfloat16* __restrict__ zhi, __nv_bfloat16* __restrict__ zlo)
{
    __shared__ float zs[80 * 129];
    __shared__ float bbs[80];
    __shared__ float scl[128];
    const int tid = threadIdx.x;
    const int c = blockIdx.y;
    const int b0 = blockIdx.x * 128;

    if (tid < 80) bbs[tid] = bbv[c * SS + tid];
#pragma unroll
    for (int i = 0; i < 40; ++i) {
        int idx = tid + i * 256;
        int q = idx >> 7, col = idx & 127;
        zs[q * 129 + col] = zT[(size_t)(c * SS + q) * BB + b0 + col];
    }
    __syncthreads();
    if (tid < 128) {
        float s = 0.0f;
#pragma unroll 4
        for (int q = 0; q < 80; ++q) s += fabsf(zs[q * 129 + tid] + bbs[q]);
        scl[tid] = 1.0f / fmaxf(sqrtf(s), 1e-12f);
    }
    __syncthreads();
#pragma unroll
    for (int i = 0; i < 40; ++i) {
        int idx = tid + i * 256;
        int b = idx / 80, q = idx % 80;
        float v = zs[q * 129 + b] + bbs[q];
        float sv = copysignf(sqrtf(fabsf(v)), v) * scl[b];
        __nv_bfloat16 h = __float2bfloat16(sv);
        __nv_bfloat16 lo = __float2bfloat16(sv - __bfloat162float(h));
        size_t o = (size_t)(b0 + b) * MM + c * SS + q;
        zhi[o] = h;
        zlo[o] = lo;
    }
}

// ---------------------------------------------------------------------------
// launch
// ---------------------------------------------------------------------------
extern "C" void kernel_launch(void* const* d_in, const int* in_sizes, int n_in,
                              void* d_out, int out_size)
{
    (void)in_sizes; (void)n_in; (void)out_size;
    const float* x0   = (const float*)d_in[0];
    const float* x1   = (const float*)d_in[1];
    const float* W0   = (const float*)d_in[2];
    const float* b0   = (const float*)d_in[3];
    const float* W1   = (const float*)d_in[4];
    const float* b1   = (const float*)d_in[5];
    const float* Wb   = (const float*)d_in[6];
    const float* bb   = (const float*)d_in[7];
    const float* Wout = (const float*)d_in[8];
    const float* bout = (const float*)d_in[9];
    float* out = (float*)d_out;

    float *h0p, *h1p, *zTp;
    cudaGetSymbolAddress((void**)&h0p, g_h0);
    cudaGetSymbolAddress((void**)&h1p, g_h1);
    cudaGetSymbolAddress((void**)&zTp, g_zT);
    void *x0hi, *x0lo, *x1hi, *x1lo, *W0hi, *W0lo, *W1hi, *W1lo;
    void *Wohi, *Wolo, *Wbhi, *Wblo, *h1hi, *h1lo, *zhi, *zlo;
    cudaGetSymbolAddress(&x0hi, g_x0hi); cudaGetSymbolAddress(&x0lo, g_x0lo);
    cudaGetSymbolAddress(&x1hi, g_x1hi); cudaGetSymbolAddress(&x1lo, g_x1lo);
    cudaGetSymbolAddress(&W0hi, g_W0hi); cudaGetSymbolAddress(&W0lo, g_W0lo);
    cudaGetSymbolAddress(&W1hi, g_W1hi); cudaGetSymbolAddress(&W1lo, g_W1lo);
    cudaGetSymbolAddress(&Wohi, g_Wouthi); cudaGetSymbolAddress(&Wolo, g_Woutlo);
    cudaGetSymbolAddress(&Wbhi, g_Wbhi); cudaGetSymbolAddress(&Wblo, g_Wblo);
    cudaGetSymbolAddress(&h1hi, g_h1hi); cudaGetSymbolAddress(&h1lo, g_h1lo);
    cudaGetSymbolAddress(&zhi, g_zhi); cudaGetSymbolAddress(&zlo, g_zlo);

    // 1) split static inputs
    {
        int n4;
        n4 = BB * DIN / 4;
        split_bf16<<<(n4 + 255) / 256, 256>>>(x0, (__nv_bfloat16*)x0hi, (__nv_bfloat16*)x0lo, n4);
        split_bf16<<<(n4 + 255) / 256, 256>>>(x1, (__nv_bfloat16*)x1hi, (__nv_bfloat16*)x1lo, n4);
        n4 = MM * DIN / 4;
        split_bf16<<<(n4 + 255) / 256, 256>>>(W0, (__nv_bfloat16*)W0hi, (__nv_bfloat16*)W0lo, n4);
        split_bf16<<<(n4 + 255) / 256, 256>>>(W1, (__nv_bfloat16*)W1hi, (__nv_bfloat16*)W1lo, n4);
        n4 = OUTN * MM / 4;
        split_bf16<<<(n4 + 255) / 256, 256>>>(Wout, (__nv_bfloat16*)Wohi, (__nv_bfloat16*)Wolo, n4);
        n4 = CC * SS * SS * SS / 4;
        split_bf16<<<(n4 + 255) / 256, 256>>>(Wb, (__nv_bfloat16*)Wbhi, (__nv_bfloat16*)Wblo, n4);
    }

    cudaFuncSetAttribute(tc_gemm_nt, cudaFuncAttributeMaxDynamicSharedMemorySize, GEMM_SMEM);
    cudaFuncSetAttribute(bilq_kernel, cudaFuncAttributeMaxDynamicSharedMemorySize, BIL_SMEM);

    // 2) h0 = x0 @ W0^T + b0 ; h1 = x1 @ W1^T + b1
    {
        dim3 grid((MM + 127) / 128, BB / 128);
        tc_gemm_nt<<<grid, 256, GEMM_SMEM>>>(
            (const __nv_bfloat16*)x0hi, (const __nv_bfloat16*)x0lo,
            (const __nv_bfloat16*)W0hi, (const __nv_bfloat16*)W0lo, b0, h0p, MM, DIN);
        tc_gemm_nt<<<grid, 256, GEMM_SMEM>>>(
            (const __nv_bfloat16*)x1hi, (const __nv_bfloat16*)x1lo,
            (const __nv_bfloat16*)W1hi, (const __nv_bfloat16*)W1lo, b1, h1p, MM, DIN);
    }

    // 3) split h1 to bf16 hi/lo
    {
        int n4 = BB * MM / 4;
        split_bf16<<<(n4 + 255) / 256, 256>>>(h1p, (__nv_bfloat16*)h1hi, (__nv_bfloat16*)h1lo, n4);
    }

    // 4) fused bilinear (tensor cores) -> zT
    {
        dim3 grid(BSPLIT, SS / 2, CC);
        bilq_kernel<<<grid, 256, BIL_SMEM>>>(
            (const __nv_bfloat16*)Wbhi, (const __nv_bfloat16*)Wblo,
            (const __nv_bfloat16*)h1hi, (const __nv_bfloat16*)h1lo,
            h0p, zTp);
    }

    // 5) bias + signed sqrt + normalize + bf16 split
    {
        dim3 grid(BB / 128, CC);
        norm_kernel<<<grid, 256>>>(zTp, bb, (__nv_bfloat16*)zhi, (__nv_bfloat16*)zlo);
    }

    // 6) out = z @ Wout^T + bout
    {
        dim3 grid((OUTN + 127) / 128, BB / 128);
        tc_gemm_nt<<<grid, 256, GEMM_SMEM>>>(
            (const __nv_bfloat16*)zhi, (const __nv_bfloat16*)zlo,
            (const __nv_bfloat16*)Wohi, (const __nv_bfloat16*)Wolo, bout, out, OUTN, MM);
    }
}

// round 5
// speedup vs baseline: 3.4980x; 1.0200x over previous
#include <cuda_runtime.h>
#include <cuda_bf16.h>
#include <math.h>
#include <stdint.h>

// Problem constants
#define BB    8192
#define DIN   2048
#define MM    1600
#define CC    20
#define SS    80
#define OUTN  3000

// ---------------------------------------------------------------------------
// Scratch (static device globals)
// ---------------------------------------------------------------------------
__device__ float g_h0[(size_t)BB * MM];
__device__ float g_zT[(size_t)MM * BB];     // z transposed: [feat][b]

__device__ __nv_bfloat16 g_x0hi[(size_t)BB * DIN];
__device__ __nv_bfloat16 g_x0lo[(size_t)BB * DIN];
__device__ __nv_bfloat16 g_x1hi[(size_t)BB * DIN];
__device__ __nv_bfloat16 g_x1lo[(size_t)BB * DIN];
__device__ __nv_bfloat16 g_W0hi[(size_t)MM * DIN];
__device__ __nv_bfloat16 g_W0lo[(size_t)MM * DIN];
__device__ __nv_bfloat16 g_W1hi[(size_t)MM * DIN];
__device__ __nv_bfloat16 g_W1lo[(size_t)MM * DIN];
__device__ __nv_bfloat16 g_Wouthi[(size_t)OUTN * MM];
__device__ __nv_bfloat16 g_Woutlo[(size_t)OUTN * MM];
__device__ __nv_bfloat16 g_Wbhi[(size_t)CC * SS * SS * SS];
__device__ __nv_bfloat16 g_Wblo[(size_t)CC * SS * SS * SS];
__device__ __nv_bfloat16 g_h1hi[(size_t)BB * MM];
__device__ __nv_bfloat16 g_h1lo[(size_t)BB * MM];
__device__ __nv_bfloat16 g_zhi[(size_t)BB * MM];
__device__ __nv_bfloat16 g_zlo[(size_t)BB * MM];

// ---------------------------------------------------------------------------
// Low-level helpers (portable ISA: cp.async / ldmatrix / mma.sync)
// ---------------------------------------------------------------------------
__device__ __forceinline__ uint32_t smem_u32(const void* p) {
    uint32_t a;
    asm("{ .reg .u64 t; cvta.to.shared.u64 t, %1; cvt.u32.u64 %0, t; }"
        : "=r"(a) : "l"(p));
    return a;
}

#define CP16(dst, src) \
    asm volatile("cp.async.cg.shared.global [%0], [%1], 16;" \
                 :: "r"(dst), "l"(src) : "memory")
#define CP16P(dst, src, nbytes) \
    asm volatile("cp.async.cg.shared.global [%0], [%1], 16, %2;" \
                 :: "r"(dst), "l"(src), "r"(nbytes) : "memory")
#define CP_COMMIT() asm volatile("cp.async.commit_group;" ::: "memory")
#define CP_WAIT0()  asm volatile("cp.async.wait_group 0;" ::: "memory")
#define CP_WAIT1()  asm volatile("cp.async.wait_group 1;" ::: "memory")

#define LDX4(r0, r1, r2, r3, addr) \
    asm volatile("ldmatrix.sync.aligned.m8n8.x4.shared.b16 {%0,%1,%2,%3}, [%4];" \
                 : "=r"(r0), "=r"(r1), "=r"(r2), "=r"(r3) : "r"(addr))

#define MMA16816(d0, d1, d2, d3, a0, a1, a2, a3, b0, b1) \
    asm volatile("mma.sync.aligned.m16n8k16.row.col.f32.bf16.bf16.f32 " \
                 "{%0,%1,%2,%3}, {%4,%5,%6,%7}, {%8,%9}, {%0,%1,%2,%3};" \
                 : "+f"(d0), "+f"(d1), "+f"(d2), "+f"(d3) \
                 : "r"(a0), "r"(a1), "r"(a2), "r"(a3), "r"(b0), "r"(b1))

// ---------------------------------------------------------------------------
// Split fp32 -> bf16 hi + bf16 lo
// ---------------------------------------------------------------------------
__global__ __launch_bounds__(256)
void split_bf16(const float* __restrict__ in, __nv_bfloat16* __restrict__ hi,
                __nv_bfloat16* __restrict__ lo, int n4)
{
    int i = blockIdx.x * blockDim.x + threadIdx.x;
    if (i >= n4) return;
    float4 v = ((const float4*)in)[i];
    __nv_bfloat16 h0 = __float2bfloat16(v.x);
    __nv_bfloat16 h1 = __float2bfloat16(v.y);
    __nv_bfloat16 h2 = __float2bfloat16(v.z);
    __nv_bfloat16 h3 = __float2bfloat16(v.w);
    __nv_bfloat16 l0 = __float2bfloat16(v.x - __bfloat162float(h0));
    __nv_bfloat16 l1 = __float2bfloat16(v.y - __bfloat162float(h1));
    __nv_bfloat16 l2 = __float2bfloat16(v.z - __bfloat162float(h2));
    __nv_bfloat16 l3 = __float2bfloat16(v.w - __bfloat162float(h3));
    __nv_bfloat162 hv0 = __nv_bfloat162(h0, h1), hv1 = __nv_bfloat162(h2, h3);
    __nv_bfloat162 lv0 = __nv_bfloat162(l0, l1), lv1 = __nv_bfloat162(l2, l3);
    uint2 hp, lp;
    hp.x = *(uint32_t*)&hv0; hp.y = *(uint32_t*)&hv1;
    lp.x = *(uint32_t*)&lv0; lp.y = *(uint32_t*)&lv1;
    ((uint2*)hi)[i] = hp;
    ((uint2*)lo)[i] = lp;
}

// ---------------------------------------------------------------------------
// mma.sync NT GEMM: CTA 256(M) x 128(N) x BK64, 8 warps (warp tile 64x64),
// 2-stage cp.async, one barrier per K-iter. 3-product bf16 hi/lo emulation.
// OMODE 0: fp32 C (+bias).  OMODE 1: bf16 hi/lo pair (+bias).
// ---------------------------------------------------------------------------
#define BK 64
#define STAGE2 98304     // Ahi 32K | Alo 32K | Bhi 16K | Blo 16K
#define GEMM_SMEM2 (2 * STAGE2)

struct GemmPtrs {
    const __nv_bfloat16 *Ahi, *Alo, *Bhi, *Blo;
};

__device__ __forceinline__ void issue_stage2(
    uint32_t sbase, int stage, GemmPtrs p,
    int m0, int n0, int k0, int N, int K, int tid)
{
    uint32_t st = sbase + stage * STAGE2;
    // A: 256 rows x 8 16B-chunks, hi+lo
#pragma unroll
    for (int i = 0; i < 8; ++i) {
        int idx = tid + i * 256;
        int r = idx >> 3;
        int c = idx & 7;
        uint32_t dst = (uint32_t)(r * 128 + ((c ^ (r & 7)) << 4));
        size_t aoff = (size_t)(m0 + r) * K + k0 + c * 8;
        CP16(st + dst,         (const char*)(p.Ahi + aoff));
        CP16(st + 32768 + dst, (const char*)(p.Alo + aoff));
    }
    // B: 128 rows x 8 chunks, hi+lo (ragged N guarded)
#pragma unroll
    for (int i = 0; i < 4; ++i) {
        int idx = tid + i * 256;
        int r = idx >> 3;
        int c = idx & 7;
        uint32_t dst = (uint32_t)(r * 128 + ((c ^ (r & 7)) << 4));
        int n = n0 + r;
        int pred = (n < N) ? 16 : 0;
        int ncl = (n < N) ? n : (N - 1);
        size_t boff = (size_t)ncl * K + k0 + c * 8;
        CP16P(st + 65536 + dst, (const char*)(p.Bhi + boff), pred);
        CP16P(st + 81920 + dst, (const char*)(p.Blo + boff), pred);
    }
    CP_COMMIT();
}

template <int OMODE>
__global__ __launch_bounds__(256, 1)
void tc_gemm_nt2(const __nv_bfloat16* __restrict__ Ahi,
                 const __nv_bfloat16* __restrict__ Alo,
                 const __nv_bfloat16* __restrict__ Bhi,
                 const __nv_bfloat16* __restrict__ Blo,
                 const float* __restrict__ bias,
                 float* __restrict__ C,
                 __nv_bfloat16* __restrict__ Chi,
                 __nv_bfloat16* __restrict__ Clo,
                 int N, int K)
{
    extern __shared__ __align__(128) char smem[];
    const uint32_t sb = smem_u32(smem);

    const int tid = threadIdx.x;
    const int l   = tid & 31;
    const int wid = tid >> 5;
    const int wm  = wid & 3;     // 4 M-groups of 64
    const int wn  = wid >> 2;    // 2 N-groups of 64
    const int m0  = blockIdx.y * 256;
    const int n0  = blockIdx.x * 128;
    const int niter = K / BK;

    GemmPtrs p; p.Ahi = Ahi; p.Alo = Alo; p.Bhi = Bhi; p.Blo = Blo;

    const uint32_t aRow  = (uint32_t)(wm * 64 + (l & 15));
    const uint32_t aXor  = aRow & 7;
    const uint32_t aHalf = (uint32_t)(l >> 4);
    const uint32_t bRow  = (uint32_t)(wn * 64 + (l & 7) + ((l >> 4) << 3));
    const uint32_t bXor  = bRow & 7;
    const uint32_t bHalf = (uint32_t)((l >> 3) & 1);

    float d[4][8][4];
#pragma unroll
    for (int mg = 0; mg < 4; ++mg)
#pragma unroll
        for (int j = 0; j < 8; ++j)
#pragma unroll
            for (int e = 0; e < 4; ++e) d[mg][j][e] = 0.0f;

    issue_stage2(sb, 0, p, m0, n0, 0, N, K, tid);

    for (int it = 0; it < niter; ++it) {
        CP_WAIT0();
        __syncthreads();
        if (it + 1 < niter)
            issue_stage2(sb, (it + 1) & 1, p, m0, n0, (it + 1) * BK, N, K, tid);

        const uint32_t st = sb + (it & 1) * STAGE2;
        const uint32_t sAhi = st;
        const uint32_t sAlo = st + 32768;
        const uint32_t sBhi = st + 65536;
        const uint32_t sBlo = st + 81920;

#pragma unroll
        for (int kk = 0; kk < 4; ++kk) {
            uint32_t ahi[4][4], alo[4][4], bhi[4][4], blo[4][4];
            const uint32_t ach = (((2 * kk + aHalf) ^ aXor) << 4);
            const uint32_t bch = (((2 * kk + bHalf) ^ bXor) << 4);
#pragma unroll
            for (int mg = 0; mg < 4; ++mg) {
                uint32_t off = (aRow + mg * 16) * 128 + ach;
                LDX4(ahi[mg][0], ahi[mg][1], ahi[mg][2], ahi[mg][3], sAhi + off);
                LDX4(alo[mg][0], alo[mg][1], alo[mg][2], alo[mg][3], sAlo + off);
            }
#pragma unroll
            for (int ng = 0; ng < 4; ++ng) {
                uint32_t off = (bRow + ng * 16) * 128 + bch;
                LDX4(bhi[ng][0], bhi[ng][1], bhi[ng][2], bhi[ng][3], sBhi + off);
                LDX4(blo[ng][0], blo[ng][1], blo[ng][2], blo[ng][3], sBlo + off);
            }
#pragma unroll
            for (int mg = 0; mg < 4; ++mg) {
#pragma unroll
                for (int ng = 0; ng < 4; ++ng) {
#pragma unroll
                    for (int hh = 0; hh < 2; ++hh) {
                        float* dd = d[mg][ng * 2 + hh];
                        MMA16816(dd[0], dd[1], dd[2], dd[3],
                                 ahi[mg][0], ahi[mg][1], ahi[mg][2], ahi[mg][3],
                                 bhi[ng][2 * hh], bhi[ng][2 * hh + 1]);
                        MMA16816(dd[0], dd[1], dd[2], dd[3],
                                 ahi[mg][0], ahi[mg][1], ahi[mg][2], ahi[mg][3],
                                 blo[ng][2 * hh], blo[ng][2 * hh + 1]);
                        MMA16816(dd[0], dd[1], dd[2], dd[3],
                                 alo[mg][0], alo[mg][1], alo[mg][2], alo[mg][3],
                                 bhi[ng][2 * hh], bhi[ng][2 * hh + 1]);
                    }
                }
            }
        }
    }

    // epilogue
#pragma unroll
    for (int mg = 0; mg < 4; ++mg) {
#pragma unroll
        for (int j = 0; j < 8; ++j) {
            int m = m0 + wm * 64 + mg * 16 + (l >> 2);
            int n = n0 + wn * 64 + j * 8 + 2 * (l & 3);
            if (n < N) {
                float v0 = d[mg][j][0] + bias[n];
                float v1 = d[mg][j][1] + bias[n + 1];
                float v2 = d[mg][j][2] + bias[n];
                float v3 = d[mg][j][3] + bias[n + 1];
                if (OMODE == 0) {
                    *(float2*)&C[(size_t)m * N + n] = make_float2(v0, v1);
                    *(float2*)&C[(size_t)(m + 8) * N + n] = make_float2(v2, v3);
                } else {
                    __nv_bfloat16 h0 = __float2bfloat16(v0);
                    __nv_bfloat16 h1 = __float2bfloat16(v1);
                    __nv_bfloat16 h2 = __float2bfloat16(v2);
                    __nv_bfloat16 h3 = __float2bfloat16(v3);
                    __nv_bfloat162 hp0(h0, h1), hp1(h2, h3);
                    __nv_bfloat162 lp0(__float2bfloat16(v0 - __bfloat162float(h0)),
                                       __float2bfloat16(v1 - __bfloat162float(h1)));
                    __nv_bfloat162 lp1(__float2bfloat16(v2 - __bfloat162float(h2)),
                                       __float2bfloat16(v3 - __bfloat162float(h3)));
                    *(__nv_bfloat162*)&Chi[(size_t)m * N + n] = hp0;
                    *(__nv_bfloat162*)&Chi[(size_t)(m + 8) * N + n] = hp1;
                    *(__nv_bfloat162*)&Clo[(size_t)m * N + n] = lp0;
                    *(__nv_bfloat162*)&Clo[(size_t)(m + 8) * N + n] = lp1;
                }
            }
        }
    }
}

// ---------------------------------------------------------------------------
// Fused bilinear as GEMM (unchanged from round 4):
// zT[c*80+q][b] = sum_s h0[b,s] * (Wb[c,q,s,:] . h1[b,:])
// ---------------------------------------------------------------------------
#define A_PITCH 176
#define B_PITCH 176
#define H0_PITCHF 84
#define SA_HI   0
#define SA_LO   28160
#define SB_BASE 56320
#define SB_STAGE 45056
#define SB_LOOFF 22528
#define SH0_BASE 146432
#define SH0_STAGE 43008
#define BIL_SMEM 232448
#define BSPLIT 2

__global__ __launch_bounds__(256, 1)
void bilq_kernel(const __nv_bfloat16* __restrict__ Wbhi,
                 const __nv_bfloat16* __restrict__ Wblo,
                 const __nv_bfloat16* __restrict__ h1hi,
                 const __nv_bfloat16* __restrict__ h1lo,
                 const float* __restrict__ h0g,
                 float* __restrict__ zT)
{
    extern __shared__ __align__(128) char smem[];
    const uint32_t sb = smem_u32(smem);
    const int tid = threadIdx.x;
    const int l   = tid & 31;
    const int wid = tid >> 5;
    const int wm  = wid >> 2;
    const int wn  = wid & 3;
    const int c     = blockIdx.z;
    const int q0    = blockIdx.y * 2;
    const int bhalf = blockIdx.x;
    const int NB = 64 / BSPLIT;

    {
        const size_t wb_base = (size_t)c * (SS * SS * SS) + (size_t)q0 * (SS * SS);
#pragma unroll
        for (int i = 0; i < 7; ++i) {
            int idx = tid + i * 256;
            if (idx < 1600) {
                int row = idx / 10, ch = idx % 10;
                size_t src = wb_base + (size_t)(row / 80) * (SS * SS)
                           + (size_t)(row % 80) * SS + ch * 8;
                uint32_t dst = sb + SA_HI + row * A_PITCH + ch * 16;
                CP16(dst, (const char*)(Wbhi + src));
                CP16(dst + SA_LO, (const char*)(Wblo + src));
            }
        }
    }

    auto issue_bt = [&](int st, int b0) {
        uint32_t sB = sb + SB_BASE + st * SB_STAGE;
#pragma unroll
        for (int i = 0; i < 5; ++i) {
            int idx = tid + i * 256;
            int r = idx / 10, ch = idx % 10;
            size_t src = (size_t)(b0 + r) * MM + c * SS + ch * 8;
            uint32_t dst = sB + r * B_PITCH + ch * 16;
            CP16(dst, (const char*)(h1hi + src));
            CP16(dst + SB_LOOFF, (const char*)(h1lo + src));
        }
        uint32_t sH = sb + SH0_BASE + st * SH0_STAGE;
#pragma unroll
        for (int i = 0; i < 10; ++i) {
            int idx = tid + i * 256;
            int r = idx / 20, ch = idx % 20;
            size_t src = (size_t)(b0 + r) * MM + c * SS + ch * 4;
            CP16(sH + r * (H0_PITCHF * 4) + ch * 16, (const char*)(h0g + src));
        }
        CP_COMMIT();
    };

    issue_bt(0, (bhalf * NB + 0) * 128);

    const uint32_t aRowOff  = (uint32_t)(wm * 80 + (l & 15)) * A_PITCH;
    const uint32_t aHalf    = (uint32_t)(l >> 4);
    const uint32_t bRowOff  = (uint32_t)((l & 7) + ((l >> 4) << 3)) * B_PITCH;
    const uint32_t bHalf    = (uint32_t)((l >> 3) & 1);

    for (int nIt = 0; nIt < NB; ++nIt) {
        const int b0 = (bhalf * NB + nIt) * 128;
        if (nIt + 1 < NB) {
            issue_bt((nIt + 1) & 1, (bhalf * NB + nIt + 1) * 128);
            CP_WAIT1();
        } else {
            CP_WAIT0();
        }
        __syncthreads();

        const int st = nIt & 1;
        const uint32_t sAhi = sb + SA_HI;
        const uint32_t sAlo = sb + SA_LO;
        const uint32_t sBhi = sb + SB_BASE + st * SB_STAGE;
        const uint32_t sBlo = sBhi + SB_LOOFF;
        const float* h0s = (const float*)(smem + SH0_BASE + st * SH0_STAGE);

        float d[5][4][4];
#pragma unroll
        for (int mt = 0; mt < 5; ++mt)
#pragma unroll
            for (int nt = 0; nt < 4; ++nt)
#pragma unroll
                for (int e = 0; e < 4; ++e) d[mt][nt][e] = 0.0f;

#pragma unroll
        for (int kk = 0; kk < 5; ++kk) {
            uint32_t ah[5][4], al[5][4], bh[2][4], bl[2][4];
            const uint32_t aco = ((2 * kk + aHalf) << 4);
            const uint32_t bco = ((2 * kk + bHalf) << 4);
#pragma unroll
            for (int mt = 0; mt < 5; ++mt) {
                uint32_t off = aRowOff + mt * 16 * A_PITCH + aco;
                LDX4(ah[mt][0], ah[mt][1], ah[mt][2], ah[mt][3], sAhi + off);
                LDX4(al[mt][0], al[mt][1], al[mt][2], al[mt][3], sAlo + off);
            }
#pragma unroll
            for (int pr = 0; pr < 2; ++pr) {
                uint32_t off = (uint32_t)(wn * 32 + pr * 16) * B_PITCH + bRowOff + bco;
                LDX4(bh[pr][0], bh[pr][1], bh[pr][2], bh[pr][3], sBhi + off);
                LDX4(bl[pr][0], bl[pr][1], bl[pr][2], bl[pr][3], sBlo + off);
            }
#pragma unroll
            for (int mt = 0; mt < 5; ++mt) {
#pragma unroll
                for (int pr = 0; pr < 2; ++pr) {
#pragma unroll
                    for (int hh = 0; hh < 2; ++hh) {
                        int nt = pr * 2 + hh;
                        float* dd = d[mt][nt];
                        MMA16816(dd[0], dd[1], dd[2], dd[3],
                                 ah[mt][0], ah[mt][1], ah[mt][2], ah[mt][3],
                                 bh[pr][2 * hh], bh[pr][2 * hh + 1]);
                        MMA16816(dd[0], dd[1], dd[2], dd[3],
                                 ah[mt][0], ah[mt][1], ah[mt][2], ah[mt][3],
                                 bl[pr][2 * hh], bl[pr][2 * hh + 1]);
                        MMA16816(dd[0], dd[1], dd[2], dd[3],
                                 al[mt][0], al[mt][1], al[mt][2], al[mt][3],
                                 bh[pr][2 * hh], bh[pr][2 * hh + 1]);
                    }
                }
            }
        }

        float p8[8];
#pragma unroll
        for (int i = 0; i < 8; ++i) p8[i] = 0.0f;
#pragma unroll
        for (int mt = 0; mt < 5; ++mt) {
#pragma unroll
            for (int e = 0; e < 4; ++e) {
                int s = mt * 16 + (l >> 2) + 8 * (e >> 1);
#pragma unroll
                for (int nt = 0; nt < 4; ++nt) {
                    int bl_ = wn * 32 + nt * 8 + 2 * (l & 3) + (e & 1);
                    p8[nt * 2 + (e & 1)] += d[mt][nt][e] * h0s[bl_ * H0_PITCHF + s];
                }
            }
        }
#pragma unroll
        for (int pi = 0; pi < 8; ++pi) {
            float v = p8[pi];
            v += __shfl_xor_sync(0xffffffffu, v, 4);
            v += __shfl_xor_sync(0xffffffffu, v, 8);
            v += __shfl_xor_sync(0xffffffffu, v, 16);
            p8[pi] = v;
        }
        if (l < 4) {
            int feat = c * SS + q0 + wm;
            float* dst = zT + (size_t)feat * BB + b0 + wn * 32 + 2 * l;
#pragma unroll
            for (int nt = 0; nt < 4; ++nt)
                *(float2*)(dst + nt * 8) = make_float2(p8[nt * 2], p8[nt * 2 + 1]);
        }
        __syncthreads();
    }
}

// ---------------------------------------------------------------------------
// norm: z = signed_sqrt(zT + bb); per-chunk L2 normalize; emit bf16 hi/lo.
// ---------------------------------------------------------------------------
__global__ __launch_bounds__(256)
void norm_kernel(const float* __restrict__ zT, const float* __restrict__ bbv,
                 __nv_bfloat16* __restrict__ zhi, __nv_bfloat16* __restrict__ zlo)
{
    __shared__ float zs[80 * 129];
    __shared__ float bbs[80];
    __shared__ float scl[128];
    const int tid = threadIdx.x;
    const int c = blockIdx.y;
    const int b0 = blockIdx.x * 128;

    if (tid < 80) bbs[tid] = bbv[c * SS + tid];
#pragma unroll
    for (int i = 0; i < 40; ++i) {
        int idx = tid + i * 256;
        int q = idx >> 7, col = idx & 127;
        zs[q * 129 + col] = zT[(size_t)(c * SS + q) * BB + b0 + col];
    }
    __syncthreads();
    if (tid < 128) {
        float s = 0.0f;
#pragma unroll 4
        for (int q = 0; q < 80; ++q) s += fabsf(zs[q * 129 + tid] + bbs[q]);
        scl[tid] = 1.0f / fmaxf(sqrtf(s), 1e-12f);
    }
    __syncthreads();
#pragma unroll
    for (int i = 0; i < 40; ++i) {
        int idx = tid + i * 256;
        int b = idx / 80, q = idx % 80;
        float v = zs[q * 129 + b] + bbs[q];
        float sv = copysignf(sqrtf(fabsf(v)), v) * scl[b];
        __nv_bfloat16 h = __float2bfloat16(sv);
        __nv_bfloat16 lo = __float2bfloat16(sv - __bfloat162float(h));
        size_t o = (size_t)(b0 + b) * MM + c * SS + q;
        zhi[o] = h;
        zlo[o] = lo;
    }
}

// ---------------------------------------------------------------------------
// launch
// ---------------------------------------------------------------------------
extern "C" void kernel_launch(void* const* d_in, const int* in_sizes, int n_in,
                              void* d_out, int out_size)
{
    (void)in_sizes; (void)n_in; (void)out_size;
    const float* x0   = (const float*)d_in[0];
    const float* x1   = (const float*)d_in[1];
    const float* W0   = (const float*)d_in[2];
    const float* b0   = (const float*)d_in[3];
    const float* W1   = (const float*)d_in[4];
    const float* b1   = (const float*)d_in[5];
    const float* Wb   = (const float*)d_in[6];
    const float* bb   = (const float*)d_in[7];
    const float* Wout = (const float*)d_in[8];
    const float* bout = (const float*)d_in[9];
    float* out = (float*)d_out;

    float *h0p, *zTp;
    cudaGetSymbolAddress((void**)&h0p, g_h0);
    cudaGetSymbolAddress((void**)&zTp, g_zT);
    void *x0hi, *x0lo, *x1hi, *x1lo, *W0hi, *W0lo, *W1hi, *W1lo;
    void *Wohi, *Wolo, *Wbhi, *Wblo, *h1hi, *h1lo, *zhi, *zlo;
    cudaGetSymbolAddress(&x0hi, g_x0hi); cudaGetSymbolAddress(&x0lo, g_x0lo);
    cudaGetSymbolAddress(&x1hi, g_x1hi); cudaGetSymbolAddress(&x1lo, g_x1lo);
    cudaGetSymbolAddress(&W0hi, g_W0hi); cudaGetSymbolAddress(&W0lo, g_W0lo);
    cudaGetSymbolAddress(&W1hi, g_W1hi); cudaGetSymbolAddress(&W1lo, g_W1lo);
    cudaGetSymbolAddress(&Wohi, g_Wouthi); cudaGetSymbolAddress(&Wolo, g_Woutlo);
    cudaGetSymbolAddress(&Wbhi, g_Wbhi); cudaGetSymbolAddress(&Wblo, g_Wblo);
    cudaGetSymbolAddress(&h1hi, g_h1hi); cudaGetSymbolAddress(&h1lo, g_h1lo);
    cudaGetSymbolAddress(&zhi, g_zhi); cudaGetSymbolAddress(&zlo, g_zlo);

    // 1) split static inputs
    {
        int n4;
        n4 = BB * DIN / 4;
        split_bf16<<<(n4 + 255) / 256, 256>>>(x0, (__nv_bfloat16*)x0hi, (__nv_bfloat16*)x0lo, n4);
        split_bf16<<<(n4 + 255) / 256, 256>>>(x1, (__nv_bfloat16*)x1hi, (__nv_bfloat16*)x1lo, n4);
        n4 = MM * DIN / 4;
        split_bf16<<<(n4 + 255) / 256, 256>>>(W0, (__nv_bfloat16*)W0hi, (__nv_bfloat16*)W0lo, n4);
        split_bf16<<<(n4 + 255) / 256, 256>>>(W1, (__nv_bfloat16*)W1hi, (__nv_bfloat16*)W1lo, n4);
        n4 = OUTN * MM / 4;
        split_bf16<<<(n4 + 255) / 256, 256>>>(Wout, (__nv_bfloat16*)Wohi, (__nv_bfloat16*)Wolo, n4);
        n4 = CC * SS * SS * SS / 4;
        split_bf16<<<(n4 + 255) / 256, 256>>>(Wb, (__nv_bfloat16*)Wbhi, (__nv_bfloat16*)Wblo, n4);
    }

    cudaFuncSetAttribute(tc_gemm_nt2<0>, cudaFuncAttributeMaxDynamicSharedMemorySize, GEMM_SMEM2);
    cudaFuncSetAttribute(tc_gemm_nt2<1>, cudaFuncAttributeMaxDynamicSharedMemorySize, GEMM_SMEM2);
    cudaFuncSetAttribute(bilq_kernel, cudaFuncAttributeMaxDynamicSharedMemorySize, BIL_SMEM);

    // 2) h0 = x0 @ W0^T + b0 (fp32); h1 = x1 @ W1^T + b1 (bf16 hi/lo direct)
    {
        dim3 grid((MM + 127) / 128, BB / 256);
        tc_gemm_nt2<0><<<grid, 256, GEMM_SMEM2>>>(
            (const __nv_bfloat16*)x0hi, (const __nv_bfloat16*)x0lo,
            (const __nv_bfloat16*)W0hi, (const __nv_bfloat16*)W0lo, b0,
            h0p, nullptr, nullptr, MM, DIN);
        tc_gemm_nt2<1><<<grid, 256, GEMM_SMEM2>>>(
            (const __nv_bfloat16*)x1hi, (const __nv_bfloat16*)x1lo,
            (const __nv_bfloat16*)W1hi, (const __nv_bfloat16*)W1lo, b1,
            nullptr, (__nv_bfloat16*)h1hi, (__nv_bfloat16*)h1lo, MM, DIN);
    }

    // 3) fused bilinear (tensor cores) -> zT
    {
        dim3 grid(BSPLIT, SS / 2, CC);
        bilq_kernel<<<grid, 256, BIL_SMEM>>>(
            (const __nv_bfloat16*)Wbhi, (const __nv_bfloat16*)Wblo,
            (const __nv_bfloat16*)h1hi, (const __nv_bfloat16*)h1lo,
            h0p, zTp);
    }

    // 4) bias + signed sqrt + normalize + bf16 split
    {
        dim3 grid(BB / 128, CC);
        norm_kernel<<<grid, 256>>>(zTp, bb, (__nv_bfloat16*)zhi, (__nv_bfloat16*)zlo);
    }

    // 5) out = z @ Wout^T + bout
    {
        dim3 grid((OUTN + 127) / 128, BB / 256);
        tc_gemm_nt2<0><<<grid, 256, GEMM_SMEM2>>>(
            (const __nv_bfloat16*)zhi, (const __nv_bfloat16*)zlo,
            (const __nv_bfloat16*)Wohi, (const __nv_bfloat16*)Wolo, bout,
            out, nullptr, nullptr, OUTN, MM);
    }
}

// round 6
// speedup vs baseline: 4.6064x; 1.3169x over previous
#include <cuda_runtime.h>
#include <cuda_fp16.h>
#include <math.h>
#include <stdint.h>

// Problem constants
#define BB    8192
#define DIN   2048
#define MM    1600
#define CC    20
#define SS    80
#define OUTN  3000

// ---------------------------------------------------------------------------
// Scratch (static device globals)
// ---------------------------------------------------------------------------
__device__ float g_h0[(size_t)BB * MM];
__device__ float g_zT[(size_t)MM * BB];

__device__ __half g_x0h[(size_t)BB * DIN];
__device__ __half g_x1h[(size_t)BB * DIN];
__device__ __half g_W0hi[(size_t)MM * DIN];
__device__ __half g_W0lo[(size_t)MM * DIN];
__device__ __half g_W1hi[(size_t)MM * DIN];
__device__ __half g_W1lo[(size_t)MM * DIN];
__device__ __half g_Wouthi[(size_t)OUTN * MM];
__device__ __half g_Woutlo[(size_t)OUTN * MM];
__device__ __half g_Wbh[(size_t)CC * SS * SS * SS];
__device__ __half g_h1hi[(size_t)BB * MM];
__device__ __half g_h1lo[(size_t)BB * MM];
__device__ __half g_zh[(size_t)BB * MM];

// ---------------------------------------------------------------------------
// Low-level helpers
// ---------------------------------------------------------------------------
__device__ __forceinline__ uint32_t smem_u32(const void* p) {
    uint32_t a;
    asm("{ .reg .u64 t; cvta.to.shared.u64 t, %1; cvt.u32.u64 %0, t; }"
        : "=r"(a) : "l"(p));
    return a;
}

#define CP16(dst, src) \
    asm volatile("cp.async.cg.shared.global [%0], [%1], 16;" \
                 :: "r"(dst), "l"(src) : "memory")
#define CP16P(dst, src, nbytes) \
    asm volatile("cp.async.cg.shared.global [%0], [%1], 16, %2;" \
                 :: "r"(dst), "l"(src), "r"(nbytes) : "memory")
#define CP_COMMIT() asm volatile("cp.async.commit_group;" ::: "memory")
#define CP_WAIT0()  asm volatile("cp.async.wait_group 0;" ::: "memory")
#define CP_WAIT1()  asm volatile("cp.async.wait_group 1;" ::: "memory")

#define LDX4(r0, r1, r2, r3, addr) \
    asm volatile("ldmatrix.sync.aligned.m8n8.x4.shared.b16 {%0,%1,%2,%3}, [%4];" \
                 : "=r"(r0), "=r"(r1), "=r"(r2), "=r"(r3) : "r"(addr))

#define MMAH(d0, d1, d2, d3, a0, a1, a2, a3, b0, b1) \
    asm volatile("mma.sync.aligned.m16n8k16.row.col.f32.f16.f16.f32 " \
                 "{%0,%1,%2,%3}, {%4,%5,%6,%7}, {%8,%9}, {%0,%1,%2,%3};" \
                 : "+f"(d0), "+f"(d1), "+f"(d2), "+f"(d3) \
                 : "r"(a0), "r"(a1), "r"(a2), "r"(a3), "r"(b0), "r"(b1))

// ---------------------------------------------------------------------------
// fp32 -> fp16 convert (hi only) and hi/lo split
// ---------------------------------------------------------------------------
__global__ __launch_bounds__(256)
void cvt_fp16(const float* __restrict__ in, __half* __restrict__ out, int n4)
{
    int i = blockIdx.x * blockDim.x + threadIdx.x;
    if (i >= n4) return;
    float4 v = ((const float4*)in)[i];
    __half2 a = __halves2half2(__float2half(v.x), __float2half(v.y));
    __half2 b = __halves2half2(__float2half(v.z), __float2half(v.w));
    uint2 o;
    o.x = *(uint32_t*)&a; o.y = *(uint32_t*)&b;
    ((uint2*)out)[i] = o;
}

__global__ __launch_bounds__(256)
void split_fp16(const float* __restrict__ in, __half* __restrict__ hi,
                __half* __restrict__ lo, int n4)
{
    int i = blockIdx.x * blockDim.x + threadIdx.x;
    if (i >= n4) return;
    float4 v = ((const float4*)in)[i];
    __half h0 = __float2half(v.x), h1 = __float2half(v.y);
    __half h2 = __float2half(v.z), h3 = __float2half(v.w);
    __half l0 = __float2half(v.x - __half2float(h0));
    __half l1 = __float2half(v.y - __half2float(h1));
    __half l2 = __float2half(v.z - __half2float(h2));
    __half l3 = __float2half(v.w - __half2float(h3));
    __half2 hv0 = __halves2half2(h0, h1), hv1 = __halves2half2(h2, h3);
    __half2 lv0 = __halves2half2(l0, l1), lv1 = __halves2half2(l2, l3);
    uint2 hp, lp;
    hp.x = *(uint32_t*)&hv0; hp.y = *(uint32_t*)&hv1;
    lp.x = *(uint32_t*)&lv0; lp.y = *(uint32_t*)&lv1;
    ((uint2*)hi)[i] = hp;
    ((uint2*)lo)[i] = lp;
}

// ---------------------------------------------------------------------------
// fp16 2-product NT GEMM: C = A * (Bhi+Blo)^T + bias.
// CTA 256x128xBK64, 8 warps (64x64), 3-stage cp.async.
// OMODE 0: fp32 C.  OMODE 1: fp16 hi/lo pair.
// ---------------------------------------------------------------------------
#define BK 64
#define STAGE3 65536     // A 32K | Bhi 16K | Blo 16K
#define GEMM_SMEM3 (3 * STAGE3)

__device__ __forceinline__ void issue_stage3(
    uint32_t sbase, int stage,
    const __half* __restrict__ A, const __half* __restrict__ Bhi,
    const __half* __restrict__ Blo,
    int m0, int n0, int k0, int N, int K, int tid)
{
    uint32_t st = sbase + stage * STAGE3;
#pragma unroll
    for (int i = 0; i < 8; ++i) {
        int idx = tid + i * 256;
        int r = idx >> 3;
        int c = idx & 7;
        uint32_t dst = (uint32_t)(r * 128 + ((c ^ (r & 7)) << 4));
        size_t aoff = (size_t)(m0 + r) * K + k0 + c * 8;
        CP16(st + dst, (const char*)(A + aoff));
    }
#pragma unroll
    for (int i = 0; i < 4; ++i) {
        int idx = tid + i * 256;
        int r = idx >> 3;
        int c = idx & 7;
        uint32_t dst = (uint32_t)(r * 128 + ((c ^ (r & 7)) << 4));
        int n = n0 + r;
        int pred = (n < N) ? 16 : 0;
        int ncl = (n < N) ? n : (N - 1);
        size_t boff = (size_t)ncl * K + k0 + c * 8;
        CP16P(st + 32768 + dst, (const char*)(Bhi + boff), pred);
        CP16P(st + 49152 + dst, (const char*)(Blo + boff), pred);
    }
    CP_COMMIT();
}

template <int OMODE>
__global__ __launch_bounds__(256, 1)
void tc_gemm3(const __half* __restrict__ A,
              const __half* __restrict__ Bhi,
              const __half* __restrict__ Blo,
              const float* __restrict__ bias,
              float* __restrict__ C,
              __half* __restrict__ Chi,
              __half* __restrict__ Clo,
              int N, int K)
{
    extern __shared__ __align__(128) char smem[];
    const uint32_t sb = smem_u32(smem);

    const int tid = threadIdx.x;
    const int l   = tid & 31;
    const int wid = tid >> 5;
    const int wm  = wid & 3;
    const int wn  = wid >> 2;
    const int m0  = blockIdx.y * 256;
    const int n0  = blockIdx.x * 128;
    const int niter = K / BK;

    const uint32_t aRow  = (uint32_t)(wm * 64 + (l & 15));
    const uint32_t aXor  = aRow & 7;
    const uint32_t aHalf = (uint32_t)(l >> 4);
    const uint32_t bRow  = (uint32_t)(wn * 64 + (l & 7) + ((l >> 4) << 3));
    const uint32_t bXor  = bRow & 7;
    const uint32_t bHalf = (uint32_t)((l >> 3) & 1);

    float d[4][8][4];
#pragma unroll
    for (int mg = 0; mg < 4; ++mg)
#pragma unroll
        for (int j = 0; j < 8; ++j)
#pragma unroll
            for (int e = 0; e < 4; ++e) d[mg][j][e] = 0.0f;

    issue_stage3(sb, 0, A, Bhi, Blo, m0, n0, 0, N, K, tid);
    if (niter > 1) issue_stage3(sb, 1, A, Bhi, Blo, m0, n0, BK, N, K, tid);

    for (int it = 0; it < niter; ++it) {
        if (it < niter - 1) CP_WAIT1(); else CP_WAIT0();
        __syncthreads();
        if (it + 2 < niter)
            issue_stage3(sb, (it + 2) % 3, A, Bhi, Blo, m0, n0, (it + 2) * BK, N, K, tid);

        const uint32_t st = sb + (it % 3) * STAGE3;
        const uint32_t sA   = st;
        const uint32_t sBhi = st + 32768;
        const uint32_t sBlo = st + 49152;

#pragma unroll
        for (int kk = 0; kk < 4; ++kk) {
            uint32_t ah[4][4], bh[4][4], bl[4][4];
            const uint32_t ach = (((2 * kk + aHalf) ^ aXor) << 4);
            const uint32_t bch = (((2 * kk + bHalf) ^ bXor) << 4);
#pragma unroll
            for (int mg = 0; mg < 4; ++mg) {
                uint32_t off = (aRow + mg * 16) * 128 + ach;
                LDX4(ah[mg][0], ah[mg][1], ah[mg][2], ah[mg][3], sA + off);
            }
#pragma unroll
            for (int ng = 0; ng < 4; ++ng) {
                uint32_t off = (bRow + ng * 16) * 128 + bch;
                LDX4(bh[ng][0], bh[ng][1], bh[ng][2], bh[ng][3], sBhi + off);
                LDX4(bl[ng][0], bl[ng][1], bl[ng][2], bl[ng][3], sBlo + off);
            }
#pragma unroll
            for (int mg = 0; mg < 4; ++mg) {
#pragma unroll
                for (int ng = 0; ng < 4; ++ng) {
#pragma unroll
                    for (int hh = 0; hh < 2; ++hh) {
                        float* dd = d[mg][ng * 2 + hh];
                        MMAH(dd[0], dd[1], dd[2], dd[3],
                             ah[mg][0], ah[mg][1], ah[mg][2], ah[mg][3],
                             bh[ng][2 * hh], bh[ng][2 * hh + 1]);
                        MMAH(dd[0], dd[1], dd[2], dd[3],
                             ah[mg][0], ah[mg][1], ah[mg][2], ah[mg][3],
                             bl[ng][2 * hh], bl[ng][2 * hh + 1]);
                    }
                }
            }
        }
    }

#pragma unroll
    for (int mg = 0; mg < 4; ++mg) {
#pragma unroll
        for (int j = 0; j < 8; ++j) {
            int m = m0 + wm * 64 + mg * 16 + (l >> 2);
            int n = n0 + wn * 64 + j * 8 + 2 * (l & 3);
            if (n < N) {
                float v0 = d[mg][j][0] + bias[n];
                float v1 = d[mg][j][1] + bias[n + 1];
                float v2 = d[mg][j][2] + bias[n];
                float v3 = d[mg][j][3] + bias[n + 1];
                if (OMODE == 0) {
                    *(float2*)&C[(size_t)m * N + n] = make_float2(v0, v1);
                    *(float2*)&C[(size_t)(m + 8) * N + n] = make_float2(v2, v3);
                } else {
                    __half h0_ = __float2half(v0), h1_ = __float2half(v1);
                    __half h2_ = __float2half(v2), h3_ = __float2half(v3);
                    __half2 hp0 = __halves2half2(h0_, h1_);
                    __half2 hp1 = __halves2half2(h2_, h3_);
                    __half2 lp0 = __halves2half2(
                        __float2half(v0 - __half2float(h0_)),
                        __float2half(v1 - __half2float(h1_)));
                    __half2 lp1 = __halves2half2(
                        __float2half(v2 - __half2float(h2_)),
                        __float2half(v3 - __half2float(h3_)));
                    *(__half2*)&Chi[(size_t)m * N + n] = hp0;
                    *(__half2*)&Chi[(size_t)(m + 8) * N + n] = hp1;
                    *(__half2*)&Clo[(size_t)m * N + n] = lp0;
                    *(__half2*)&Clo[(size_t)(m + 8) * N + n] = lp1;
                }
            }
        }
    }
}

// ---------------------------------------------------------------------------
// Fused bilinear (fp16 2-product):
// zT[c*80+q][b] = sum_s h0[b,s] * (Wb[c,q,s,:] . h1[b,:])
// A = Wb fp16 hi (CTA-resident), B = h1 hi/lo (2-stage), h0 fp32 epilogue.
// ---------------------------------------------------------------------------
#define A_PITCH 176
#define B_PITCH 176
#define H0_PITCHF 84
#define SB_BASE 28160       // after A (160*176)
#define SB_STAGE 45056
#define SB_LOOFF 22528
#define SH0_BASE 118272     // SB_BASE + 2*SB_STAGE
#define SH0_STAGE 43008
#define BIL_SMEM 204288
#define BSPLIT 2

__global__ __launch_bounds__(256, 1)
void bilq_kernel(const __half* __restrict__ Wbh,
                 const __half* __restrict__ h1hi,
                 const __half* __restrict__ h1lo,
                 const float* __restrict__ h0g,
                 float* __restrict__ zT)
{
    extern __shared__ __align__(128) char smem[];
    const uint32_t sb = smem_u32(smem);
    const int tid = threadIdx.x;
    const int l   = tid & 31;
    const int wid = tid >> 5;
    const int wm  = wid >> 2;
    const int wn  = wid & 3;
    const int c     = blockIdx.z;
    const int q0    = blockIdx.y * 2;
    const int bhalf = blockIdx.x;
    const int NB = 64 / BSPLIT;

    {
        const size_t wb_base = (size_t)c * (SS * SS * SS) + (size_t)q0 * (SS * SS);
#pragma unroll
        for (int i = 0; i < 7; ++i) {
            int idx = tid + i * 256;
            if (idx < 1600) {
                int row = idx / 10, ch = idx % 10;
                size_t src = wb_base + (size_t)(row / 80) * (SS * SS)
                           + (size_t)(row % 80) * SS + ch * 8;
                CP16(sb + row * A_PITCH + ch * 16, (const char*)(Wbh + src));
            }
        }
    }

    auto issue_bt = [&](int st, int b0) {
        uint32_t sB = sb + SB_BASE + st * SB_STAGE;
#pragma unroll
        for (int i = 0; i < 5; ++i) {
            int idx = tid + i * 256;
            int r = idx / 10, ch = idx % 10;
            size_t src = (size_t)(b0 + r) * MM + c * SS + ch * 8;
            uint32_t dst = sB + r * B_PITCH + ch * 16;
            CP16(dst, (const char*)(h1hi + src));
            CP16(dst + SB_LOOFF, (const char*)(h1lo + src));
        }
        uint32_t sH = sb + SH0_BASE + st * SH0_STAGE;
#pragma unroll
        for (int i = 0; i < 10; ++i) {
            int idx = tid + i * 256;
            int r = idx / 20, ch = idx % 20;
            size_t src = (size_t)(b0 + r) * MM + c * SS + ch * 4;
            CP16(sH + r * (H0_PITCHF * 4) + ch * 16, (const char*)(h0g + src));
        }
        CP_COMMIT();
    };

    issue_bt(0, (bhalf * NB + 0) * 128);

    const uint32_t aRowOff  = (uint32_t)(wm * 80 + (l & 15)) * A_PITCH;
    const uint32_t aHalf    = (uint32_t)(l >> 4);
    const uint32_t bRowOff  = (uint32_t)((l & 7) + ((l >> 4) << 3)) * B_PITCH;
    const uint32_t bHalf    = (uint32_t)((l >> 3) & 1);

    for (int nIt = 0; nIt < NB; ++nIt) {
        const int b0 = (bhalf * NB + nIt) * 128;
        if (nIt + 1 < NB) {
            issue_bt((nIt + 1) & 1, (bhalf * NB + nIt + 1) * 128);
            CP_WAIT1();
        } else {
            CP_WAIT0();
        }
        __syncthreads();

        const int st = nIt & 1;
        const uint32_t sA = sb;
        const uint32_t sBhi = sb + SB_BASE + st * SB_STAGE;
        const uint32_t sBlo = sBhi + SB_LOOFF;
        const float* h0s = (const float*)(smem + SH0_BASE + st * SH0_STAGE);

        float d[5][4][4];
#pragma unroll
        for (int mt = 0; mt < 5; ++mt)
#pragma unroll
            for (int nt = 0; nt < 4; ++nt)
#pragma unroll
                for (int e = 0; e < 4; ++e) d[mt][nt][e] = 0.0f;

#pragma unroll
        for (int kk = 0; kk < 5; ++kk) {
            uint32_t ah[5][4], bh[2][4], bl[2][4];
            const uint32_t aco = ((2 * kk + aHalf) << 4);
            const uint32_t bco = ((2 * kk + bHalf) << 4);
#pragma unroll
            for (int mt = 0; mt < 5; ++mt) {
                uint32_t off = aRowOff + mt * 16 * A_PITCH + aco;
                LDX4(ah[mt][0], ah[mt][1], ah[mt][2], ah[mt][3], sA + off);
            }
#pragma unroll
            for (int pr = 0; pr < 2; ++pr) {
                uint32_t off = (uint32_t)(wn * 32 + pr * 16) * B_PITCH + bRowOff + bco;
                LDX4(bh[pr][0], bh[pr][1], bh[pr][2], bh[pr][3], sBhi + off);
                LDX4(bl[pr][0], bl[pr][1], bl[pr][2], bl[pr][3], sBlo + off);
            }
#pragma unroll
            for (int mt = 0; mt < 5; ++mt) {
#pragma unroll
                for (int pr = 0; pr < 2; ++pr) {
#pragma unroll
                    for (int hh = 0; hh < 2; ++hh) {
                        int nt = pr * 2 + hh;
                        float* dd = d[mt][nt];
                        MMAH(dd[0], dd[1], dd[2], dd[3],
                             ah[mt][0], ah[mt][1], ah[mt][2], ah[mt][3],
                             bh[pr][2 * hh], bh[pr][2 * hh + 1]);
                        MMAH(dd[0], dd[1], dd[2], dd[3],
                             ah[mt][0], ah[mt][1], ah[mt][2], ah[mt][3],
                             bl[pr][2 * hh], bl[pr][2 * hh + 1]);
                    }
                }
            }
        }

        float p8[8];
#pragma unroll
        for (int i = 0; i < 8; ++i) p8[i] = 0.0f;
#pragma unroll
        for (int mt = 0; mt < 5; ++mt) {
#pragma unroll
            for (int e = 0; e < 4; ++e) {
                int s = mt * 16 + (l >> 2) + 8 * (e >> 1);
#pragma unroll
                for (int nt = 0; nt < 4; ++nt) {
                    int bl_ = wn * 32 + nt * 8 + 2 * (l & 3) + (e & 1);
                    p8[nt * 2 + (e & 1)] += d[mt][nt][e] * h0s[bl_ * H0_PITCHF + s];
                }
            }
        }
#pragma unroll
        for (int pi = 0; pi < 8; ++pi) {
            float v = p8[pi];
            v += __shfl_xor_sync(0xffffffffu, v, 4);
            v += __shfl_xor_sync(0xffffffffu, v, 8);
            v += __shfl_xor_sync(0xffffffffu, v, 16);
            p8[pi] = v;
        }
        if (l < 4) {
            int feat = c * SS + q0 + wm;
            float* dst = zT + (size_t)feat * BB + b0 + wn * 32 + 2 * l;
#pragma unroll
            for (int nt = 0; nt < 4; ++nt)
                *(float2*)(dst + nt * 8) = make_float2(p8[nt * 2], p8[nt * 2 + 1]);
        }
        __syncthreads();
    }
}

// ---------------------------------------------------------------------------
// norm: z = signed_sqrt(zT + bb); per-chunk L2 normalize; emit fp16.
// ---------------------------------------------------------------------------
__global__ __launch_bounds__(256)
void norm_kernel(const float* __restrict__ zT, const float* __restrict__ bbv,
                 __half* __restrict__ zh)
{
    __shared__ float zs[80 * 129];
    __shared__ float bbs[80];
    __shared__ float scl[128];
    const int tid = threadIdx.x;
    const int c = blockIdx.y;
    const int b0 = blockIdx.x * 128;

    if (tid < 80) bbs[tid] = bbv[c * SS + tid];
#pragma unroll
    for (int i = 0; i < 40; ++i) {
        int idx = tid + i * 256;
        int q = idx >> 7, col = idx & 127;
        zs[q * 129 + col] = zT[(size_t)(c * SS + q) * BB + b0 + col];
    }
    __syncthreads();
    if (tid < 128) {
        float s = 0.0f;
#pragma unroll 4
        for (int q = 0; q < 80; ++q) s += fabsf(zs[q * 129 + tid] + bbs[q]);
        scl[tid] = 1.0f / fmaxf(sqrtf(s), 1e-12f);
    }
    __syncthreads();
#pragma unroll
    for (int i = 0; i < 40; ++i) {
        int idx = tid + i * 256;
        int b = idx / 80, q = idx % 80;
        float v = zs[q * 129 + b] + bbs[q];
        float sv = copysignf(sqrtf(fabsf(v)), v) * scl[b];
        zh[(size_t)(b0 + b) * MM + c * SS + q] = __float2half(sv);
    }
}

// ---------------------------------------------------------------------------
// launch
// ---------------------------------------------------------------------------
extern "C" void kernel_launch(void* const* d_in, const int* in_sizes, int n_in,
                              void* d_out, int out_size)
{
    (void)in_sizes; (void)n_in; (void)out_size;
    const float* x0   = (const float*)d_in[0];
    const float* x1   = (const float*)d_in[1];
    const float* W0   = (const float*)d_in[2];
    const float* b0   = (const float*)d_in[3];
    const float* W1   = (const float*)d_in[4];
    const float* b1   = (const float*)d_in[5];
    const float* Wb   = (const float*)d_in[6];
    const float* bb   = (const float*)d_in[7];
    const float* Wout = (const float*)d_in[8];
    const float* bout = (const float*)d_in[9];
    float* out = (float*)d_out;

    float *h0p, *zTp;
    cudaGetSymbolAddress((void**)&h0p, g_h0);
    cudaGetSymbolAddress((void**)&zTp, g_zT);
    void *x0h, *x1h, *W0hi, *W0lo, *W1hi, *W1lo, *Wohi, *Wolo, *Wbh;
    void *h1hi, *h1lo, *zh;
    cudaGetSymbolAddress(&x0h, g_x0h);  cudaGetSymbolAddress(&x1h, g_x1h);
    cudaGetSymbolAddress(&W0hi, g_W0hi); cudaGetSymbolAddress(&W0lo, g_W0lo);
    cudaGetSymbolAddress(&W1hi, g_W1hi); cudaGetSymbolAddress(&W1lo, g_W1lo);
    cudaGetSymbolAddress(&Wohi, g_Wouthi); cudaGetSymbolAddress(&Wolo, g_Woutlo);
    cudaGetSymbolAddress(&Wbh, g_Wbh);
    cudaGetSymbolAddress(&h1hi, g_h1hi); cudaGetSymbolAddress(&h1lo, g_h1lo);
    cudaGetSymbolAddress(&zh, g_zh);

    cudaFuncSetAttribute(tc_gemm3<0>, cudaFuncAttributeMaxDynamicSharedMemorySize, GEMM_SMEM3);
    cudaFuncSetAttribute(tc_gemm3<1>, cudaFuncAttributeMaxDynamicSharedMemorySize, GEMM_SMEM3);
    cudaFuncSetAttribute(bilq_kernel, cudaFuncAttributeMaxDynamicSharedMemorySize, BIL_SMEM);

    // launches 0-3: converts/splits needed by the two input GEMMs
    {
        int n4 = BB * DIN / 4;
        cvt_fp16<<<(n4 + 255) / 256, 256>>>(x0, (__half*)x0h, n4);
        cvt_fp16<<<(n4 + 255) / 256, 256>>>(x1, (__half*)x1h, n4);
        n4 = MM * DIN / 4;
        split_fp16<<<(n4 + 255) / 256, 256>>>(W0, (__half*)W0hi, (__half*)W0lo, n4);
        split_fp16<<<(n4 + 255) / 256, 256>>>(W1, (__half*)W1hi, (__half*)W1lo, n4);
    }

    // launches 4-5: input GEMMs (launch index 5 = h1 GEMM gets profiled by ncu)
    {
        dim3 grid((MM + 127) / 128, BB / 256);
        tc_gemm3<0><<<grid, 256, GEMM_SMEM3>>>(
            (const __half*)x0h, (const __half*)W0hi, (const __half*)W0lo, b0,
            h0p, nullptr, nullptr, MM, DIN);
        tc_gemm3<1><<<grid, 256, GEMM_SMEM3>>>(
            (const __half*)x1h, (const __half*)W1hi, (const __half*)W1lo, b1,
            nullptr, (__half*)h1hi, (__half*)h1lo, MM, DIN);
    }

    // remaining converts
    {
        int n4 = OUTN * MM / 4;
        split_fp16<<<(n4 + 255) / 256, 256>>>(Wout, (__half*)Wohi, (__half*)Wolo, n4);
        n4 = CC * SS * SS * SS / 4;
        cvt_fp16<<<(n4 + 255) / 256, 256>>>(Wb, (__half*)Wbh, n4);
    }

    // fused bilinear -> zT
    {
        dim3 grid(BSPLIT, SS / 2, CC);
        bilq_kernel<<<grid, 256, BIL_SMEM>>>(
            (const __half*)Wbh, (const __half*)h1hi, (const __half*)h1lo,
            h0p, zTp);
    }

    // bias + signed sqrt + normalize -> fp16 z
    {
        dim3 grid(BB / 128, CC);
        norm_kernel<<<grid, 256>>>(zTp, bb, (__half*)zh);
    }

    // out = z @ Wout^T + bout
    {
        dim3 grid((OUTN + 127) / 128, BB / 256);
        tc_gemm3<0><<<grid, 256, GEMM_SMEM3>>>(
            (const __half*)zh, (const __half*)Wohi, (const __half*)Wolo, bout,
            out, nullptr, nullptr, OUTN, MM);
    }
}

// round 7
// speedup vs baseline: 5.6605x; 1.2288x over previous
#include <cuda_runtime.h>
#include <cuda_fp16.h>
#include <math.h>
#include <stdint.h>

// Problem constants
#define BB    8192
#define DIN   2048
#define MM    1600
#define CC    20
#define SS    80
#define OUTN  3000

// ---------------------------------------------------------------------------
// Scratch (static device globals)
// ---------------------------------------------------------------------------
__device__ float g_h0[(size_t)BB * MM];
__device__ float g_zT[(size_t)MM * BB];

__device__ __half g_x0h[(size_t)BB * DIN];
__device__ __half g_x1h[(size_t)BB * DIN];
__device__ __half g_W0hi[(size_t)MM * DIN];
__device__ __half g_W0lo[(size_t)MM * DIN];
__device__ __half g_W1hi[(size_t)MM * DIN];
__device__ __half g_W1lo[(size_t)MM * DIN];
__device__ __half g_Wouthi[(size_t)OUTN * MM];
__device__ __half g_Woutlo[(size_t)OUTN * MM];
__device__ __half g_Wbh[(size_t)CC * SS * SS * SS];
__device__ __half g_h1h[(size_t)BB * MM];
__device__ __half g_zh[(size_t)BB * MM];

// ---------------------------------------------------------------------------
// Low-level helpers
// ---------------------------------------------------------------------------
__device__ __forceinline__ uint32_t smem_u32(const void* p) {
    uint32_t a;
    asm("{ .reg .u64 t; cvta.to.shared.u64 t, %1; cvt.u32.u64 %0, t; }"
        : "=r"(a) : "l"(p));
    return a;
}

#define CP16(dst, src) \
    asm volatile("cp.async.cg.shared.global [%0], [%1], 16;" \
                 :: "r"(dst), "l"(src) : "memory")
#define CP16P(dst, src, nbytes) \
    asm volatile("cp.async.cg.shared.global [%0], [%1], 16, %2;" \
                 :: "r"(dst), "l"(src), "r"(nbytes) : "memory")
#define CP_COMMIT() asm volatile("cp.async.commit_group;" ::: "memory")
#define CP_WAIT0()  asm volatile("cp.async.wait_group 0;" ::: "memory")
#define CP_WAIT1()  asm volatile("cp.async.wait_group 1;" ::: "memory")

#define LDX4(r0, r1, r2, r3, addr) \
    asm volatile("ldmatrix.sync.aligned.m8n8.x4.shared.b16 {%0,%1,%2,%3}, [%4];" \
                 : "=r"(r0), "=r"(r1), "=r"(r2), "=r"(r3) : "r"(addr))

#define MMAH(d0, d1, d2, d3, a0, a1, a2, a3, b0, b1) \
    asm volatile("mma.sync.aligned.m16n8k16.row.col.f32.f16.f16.f32 " \
                 "{%0,%1,%2,%3}, {%4,%5,%6,%7}, {%8,%9}, {%0,%1,%2,%3};" \
                 : "+f"(d0), "+f"(d1), "+f"(d2), "+f"(d3) \
                 : "r"(a0), "r"(a1), "r"(a2), "r"(a3), "r"(b0), "r"(b1))

// ---------------------------------------------------------------------------
// fp32 -> fp16 convert (hi only) and hi/lo split
// ---------------------------------------------------------------------------
__global__ __launch_bounds__(256)
void cvt_fp16(const float* __restrict__ in, __half* __restrict__ out, int n4)
{
    int i = blockIdx.x * blockDim.x + threadIdx.x;
    if (i >= n4) return;
    float4 v = ((const float4*)in)[i];
    __half2 a = __halves2half2(__float2half(v.x), __float2half(v.y));
    __half2 b = __halves2half2(__float2half(v.z), __float2half(v.w));
    uint2 o;
    o.x = *(uint32_t*)&a; o.y = *(uint32_t*)&b;
    ((uint2*)out)[i] = o;
}

__global__ __launch_bounds__(256)
void split_fp16(const float* __restrict__ in, __half* __restrict__ hi,
                __half* __restrict__ lo, int n4)
{
    int i = blockIdx.x * blockDim.x + threadIdx.x;
    if (i >= n4) return;
    float4 v = ((const float4*)in)[i];
    __half h0 = __float2half(v.x), h1 = __float2half(v.y);
    __half h2 = __float2half(v.z), h3 = __float2half(v.w);
    __half l0 = __float2half(v.x - __half2float(h0));
    __half l1 = __float2half(v.y - __half2float(h1));
    __half l2 = __float2half(v.z - __half2float(h2));
    __half l3 = __float2half(v.w - __half2float(h3));
    __half2 hv0 = __halves2half2(h0, h1), hv1 = __halves2half2(h2, h3);
    __half2 lv0 = __halves2half2(l0, l1), lv1 = __halves2half2(l2, l3);
    uint2 hp, lp;
    hp.x = *(uint32_t*)&hv0; hp.y = *(uint32_t*)&hv1;
    lp.x = *(uint32_t*)&lv0; lp.y = *(uint32_t*)&lv1;
    ((uint2*)hi)[i] = hp;
    ((uint2*)lo)[i] = lp;
}

// ---------------------------------------------------------------------------
// GEMM core: fp16 2-product (A hi-only, B hi/lo), CTA 256x128xBK64, 8 warps,
// 3-stage cp.async. Shared by the merged input GEMM and the out GEMM.
// ---------------------------------------------------------------------------
#define BK 64
#define STAGE3 65536     // A 32K | Bhi 16K | Blo 16K
#define GEMM_SMEM3 (3 * STAGE3)

__device__ __forceinline__ void issue_stage3(
    uint32_t sbase, int stage,
    const __half* __restrict__ A, const __half* __restrict__ Bhi,
    const __half* __restrict__ Blo,
    int m0, int n0, int k0, int N, int K, int tid)
{
    uint32_t st = sbase + stage * STAGE3;
#pragma unroll
    for (int i = 0; i < 8; ++i) {
        int idx = tid + i * 256;
        int r = idx >> 3;
        int c = idx & 7;
        uint32_t dst = (uint32_t)(r * 128 + ((c ^ (r & 7)) << 4));
        size_t aoff = (size_t)(m0 + r) * K + k0 + c * 8;
        CP16(st + dst, (const char*)(A + aoff));
    }
#pragma unroll
    for (int i = 0; i < 4; ++i) {
        int idx = tid + i * 256;
        int r = idx >> 3;
        int c = idx & 7;
        uint32_t dst = (uint32_t)(r * 128 + ((c ^ (r & 7)) << 4));
        int n = n0 + r;
        int pred = (n < N) ? 16 : 0;
        int ncl = (n < N) ? n : (N - 1);
        size_t boff = (size_t)ncl * K + k0 + c * 8;
        CP16P(st + 32768 + dst, (const char*)(Bhi + boff), pred);
        CP16P(st + 49152 + dst, (const char*)(Blo + boff), pred);
    }
    CP_COMMIT();
}

// mainloop producing the 4x8x4 accumulator
__device__ __forceinline__ void gemm_mainloop(
    uint32_t sb, const __half* A, const __half* Bhi, const __half* Blo,
    int m0, int n0, int N, int K, int tid, float d[4][8][4])
{
    const int l  = tid & 31;
    const int wid = tid >> 5;
    const int wm = wid & 3;
    const int wn = wid >> 2;
    const int niter = K / BK;

    const uint32_t aRow  = (uint32_t)(wm * 64 + (l & 15));
    const uint32_t aXor  = aRow & 7;
    const uint32_t aHalf = (uint32_t)(l >> 4);
    const uint32_t bRow  = (uint32_t)(wn * 64 + (l & 7) + ((l >> 4) << 3));
    const uint32_t bXor  = bRow & 7;
    const uint32_t bHalf = (uint32_t)((l >> 3) & 1);

    issue_stage3(sb, 0, A, Bhi, Blo, m0, n0, 0, N, K, tid);
    if (niter > 1) issue_stage3(sb, 1, A, Bhi, Blo, m0, n0, BK, N, K, tid);

    for (int it = 0; it < niter; ++it) {
        if (it < niter - 1) CP_WAIT1(); else CP_WAIT0();
        __syncthreads();
        if (it + 2 < niter)
            issue_stage3(sb, (it + 2) % 3, A, Bhi, Blo, m0, n0, (it + 2) * BK, N, K, tid);

        const uint32_t st = sb + (it % 3) * STAGE3;
        const uint32_t sA   = st;
        const uint32_t sBhi = st + 32768;
        const uint32_t sBlo = st + 49152;

#pragma unroll
        for (int kk = 0; kk < 4; ++kk) {
            uint32_t ah[4][4], bh[4][4], bl[4][4];
            const uint32_t ach = (((2 * kk + aHalf) ^ aXor) << 4);
            const uint32_t bch = (((2 * kk + bHalf) ^ bXor) << 4);
#pragma unroll
            for (int mg = 0; mg < 4; ++mg) {
                uint32_t off = (aRow + mg * 16) * 128 + ach;
                LDX4(ah[mg][0], ah[mg][1], ah[mg][2], ah[mg][3], sA + off);
            }
#pragma unroll
            for (int ng = 0; ng < 4; ++ng) {
                uint32_t off = (bRow + ng * 16) * 128 + bch;
                LDX4(bh[ng][0], bh[ng][1], bh[ng][2], bh[ng][3], sBhi + off);
                LDX4(bl[ng][0], bl[ng][1], bl[ng][2], bl[ng][3], sBlo + off);
            }
#pragma unroll
            for (int mg = 0; mg < 4; ++mg) {
#pragma unroll
                for (int ng = 0; ng < 4; ++ng) {
#pragma unroll
                    for (int hh = 0; hh < 2; ++hh) {
                        float* dd = d[mg][ng * 2 + hh];
                        MMAH(dd[0], dd[1], dd[2], dd[3],
                             ah[mg][0], ah[mg][1], ah[mg][2], ah[mg][3],
                             bh[ng][2 * hh], bh[ng][2 * hh + 1]);
                        MMAH(dd[0], dd[1], dd[2], dd[3],
                             ah[mg][0], ah[mg][1], ah[mg][2], ah[mg][3],
                             bl[ng][2 * hh], bl[ng][2 * hh + 1]);
                    }
                }
            }
        }
    }
}

// Merged input GEMMs: blockIdx.z selects (x0,W0)->h0 fp32 or (x1,W1)->h1 fp16
__global__ __launch_bounds__(256, 1)
void tc_gemm_in(const __half* __restrict__ A0, const __half* __restrict__ A1,
                const __half* __restrict__ B0hi, const __half* __restrict__ B0lo,
                const __half* __restrict__ B1hi, const __half* __restrict__ B1lo,
                const float* __restrict__ bias0, const float* __restrict__ bias1,
                float* __restrict__ C0, __half* __restrict__ C1,
                int N, int K)
{
    extern __shared__ __align__(128) char smem[];
    const uint32_t sb = smem_u32(smem);
    const int tid = threadIdx.x;
    const int which = blockIdx.z;
    const int m0 = blockIdx.y * 256;
    const int n0 = blockIdx.x * 128;

    const __half* A   = which ? A1 : A0;
    const __half* Bhi = which ? B1hi : B0hi;
    const __half* Blo = which ? B1lo : B0lo;
    const float* bias = which ? bias1 : bias0;

    float d[4][8][4];
#pragma unroll
    for (int mg = 0; mg < 4; ++mg)
#pragma unroll
        for (int j = 0; j < 8; ++j)
#pragma unroll
            for (int e = 0; e < 4; ++e) d[mg][j][e] = 0.0f;

    gemm_mainloop(sb, A, Bhi, Blo, m0, n0, N, K, tid, d);

    const int l  = tid & 31;
    const int wm = (tid >> 5) & 3;
    const int wn = tid >> 7;
#pragma unroll
    for (int mg = 0; mg < 4; ++mg) {
#pragma unroll
        for (int j = 0; j < 8; ++j) {
            int m = m0 + wm * 64 + mg * 16 + (l >> 2);
            int n = n0 + wn * 64 + j * 8 + 2 * (l & 3);
            if (n < N) {
                float v0 = d[mg][j][0] + bias[n];
                float v1 = d[mg][j][1] + bias[n + 1];
                float v2 = d[mg][j][2] + bias[n];
                float v3 = d[mg][j][3] + bias[n + 1];
                if (!which) {
                    *(float2*)&C0[(size_t)m * N + n] = make_float2(v0, v1);
                    *(float2*)&C0[(size_t)(m + 8) * N + n] = make_float2(v2, v3);
                } else {
                    __half2 hp0 = __halves2half2(__float2half(v0), __float2half(v1));
                    __half2 hp1 = __halves2half2(__float2half(v2), __float2half(v3));
                    *(__half2*)&C1[(size_t)m * N + n] = hp0;
                    *(__half2*)&C1[(size_t)(m + 8) * N + n] = hp1;
                }
            }
        }
    }
}

// Out GEMM: fp32 output
__global__ __launch_bounds__(256, 1)
void tc_gemm_out(const __half* __restrict__ A,
                 const __half* __restrict__ Bhi, const __half* __restrict__ Blo,
                 const float* __restrict__ bias, float* __restrict__ C,
                 int N, int K)
{
    extern __shared__ __align__(128) char smem[];
    const uint32_t sb = smem_u32(smem);
    const int tid = threadIdx.x;
    const int m0 = blockIdx.y * 256;
    const int n0 = blockIdx.x * 128;

    float d[4][8][4];
#pragma unroll
    for (int mg = 0; mg < 4; ++mg)
#pragma unroll
        for (int j = 0; j < 8; ++j)
#pragma unroll
            for (int e = 0; e < 4; ++e) d[mg][j][e] = 0.0f;

    gemm_mainloop(sb, A, Bhi, Blo, m0, n0, N, K, tid, d);

    const int l  = tid & 31;
    const int wm = (tid >> 5) & 3;
    const int wn = tid >> 7;
#pragma unroll
    for (int mg = 0; mg < 4; ++mg) {
#pragma unroll
        for (int j = 0; j < 8; ++j) {
            int m = m0 + wm * 64 + mg * 16 + (l >> 2);
            int n = n0 + wn * 64 + j * 8 + 2 * (l & 3);
            if (n < N) {
                float v0 = d[mg][j][0] + bias[n];
                float v1 = d[mg][j][1] + bias[n + 1];
                float v2 = d[mg][j][2] + bias[n];
                float v3 = d[mg][j][3] + bias[n + 1];
                *(float2*)&C[(size_t)m * N + n] = make_float2(v0, v1);
                *(float2*)&C[(size_t)(m + 8) * N + n] = make_float2(v2, v3);
            }
        }
    }
}

// ---------------------------------------------------------------------------
// Fused bilinear (fp16 1-product):
// zT[c*80+q][b] = sum_s h0[b,s] * (Wb[c,q,s,:] . h1[b,:])
// A = Wb fp16 (CTA-resident), B = h1 fp16 (2-stage), h0 fp32 epilogue.
// ---------------------------------------------------------------------------
#define A_PITCH 176
#define B_PITCH 176
#define H0_PITCHF 84
#define SB_BASE 28160        // after A (160*176)
#define SB_STAGE 22528       // 128*176
#define SH0_BASE 73216       // SB_BASE + 2*SB_STAGE
#define SH0_STAGE 43008      // 128*84*4
#define BIL_SMEM 159232
#define BSPLIT 2

__global__ __launch_bounds__(256, 1)
void bilq_kernel(const __half* __restrict__ Wbh,
                 const __half* __restrict__ h1h,
                 const float* __restrict__ h0g,
                 float* __restrict__ zT)
{
    extern __shared__ __align__(128) char smem[];
    const uint32_t sb = smem_u32(smem);
    const int tid = threadIdx.x;
    const int l   = tid & 31;
    const int wid = tid >> 5;
    const int wm  = wid >> 2;
    const int wn  = wid & 3;
    const int c     = blockIdx.z;
    const int q0    = blockIdx.y * 2;
    const int bhalf = blockIdx.x;
    const int NB = 64 / BSPLIT;

    {
        const size_t wb_base = (size_t)c * (SS * SS * SS) + (size_t)q0 * (SS * SS);
#pragma unroll
        for (int i = 0; i < 7; ++i) {
            int idx = tid + i * 256;
            if (idx < 1600) {
                int row = idx / 10, ch = idx % 10;
                size_t src = wb_base + (size_t)(row / 80) * (SS * SS)
                           + (size_t)(row % 80) * SS + ch * 8;
                CP16(sb + row * A_PITCH + ch * 16, (const char*)(Wbh + src));
            }
        }
    }

    auto issue_bt = [&](int st, int b0) {
        uint32_t sB = sb + SB_BASE + st * SB_STAGE;
#pragma unroll
        for (int i = 0; i < 5; ++i) {
            int idx = tid + i * 256;
            int r = idx / 10, ch = idx % 10;
            size_t src = (size_t)(b0 + r) * MM + c * SS + ch * 8;
            CP16(sB + r * B_PITCH + ch * 16, (const char*)(h1h + src));
        }
        uint32_t sH = sb + SH0_BASE + st * SH0_STAGE;
#pragma unroll
        for (int i = 0; i < 10; ++i) {
            int idx = tid + i * 256;
            int r = idx / 20, ch = idx % 20;
            size_t src = (size_t)(b0 + r) * MM + c * SS + ch * 4;
            CP16(sH + r * (H0_PITCHF * 4) + ch * 16, (const char*)(h0g + src));
        }
        CP_COMMIT();
    };

    issue_bt(0, (bhalf * NB + 0) * 128);

    const uint32_t aRowOff  = (uint32_t)(wm * 80 + (l & 15)) * A_PITCH;
    const uint32_t aHalf    = (uint32_t)(l >> 4);
    const uint32_t bRowOff  = (uint32_t)((l & 7) + ((l >> 4) << 3)) * B_PITCH;
    const uint32_t bHalf    = (uint32_t)((l >> 3) & 1);

    for (int nIt = 0; nIt < NB; ++nIt) {
        const int b0 = (bhalf * NB + nIt) * 128;
        if (nIt + 1 < NB) {
            issue_bt((nIt + 1) & 1, (bhalf * NB + nIt + 1) * 128);
            CP_WAIT1();
        } else {
            CP_WAIT0();
        }
        __syncthreads();

        const int st = nIt & 1;
        const uint32_t sA = sb;
        const uint32_t sBhi = sb + SB_BASE + st * SB_STAGE;
        const float* h0s = (const float*)(smem + SH0_BASE + st * SH0_STAGE);

        float d[5][4][4];
#pragma unroll
        for (int mt = 0; mt < 5; ++mt)
#pragma unroll
            for (int nt = 0; nt < 4; ++nt)
#pragma unroll
                for (int e = 0; e < 4; ++e) d[mt][nt][e] = 0.0f;

#pragma unroll
        for (int kk = 0; kk < 5; ++kk) {
            uint32_t ah[5][4], bh[2][4];
            const uint32_t aco = ((2 * kk + aHalf) << 4);
            const uint32_t bco = ((2 * kk + bHalf) << 4);
#pragma unroll
            for (int mt = 0; mt < 5; ++mt) {
                uint32_t off = aRowOff + mt * 16 * A_PITCH + aco;
                LDX4(ah[mt][0], ah[mt][1], ah[mt][2], ah[mt][3], sA + off);
            }
#pragma unroll
            for (int pr = 0; pr < 2; ++pr) {
                uint32_t off = (uint32_t)(wn * 32 + pr * 16) * B_PITCH + bRowOff + bco;
                LDX4(bh[pr][0], bh[pr][1], bh[pr][2], bh[pr][3], sBhi + off);
            }
#pragma unroll
            for (int mt = 0; mt < 5; ++mt) {
#pragma unroll
                for (int pr = 0; pr < 2; ++pr) {
#pragma unroll
                    for (int hh = 0; hh < 2; ++hh) {
                        int nt = pr * 2 + hh;
                        float* dd = d[mt][nt];
                        MMAH(dd[0], dd[1], dd[2], dd[3],
                             ah[mt][0], ah[mt][1], ah[mt][2], ah[mt][3],
                             bh[pr][2 * hh], bh[pr][2 * hh + 1]);
                    }
                }
            }
        }

        float p8[8];
#pragma unroll
        for (int i = 0; i < 8; ++i) p8[i] = 0.0f;
#pragma unroll
        for (int mt = 0; mt < 5; ++mt) {
#pragma unroll
            for (int e = 0; e < 4; ++e) {
                int s = mt * 16 + (l >> 2) + 8 * (e >> 1);
#pragma unroll
                for (int nt = 0; nt < 4; ++nt) {
                    int bl_ = wn * 32 + nt * 8 + 2 * (l & 3) + (e & 1);
                    p8[nt * 2 + (e & 1)] += d[mt][nt][e] * h0s[bl_ * H0_PITCHF + s];
                }
            }
        }
#pragma unroll
        for (int pi = 0; pi < 8; ++pi) {
            float v = p8[pi];
            v += __shfl_xor_sync(0xffffffffu, v, 4);
            v += __shfl_xor_sync(0xffffffffu, v, 8);
            v += __shfl_xor_sync(0xffffffffu, v, 16);
            p8[pi] = v;
        }
        if (l < 4) {
            int feat = c * SS + q0 + wm;
            float* dst = zT + (size_t)feat * BB + b0 + wn * 32 + 2 * l;
#pragma unroll
            for (int nt = 0; nt < 4; ++nt)
                *(float2*)(dst + nt * 8) = make_float2(p8[nt * 2], p8[nt * 2 + 1]);
        }
        __syncthreads();
    }
}

// ---------------------------------------------------------------------------
// norm: z = signed_sqrt(zT + bb); per-chunk L2 normalize; emit fp16.
// ---------------------------------------------------------------------------
__global__ __launch_bounds__(256)
void norm_kernel(const float* __restrict__ zT, const float* __restrict__ bbv,
                 __half* __restrict__ zh)
{
    __shared__ float zs[80 * 129];
    __shared__ float bbs[80];
    __shared__ float scl[128];
    const int tid = threadIdx.x;
    const int c = blockIdx.y;
    const int b0 = blockIdx.x * 128;

    if (tid < 80) bbs[tid] = bbv[c * SS + tid];
#pragma unroll
    for (int i = 0; i < 40; ++i) {
        int idx = tid + i * 256;
        int q = idx >> 7, col = idx & 127;
        zs[q * 129 + col] = zT[(size_t)(c * SS + q) * BB + b0 + col];
    }
    __syncthreads();
    if (tid < 128) {
        float s = 0.0f;
#pragma unroll 4
        for (int q = 0; q < 80; ++q) s += fabsf(zs[q * 129 + tid] + bbs[q]);
        scl[tid] = 1.0f / fmaxf(sqrtf(s), 1e-12f);
    }
    __syncthreads();
#pragma unroll
    for (int i = 0; i < 40; ++i) {
        int idx = tid + i * 256;
        int b = idx / 80, q = idx % 80;
        float v = zs[q * 129 + b] + bbs[q];
        float sv = copysignf(sqrtf(fabsf(v)), v) * scl[b];
        zh[(size_t)(b0 + b) * MM + c * SS + q] = __float2half(sv);
    }
}

// ---------------------------------------------------------------------------
// launch
// ---------------------------------------------------------------------------
extern "C" void kernel_launch(void* const* d_in, const int* in_sizes, int n_in,
                              void* d_out, int out_size)
{
    (void)in_sizes; (void)n_in; (void)out_size;
    const float* x0   = (const float*)d_in[0];
    const float* x1   = (const float*)d_in[1];
    const float* W0   = (const float*)d_in[2];
    const float* b0   = (const float*)d_in[3];
    const float* W1   = (const float*)d_in[4];
    const float* b1   = (const float*)d_in[5];
    const float* Wb   = (const float*)d_in[6];
    const float* bb   = (const float*)d_in[7];
    const float* Wout = (const float*)d_in[8];
    const float* bout = (const float*)d_in[9];
    float* out = (float*)d_out;

    float *h0p, *zTp;
    cudaGetSymbolAddress((void**)&h0p, g_h0);
    cudaGetSymbolAddress((void**)&zTp, g_zT);
    void *x0h, *x1h, *W0hi, *W0lo, *W1hi, *W1lo, *Wohi, *Wolo, *Wbh, *h1h, *zh;
    cudaGetSymbolAddress(&x0h, g_x0h);  cudaGetSymbolAddress(&x1h, g_x1h);
    cudaGetSymbolAddress(&W0hi, g_W0hi); cudaGetSymbolAddress(&W0lo, g_W0lo);
    cudaGetSymbolAddress(&W1hi, g_W1hi); cudaGetSymbolAddress(&W1lo, g_W1lo);
    cudaGetSymbolAddress(&Wohi, g_Wouthi); cudaGetSymbolAddress(&Wolo, g_Woutlo);
    cudaGetSymbolAddress(&Wbh, g_Wbh);
    cudaGetSymbolAddress(&h1h, g_h1h);
    cudaGetSymbolAddress(&zh, g_zh);

    cudaFuncSetAttribute(tc_gemm_in, cudaFuncAttributeMaxDynamicSharedMemorySize, GEMM_SMEM3);
    cudaFuncSetAttribute(tc_gemm_out, cudaFuncAttributeMaxDynamicSharedMemorySize, GEMM_SMEM3);
    cudaFuncSetAttribute(bilq_kernel, cudaFuncAttributeMaxDynamicSharedMemorySize, BIL_SMEM);

    // launches 0-4: converts needed before the merged input GEMM
    {
        int n4 = BB * DIN / 4;
        cvt_fp16<<<(n4 + 255) / 256, 256>>>(x0, (__half*)x0h, n4);          // 0
        cvt_fp16<<<(n4 + 255) / 256, 256>>>(x1, (__half*)x1h, n4);          // 1
        n4 = CC * SS * SS * SS / 4;
        cvt_fp16<<<(n4 + 255) / 256, 256>>>(Wb, (__half*)Wbh, n4);          // 2
        n4 = MM * DIN / 4;
        split_fp16<<<(n4 + 255) / 256, 256>>>(W0, (__half*)W0hi, (__half*)W0lo, n4); // 3
        split_fp16<<<(n4 + 255) / 256, 256>>>(W1, (__half*)W1hi, (__half*)W1lo, n4); // 4
    }

    // launch 5 (ncu -s 5 -c 1 profiles this): merged input GEMMs
    {
        dim3 grid((MM + 127) / 128, BB / 256, 2);
        tc_gemm_in<<<grid, 256, GEMM_SMEM3>>>(
            (const __half*)x0h, (const __half*)x1h,
            (const __half*)W0hi, (const __half*)W0lo,
            (const __half*)W1hi, (const __half*)W1lo,
            b0, b1, h0p, (__half*)h1h, MM, DIN);
    }

    // Wout split
    {
        int n4 = OUTN * MM / 4;
        split_fp16<<<(n4 + 255) / 256, 256>>>(Wout, (__half*)Wohi, (__half*)Wolo, n4);
    }

    // fused bilinear -> zT
    {
        dim3 grid(BSPLIT, SS / 2, CC);
        bilq_kernel<<<grid, 256, BIL_SMEM>>>(
            (const __half*)Wbh, (const __half*)h1h, h0p, zTp);
    }

    // bias + signed sqrt + normalize -> fp16 z
    {
        dim3 grid(BB / 128, CC);
        norm_kernel<<<grid, 256>>>(zTp, bb, (__half*)zh);
    }

    // out = z @ Wout^T + bout
    {
        dim3 grid((OUTN + 127) / 128, BB / 256);
        tc_gemm_out<<<grid, 256, GEMM_SMEM3>>>(
            (const __half*)zh, (const __half*)Wohi, (const __half*)Wolo, bout,
            out, OUTN, MM);
    }
}

// round 8
// speedup vs baseline: 6.4820x; 1.1451x over previous
#include <cuda_runtime.h>
#include <cuda_fp16.h>
#include <math.h>
#include <stdint.h>

// Problem constants
#define BB    8192
#define DIN   2048
#define MM    1600
#define CC    20
#define SS    80
#define OUTN  3000

// ---------------------------------------------------------------------------
// Scratch (static device globals)
// ---------------------------------------------------------------------------
__device__ float g_h0[(size_t)BB * MM];
__device__ float g_zT[(size_t)MM * BB];

__device__ __half g_x0h[(size_t)BB * DIN];
__device__ __half g_x1h[(size_t)BB * DIN];
__device__ __half g_W0hi[(size_t)MM * DIN];
__device__ __half g_W0lo[(size_t)MM * DIN];
__device__ __half g_W1hi[(size_t)MM * DIN];
__device__ __half g_W1lo[(size_t)MM * DIN];
__device__ __half g_Wouth[(size_t)OUTN * MM];
__device__ __half g_Wbh[(size_t)CC * SS * SS * SS];
__device__ __half g_h1h[(size_t)BB * MM];
__device__ __half g_zh[(size_t)BB * MM];

// ---------------------------------------------------------------------------
// Low-level helpers
// ---------------------------------------------------------------------------
__device__ __forceinline__ uint32_t smem_u32(const void* p) {
    uint32_t a;
    asm("{ .reg .u64 t; cvta.to.shared.u64 t, %1; cvt.u32.u64 %0, t; }"
        : "=r"(a) : "l"(p));
    return a;
}

#define CP16(dst, src) \
    asm volatile("cp.async.cg.shared.global [%0], [%1], 16;" \
                 :: "r"(dst), "l"(src) : "memory")
#define CP16P(dst, src, nbytes) \
    asm volatile("cp.async.cg.shared.global [%0], [%1], 16, %2;" \
                 :: "r"(dst), "l"(src), "r"(nbytes) : "memory")
#define CP_COMMIT() asm volatile("cp.async.commit_group;" ::: "memory")
#define CP_WAIT0()  asm volatile("cp.async.wait_group 0;" ::: "memory")
#define CP_WAIT1()  asm volatile("cp.async.wait_group 1;" ::: "memory")

#define LDX4(r0, r1, r2, r3, addr) \
    asm volatile("ldmatrix.sync.aligned.m8n8.x4.shared.b16 {%0,%1,%2,%3}, [%4];" \
                 : "=r"(r0), "=r"(r1), "=r"(r2), "=r"(r3) : "r"(addr))

#define MMAH(d0, d1, d2, d3, a0, a1, a2, a3, b0, b1) \
    asm volatile("mma.sync.aligned.m16n8k16.row.col.f32.f16.f16.f32 " \
                 "{%0,%1,%2,%3}, {%4,%5,%6,%7}, {%8,%9}, {%0,%1,%2,%3};" \
                 : "+f"(d0), "+f"(d1), "+f"(d2), "+f"(d3) \
                 : "r"(a0), "r"(a1), "r"(a2), "r"(a3), "r"(b0), "r"(b1))

// ---------------------------------------------------------------------------
// fp32 -> fp16 convert (hi only) and hi/lo split
// ---------------------------------------------------------------------------
__global__ __launch_bounds__(256)
void cvt_fp16(const float* __restrict__ in, __half* __restrict__ out, int n4)
{
    int i = blockIdx.x * blockDim.x + threadIdx.x;
    if (i >= n4) return;
    float4 v = ((const float4*)in)[i];
    __half2 a = __halves2half2(__float2half(v.x), __float2half(v.y));
    __half2 b = __halves2half2(__float2half(v.z), __float2half(v.w));
    uint2 o;
    o.x = *(uint32_t*)&a; o.y = *(uint32_t*)&b;
    ((uint2*)out)[i] = o;
}

__global__ __launch_bounds__(256)
void split_fp16(const float* __restrict__ in, __half* __restrict__ hi,
                __half* __restrict__ lo, int n4)
{
    int i = blockIdx.x * blockDim.x + threadIdx.x;
    if (i >= n4) return;
    float4 v = ((const float4*)in)[i];
    __half h0 = __float2half(v.x), h1 = __float2half(v.y);
    __half h2 = __float2half(v.z), h3 = __float2half(v.w);
    __half l0 = __float2half(v.x - __half2float(h0));
    __half l1 = __float2half(v.y - __half2float(h1));
    __half l2 = __float2half(v.z - __half2float(h2));
    __half l3 = __float2half(v.w - __half2float(h3));
    __half2 hv0 = __halves2half2(h0, h1), hv1 = __halves2half2(h2, h3);
    __half2 lv0 = __halves2half2(l0, l1), lv1 = __halves2half2(l2, l3);
    uint2 hp, lp;
    hp.x = *(uint32_t*)&hv0; hp.y = *(uint32_t*)&hv1;
    lp.x = *(uint32_t*)&lv0; lp.y = *(uint32_t*)&lv1;
    ((uint2*)hi)[i] = hp;
    ((uint2*)lo)[i] = lp;
}

// ---------------------------------------------------------------------------
// Input GEMM (merged x0/W0->h0, x1/W1->h1): 2-product (A hi, B hi/lo),
// CTA 128x128xBK64, 2-stage cp.async, 2 CTAs/SM. Warp tile 64x32.
// ---------------------------------------------------------------------------
#define BK 64
#define STG_IN 49152            // A 16K | Bhi 16K | Blo 16K
#define SMEM_IN (2 * STG_IN)    // 96K

__device__ __forceinline__ void issue_in(
    uint32_t sbase, int stage,
    const __half* __restrict__ A, const __half* __restrict__ Bhi,
    const __half* __restrict__ Blo,
    int m0, int n0, int k0, int N, int K, int tid)
{
    uint32_t st = sbase + stage * STG_IN;
#pragma unroll
    for (int i = 0; i < 4; ++i) {
        int idx = tid + i * 256;
        int r = idx >> 3;
        int c = idx & 7;
        uint32_t dst = (uint32_t)(r * 128 + ((c ^ (r & 7)) << 4));
        CP16(st + dst, (const char*)(A + (size_t)(m0 + r) * K + k0 + c * 8));
        int n = n0 + r;
        int pred = (n < N) ? 16 : 0;
        int ncl = (n < N) ? n : (N - 1);
        size_t boff = (size_t)ncl * K + k0 + c * 8;
        CP16P(st + 16384 + dst, (const char*)(Bhi + boff), pred);
        CP16P(st + 32768 + dst, (const char*)(Blo + boff), pred);
    }
    CP_COMMIT();
}

__global__ __launch_bounds__(256, 2)
void tc_gemm_in(const __half* __restrict__ A0, const __half* __restrict__ A1,
                const __half* __restrict__ B0hi, const __half* __restrict__ B0lo,
                const __half* __restrict__ B1hi, const __half* __restrict__ B1lo,
                const float* __restrict__ bias0, const float* __restrict__ bias1,
                float* __restrict__ C0, __half* __restrict__ C1,
                int N, int K)
{
    extern __shared__ __align__(128) char smem[];
    const uint32_t sb = smem_u32(smem);
    const int tid = threadIdx.x;
    const int l   = tid & 31;
    const int wid = tid >> 5;
    const int wm  = wid & 1;     // 2 M-halves of 64
    const int wn  = wid >> 1;    // 4 N-quarters of 32
    const int which = blockIdx.z;
    const int m0 = blockIdx.y * 128;
    const int n0 = blockIdx.x * 128;
    const int niter = K / BK;

    const __half* A   = which ? A1 : A0;
    const __half* Bhi = which ? B1hi : B0hi;
    const __half* Blo = which ? B1lo : B0lo;
    const float* bias = which ? bias1 : bias0;

    const uint32_t aRow  = (uint32_t)(wm * 64 + (l & 15));
    const uint32_t aXor  = aRow & 7;
    const uint32_t aHalf = (uint32_t)(l >> 4);
    const uint32_t bRow  = (uint32_t)(wn * 32 + (l & 7) + ((l >> 4) << 3));
    const uint32_t bXor  = bRow & 7;
    const uint32_t bHalf = (uint32_t)((l >> 3) & 1);

    float d[4][4][4];
#pragma unroll
    for (int mg = 0; mg < 4; ++mg)
#pragma unroll
        for (int ng = 0; ng < 4; ++ng)
#pragma unroll
            for (int e = 0; e < 4; ++e) d[mg][ng][e] = 0.0f;

    issue_in(sb, 0, A, Bhi, Blo, m0, n0, 0, N, K, tid);
    if (niter > 1) issue_in(sb, 1, A, Bhi, Blo, m0, n0, BK, N, K, tid);

    for (int it = 0; it < niter; ++it) {
        if (it + 1 < niter) CP_WAIT1(); else CP_WAIT0();
        __syncthreads();

        const uint32_t st = sb + (it & 1) * STG_IN;
        const uint32_t sA   = st;
        const uint32_t sBhi = st + 16384;
        const uint32_t sBlo = st + 32768;

#pragma unroll
        for (int kk = 0; kk < 4; ++kk) {
            uint32_t ah[4][4], bh[2][4], bl[2][4];
            const uint32_t ach = (((2 * kk + aHalf) ^ aXor) << 4);
            const uint32_t bch = (((2 * kk + bHalf) ^ bXor) << 4);
#pragma unroll
            for (int mg = 0; mg < 4; ++mg) {
                uint32_t off = (aRow + mg * 16) * 128 + ach;
                LDX4(ah[mg][0], ah[mg][1], ah[mg][2], ah[mg][3], sA + off);
            }
#pragma unroll
            for (int bq = 0; bq < 2; ++bq) {
                uint32_t off = (bRow + bq * 16) * 128 + bch;
                LDX4(bh[bq][0], bh[bq][1], bh[bq][2], bh[bq][3], sBhi + off);
                LDX4(bl[bq][0], bl[bq][1], bl[bq][2], bl[bq][3], sBlo + off);
            }
#pragma unroll
            for (int mg = 0; mg < 4; ++mg) {
#pragma unroll
                for (int bq = 0; bq < 2; ++bq) {
#pragma unroll
                    for (int hh = 0; hh < 2; ++hh) {
                        float* dd = d[mg][bq * 2 + hh];
                        MMAH(dd[0], dd[1], dd[2], dd[3],
                             ah[mg][0], ah[mg][1], ah[mg][2], ah[mg][3],
                             bh[bq][2 * hh], bh[bq][2 * hh + 1]);
                        MMAH(dd[0], dd[1], dd[2], dd[3],
                             ah[mg][0], ah[mg][1], ah[mg][2], ah[mg][3],
                             bl[bq][2 * hh], bl[bq][2 * hh + 1]);
                    }
                }
            }
        }
        __syncthreads();
        if (it + 2 < niter)
            issue_in(sb, it & 1, A, Bhi, Blo, m0, n0, (it + 2) * BK, N, K, tid);
    }

#pragma unroll
    for (int mg = 0; mg < 4; ++mg) {
#pragma unroll
        for (int ng = 0; ng < 4; ++ng) {
            int m = m0 + wm * 64 + mg * 16 + (l >> 2);
            int n = n0 + wn * 32 + ng * 8 + 2 * (l & 3);
            if (n < N) {
                float v0 = d[mg][ng][0] + bias[n];
                float v1 = d[mg][ng][1] + bias[n + 1];
                float v2 = d[mg][ng][2] + bias[n];
                float v3 = d[mg][ng][3] + bias[n + 1];
                if (!which) {
                    *(float2*)&C0[(size_t)m * N + n] = make_float2(v0, v1);
                    *(float2*)&C0[(size_t)(m + 8) * N + n] = make_float2(v2, v3);
                } else {
                    *(__half2*)&C1[(size_t)m * N + n] =
                        __halves2half2(__float2half(v0), __float2half(v1));
                    *(__half2*)&C1[(size_t)(m + 8) * N + n] =
                        __halves2half2(__float2half(v2), __float2half(v3));
                }
            }
        }
    }
}

// ---------------------------------------------------------------------------
// Out GEMM: 1-product fp16, CTA 128x128xBK64, 3-stage, 2 CTAs/SM.
// ---------------------------------------------------------------------------
#define STG_OUT 32768           // A 16K | B 16K
#define SMEM_OUT (3 * STG_OUT)  // 96K

__device__ __forceinline__ void issue_out(
    uint32_t sbase, int stage,
    const __half* __restrict__ A, const __half* __restrict__ B,
    int m0, int n0, int k0, int N, int K, int tid)
{
    uint32_t st = sbase + stage * STG_OUT;
#pragma unroll
    for (int i = 0; i < 4; ++i) {
        int idx = tid + i * 256;
        int r = idx >> 3;
        int c = idx & 7;
        uint32_t dst = (uint32_t)(r * 128 + ((c ^ (r & 7)) << 4));
        CP16(st + dst, (const char*)(A + (size_t)(m0 + r) * K + k0 + c * 8));
        int n = n0 + r;
        int pred = (n < N) ? 16 : 0;
        int ncl = (n < N) ? n : (N - 1);
        CP16P(st + 16384 + dst, (const char*)(B + (size_t)ncl * K + k0 + c * 8), pred);
    }
    CP_COMMIT();
}

__global__ __launch_bounds__(256, 2)
void tc_gemm_out(const __half* __restrict__ A, const __half* __restrict__ B,
                 const float* __restrict__ bias, float* __restrict__ C,
                 int N, int K)
{
    extern __shared__ __align__(128) char smem[];
    const uint32_t sb = smem_u32(smem);
    const int tid = threadIdx.x;
    const int l   = tid & 31;
    const int wid = tid >> 5;
    const int wm  = wid & 1;
    const int wn  = wid >> 1;
    const int m0 = blockIdx.y * 128;
    const int n0 = blockIdx.x * 128;
    const int niter = K / BK;

    const uint32_t aRow  = (uint32_t)(wm * 64 + (l & 15));
    const uint32_t aXor  = aRow & 7;
    const uint32_t aHalf = (uint32_t)(l >> 4);
    const uint32_t bRow  = (uint32_t)(wn * 32 + (l & 7) + ((l >> 4) << 3));
    const uint32_t bXor  = bRow & 7;
    const uint32_t bHalf = (uint32_t)((l >> 3) & 1);

    float d[4][4][4];
#pragma unroll
    for (int mg = 0; mg < 4; ++mg)
#pragma unroll
        for (int ng = 0; ng < 4; ++ng)
#pragma unroll
            for (int e = 0; e < 4; ++e) d[mg][ng][e] = 0.0f;

    issue_out(sb, 0, A, B, m0, n0, 0, N, K, tid);
    if (niter > 1) issue_out(sb, 1, A, B, m0, n0, BK, N, K, tid);

    for (int it = 0; it < niter; ++it) {
        if (it + 1 < niter) CP_WAIT1(); else CP_WAIT0();
        __syncthreads();
        if (it + 2 < niter)
            issue_out(sb, (it + 2) % 3, A, B, m0, n0, (it + 2) * BK, N, K, tid);

        const uint32_t st = sb + (it % 3) * STG_OUT;
        const uint32_t sA = st;
        const uint32_t sB = st + 16384;

#pragma unroll
        for (int kk = 0; kk < 4; ++kk) {
            uint32_t ah[4][4], bh[2][4];
            const uint32_t ach = (((2 * kk + aHalf) ^ aXor) << 4);
            const uint32_t bch = (((2 * kk + bHalf) ^ bXor) << 4);
#pragma unroll
            for (int mg = 0; mg < 4; ++mg) {
                uint32_t off = (aRow + mg * 16) * 128 + ach;
                LDX4(ah[mg][0], ah[mg][1], ah[mg][2], ah[mg][3], sA + off);
            }
#pragma unroll
            for (int bq = 0; bq < 2; ++bq) {
                uint32_t off = (bRow + bq * 16) * 128 + bch;
                LDX4(bh[bq][0], bh[bq][1], bh[bq][2], bh[bq][3], sB + off);
            }
#pragma unroll
            for (int mg = 0; mg < 4; ++mg) {
#pragma unroll
                for (int bq = 0; bq < 2; ++bq) {
#pragma unroll
                    for (int hh = 0; hh < 2; ++hh) {
                        float* dd = d[mg][bq * 2 + hh];
                        MMAH(dd[0], dd[1], dd[2], dd[3],
                             ah[mg][0], ah[mg][1], ah[mg][2], ah[mg][3],
                             bh[bq][2 * hh], bh[bq][2 * hh + 1]);
                    }
                }
            }
        }
    }

#pragma unroll
    for (int mg = 0; mg < 4; ++mg) {
#pragma unroll
        for (int ng = 0; ng < 4; ++ng) {
            int m = m0 + wm * 64 + mg * 16 + (l >> 2);
            int n = n0 + wn * 32 + ng * 8 + 2 * (l & 3);
            if (n < N) {
                float v0 = d[mg][ng][0] + bias[n];
                float v1 = d[mg][ng][1] + bias[n + 1];
                float v2 = d[mg][ng][2] + bias[n];
                float v3 = d[mg][ng][3] + bias[n + 1];
                *(float2*)&C[(size_t)m * N + n] = make_float2(v0, v1);
                *(float2*)&C[(size_t)(m + 8) * N + n] = make_float2(v2, v3);
            }
        }
    }
}

// ---------------------------------------------------------------------------
// Fused bilinear (fp16 1-product):
// zT[c*80+q][b] = sum_s h0[b,s] * (Wb[c,q,s,:] . h1[b,:])
// ---------------------------------------------------------------------------
#define A_PITCH 176
#define B_PITCH 176
#define H0_PITCHF 84
#define SB_BASE 28160
#define SB_STAGE 22528
#define SH0_BASE 73216
#define SH0_STAGE 43008
#define BIL_SMEM 159232
#define BSPLIT 2

__global__ __launch_bounds__(256, 1)
void bilq_kernel(const __half* __restrict__ Wbh,
                 const __half* __restrict__ h1h,
                 const float* __restrict__ h0g,
                 float* __restrict__ zT)
{
    extern __shared__ __align__(128) char smem[];
    const uint32_t sb = smem_u32(smem);
    const int tid = threadIdx.x;
    const int l   = tid & 31;
    const int wid = tid >> 5;
    const int wm  = wid >> 2;
    const int wn  = wid & 3;
    const int c     = blockIdx.z;
    const int q0    = blockIdx.y * 2;
    const int bhalf = blockIdx.x;
    const int NB = 64 / BSPLIT;

    {
        const size_t wb_base = (size_t)c * (SS * SS * SS) + (size_t)q0 * (SS * SS);
#pragma unroll
        for (int i = 0; i < 7; ++i) {
            int idx = tid + i * 256;
            if (idx < 1600) {
                int row = idx / 10, ch = idx % 10;
                size_t src = wb_base + (size_t)(row / 80) * (SS * SS)
                           + (size_t)(row % 80) * SS + ch * 8;
                CP16(sb + row * A_PITCH + ch * 16, (const char*)(Wbh + src));
            }
        }
    }

    auto issue_bt = [&](int st, int b0) {
        uint32_t sB = sb + SB_BASE + st * SB_STAGE;
#pragma unroll
        for (int i = 0; i < 5; ++i) {
            int idx = tid + i * 256;
            int r = idx / 10, ch = idx % 10;
            size_t src = (size_t)(b0 + r) * MM + c * SS + ch * 8;
            CP16(sB + r * B_PITCH + ch * 16, (const char*)(h1h + src));
        }
        uint32_t sH = sb + SH0_BASE + st * SH0_STAGE;
#pragma unroll
        for (int i = 0; i < 10; ++i) {
            int idx = tid + i * 256;
            int r = idx / 20, ch = idx % 20;
            size_t src = (size_t)(b0 + r) * MM + c * SS + ch * 4;
            CP16(sH + r * (H0_PITCHF * 4) + ch * 16, (const char*)(h0g + src));
        }
        CP_COMMIT();
    };

    issue_bt(0, (bhalf * NB + 0) * 128);

    const uint32_t aRowOff  = (uint32_t)(wm * 80 + (l & 15)) * A_PITCH;
    const uint32_t aHalf    = (uint32_t)(l >> 4);
    const uint32_t bRowOff  = (uint32_t)((l & 7) + ((l >> 4) << 3)) * B_PITCH;
    const uint32_t bHalf    = (uint32_t)((l >> 3) & 1);

    for (int nIt = 0; nIt < NB; ++nIt) {
        const int b0 = (bhalf * NB + nIt) * 128;
        if (nIt + 1 < NB) {
            issue_bt((nIt + 1) & 1, (bhalf * NB + nIt + 1) * 128);
            CP_WAIT1();
        } else {
            CP_WAIT0();
        }
        __syncthreads();

        const int st = nIt & 1;
        const uint32_t sA = sb;
        const uint32_t sBhi = sb + SB_BASE + st * SB_STAGE;
        const float* h0s = (const float*)(smem + SH0_BASE + st * SH0_STAGE);

        float d[5][4][4];
#pragma unroll
        for (int mt = 0; mt < 5; ++mt)
#pragma unroll
            for (int nt = 0; nt < 4; ++nt)
#pragma unroll
                for (int e = 0; e < 4; ++e) d[mt][nt][e] = 0.0f;

#pragma unroll
        for (int kk = 0; kk < 5; ++kk) {
            uint32_t ah[5][4], bh[2][4];
            const uint32_t aco = ((2 * kk + aHalf) << 4);
            const uint32_t bco = ((2 * kk + bHalf) << 4);
#pragma unroll
            for (int mt = 0; mt < 5; ++mt) {
                uint32_t off = aRowOff + mt * 16 * A_PITCH + aco;
                LDX4(ah[mt][0], ah[mt][1], ah[mt][2], ah[mt][3], sA + off);
            }
#pragma unroll
            for (int pr = 0; pr < 2; ++pr) {
                uint32_t off = (uint32_t)(wn * 32 + pr * 16) * B_PITCH + bRowOff + bco;
                LDX4(bh[pr][0], bh[pr][1], bh[pr][2], bh[pr][3], sBhi + off);
            }
#pragma unroll
            for (int mt = 0; mt < 5; ++mt) {
#pragma unroll
                for (int pr = 0; pr < 2; ++pr) {
#pragma unroll
                    for (int hh = 0; hh < 2; ++hh) {
                        int nt = pr * 2 + hh;
                        float* dd = d[mt][nt];
                        MMAH(dd[0], dd[1], dd[2], dd[3],
                             ah[mt][0], ah[mt][1], ah[mt][2], ah[mt][3],
                             bh[pr][2 * hh], bh[pr][2 * hh + 1]);
                    }
                }
            }
        }

        float p8[8];
#pragma unroll
        for (int i = 0; i < 8; ++i) p8[i] = 0.0f;
#pragma unroll
        for (int mt = 0; mt < 5; ++mt) {
#pragma unroll
            for (int e = 0; e < 4; ++e) {
                int s = mt * 16 + (l >> 2) + 8 * (e >> 1);
#pragma unroll
                for (int nt = 0; nt < 4; ++nt) {
                    int bl_ = wn * 32 + nt * 8 + 2 * (l & 3) + (e & 1);
                    p8[nt * 2 + (e & 1)] += d[mt][nt][e] * h0s[bl_ * H0_PITCHF + s];
                }
            }
        }
#pragma unroll
        for (int pi = 0; pi < 8; ++pi) {
            float v = p8[pi];
            v += __shfl_xor_sync(0xffffffffu, v, 4);
            v += __shfl_xor_sync(0xffffffffu, v, 8);
            v += __shfl_xor_sync(0xffffffffu, v, 16);
            p8[pi] = v;
        }
        if (l < 4) {
            int feat = c * SS + q0 + wm;
            float* dst = zT + (size_t)feat * BB + b0 + wn * 32 + 2 * l;
#pragma unroll
            for (int nt = 0; nt < 4; ++nt)
                *(float2*)(dst + nt * 8) = make_float2(p8[nt * 2], p8[nt * 2 + 1]);
        }
        __syncthreads();
    }
}

// ---------------------------------------------------------------------------
// norm: z = signed_sqrt(zT + bb); per-chunk L2 normalize; emit fp16.
// ---------------------------------------------------------------------------
__global__ __launch_bounds__(256)
void norm_kernel(const float* __restrict__ zT, const float* __restrict__ bbv,
                 __half* __restrict__ zh)
{
    __shared__ float zs[80 * 129];
    __shared__ float bbs[80];
    __shared__ float scl[128];
    const int tid = threadIdx.x;
    const int c = blockIdx.y;
    const int b0 = blockIdx.x * 128;

    if (tid < 80) bbs[tid] = bbv[c * SS + tid];
#pragma unroll
    for (int i = 0; i < 40; ++i) {
        int idx = tid + i * 256;
        int q = idx >> 7, col = idx & 127;
        zs[q * 129 + col] = zT[(size_t)(c * SS + q) * BB + b0 + col];
    }
    __syncthreads();
    if (tid < 128) {
        float s = 0.0f;
#pragma unroll 4
        for (int q = 0; q < 80; ++q) s += fabsf(zs[q * 129 + tid] + bbs[q]);
        scl[tid] = 1.0f / fmaxf(sqrtf(s), 1e-12f);
    }
    __syncthreads();
#pragma unroll
    for (int i = 0; i < 40; ++i) {
        int idx = tid + i * 256;
        int b = idx / 80, q = idx % 80;
        float v = zs[q * 129 + b] + bbs[q];
        float sv = copysignf(sqrtf(fabsf(v)), v) * scl[b];
        zh[(size_t)(b0 + b) * MM + c * SS + q] = __float2half(sv);
    }
}

// ---------------------------------------------------------------------------
// launch
// ---------------------------------------------------------------------------
extern "C" void kernel_launch(void* const* d_in, const int* in_sizes, int n_in,
                              void* d_out, int out_size)
{
    (void)in_sizes; (void)n_in; (void)out_size;
    const float* x0   = (const float*)d_in[0];
    const float* x1   = (const float*)d_in[1];
    const float* W0   = (const float*)d_in[2];
    const float* b0   = (const float*)d_in[3];
    const float* W1   = (const float*)d_in[4];
    const float* b1   = (const float*)d_in[5];
    const float* Wb   = (const float*)d_in[6];
    const float* bb   = (const float*)d_in[7];
    const float* Wout = (const float*)d_in[8];
    const float* bout = (const float*)d_in[9];
    float* out = (float*)d_out;

    float *h0p, *zTp;
    cudaGetSymbolAddress((void**)&h0p, g_h0);
    cudaGetSymbolAddress((void**)&zTp, g_zT);
    void *x0h, *x1h, *W0hi, *W0lo, *W1hi, *W1lo, *Woh, *Wbh, *h1h, *zh;
    cudaGetSymbolAddress(&x0h, g_x0h);  cudaGetSymbolAddress(&x1h, g_x1h);
    cudaGetSymbolAddress(&W0hi, g_W0hi); cudaGetSymbolAddress(&W0lo, g_W0lo);
    cudaGetSymbolAddress(&W1hi, g_W1hi); cudaGetSymbolAddress(&W1lo, g_W1lo);
    cudaGetSymbolAddress(&Woh, g_Wouth);
    cudaGetSymbolAddress(&Wbh, g_Wbh);
    cudaGetSymbolAddress(&h1h, g_h1h);
    cudaGetSymbolAddress(&zh, g_zh);

    cudaFuncSetAttribute(tc_gemm_in, cudaFuncAttributeMaxDynamicSharedMemorySize, SMEM_IN);
    cudaFuncSetAttribute(tc_gemm_out, cudaFuncAttributeMaxDynamicSharedMemorySize, SMEM_OUT);
    cudaFuncSetAttribute(bilq_kernel, cudaFuncAttributeMaxDynamicSharedMemorySize, BIL_SMEM);

    // converts
    {
        int n4 = BB * DIN / 4;
        cvt_fp16<<<(n4 + 255) / 256, 256>>>(x0, (__half*)x0h, n4);
        cvt_fp16<<<(n4 + 255) / 256, 256>>>(x1, (__half*)x1h, n4);
        n4 = CC * SS * SS * SS / 4;
        cvt_fp16<<<(n4 + 255) / 256, 256>>>(Wb, (__half*)Wbh, n4);
        n4 = OUTN * MM / 4;
        cvt_fp16<<<(n4 + 255) / 256, 256>>>(Wout, (__half*)Woh, n4);
        n4 = MM * DIN / 4;
        split_fp16<<<(n4 + 255) / 256, 256>>>(W0, (__half*)W0hi, (__half*)W0lo, n4);
        split_fp16<<<(n4 + 255) / 256, 256>>>(W1, (__half*)W1hi, (__half*)W1lo, n4);
    }

    // merged input GEMMs
    {
        dim3 grid((MM + 127) / 128, BB / 128, 2);
        tc_gemm_in<<<grid, 256, SMEM_IN>>>(
            (const __half*)x0h, (const __half*)x1h,
            (const __half*)W0hi, (const __half*)W0lo,
            (const __half*)W1hi, (const __half*)W1lo,
            b0, b1, h0p, (__half*)h1h, MM, DIN);
    }

    // fused bilinear -> zT
    {
        dim3 grid(BSPLIT, SS / 2, CC);
        bilq_kernel<<<grid, 256, BIL_SMEM>>>(
            (const __half*)Wbh, (const __half*)h1h, h0p, zTp);
    }

    // bias + signed sqrt + normalize -> fp16 z
    {
        dim3 grid(BB / 128, CC);
        norm_kernel<<<grid, 256>>>(zTp, bb, (__half*)zh);
    }

    // out = z @ Wout^T + bout (1-product)
    {
        dim3 grid((OUTN + 127) / 128, BB / 128);
        tc_gemm_out<<<grid, 256, SMEM_OUT>>>(
            (const __half*)zh, (const __half*)Woh, bout, out, OUTN, MM);
    }
}

// round 9
// speedup vs baseline: 7.6957x; 1.1872x over previous
#include <cuda_runtime.h>
#include <cuda_fp16.h>
#include <math.h>
#include <stdint.h>

// Problem constants
#define BB    8192
#define DIN   2048
#define MM    1600
#define CC    20
#define SS    80
#define OUTN  3000

// ---------------------------------------------------------------------------
// Scratch (static device globals)
// ---------------------------------------------------------------------------
__device__ float g_h0[(size_t)BB * MM];
__device__ float g_zT[(size_t)MM * BB];

__device__ __half g_x0h[(size_t)BB * DIN];
__device__ __half g_x1h[(size_t)BB * DIN];
__device__ __half g_W0h[(size_t)MM * DIN];
__device__ __half g_W1h[(size_t)MM * DIN];
__device__ __half g_Wouth[(size_t)OUTN * MM];
__device__ __half g_Wbh[(size_t)CC * SS * SS * SS];
__device__ __half g_h1h[(size_t)BB * MM];
__device__ __half g_zh[(size_t)BB * MM];

// ---------------------------------------------------------------------------
// Low-level helpers
// ---------------------------------------------------------------------------
__device__ __forceinline__ uint32_t smem_u32(const void* p) {
    uint32_t a;
    asm("{ .reg .u64 t; cvta.to.shared.u64 t, %1; cvt.u32.u64 %0, t; }"
        : "=r"(a) : "l"(p));
    return a;
}

#define CP16(dst, src) \
    asm volatile("cp.async.cg.shared.global [%0], [%1], 16;" \
                 :: "r"(dst), "l"(src) : "memory")
#define CP16P(dst, src, nbytes) \
    asm volatile("cp.async.cg.shared.global [%0], [%1], 16, %2;" \
                 :: "r"(dst), "l"(src), "r"(nbytes) : "memory")
#define CP_COMMIT() asm volatile("cp.async.commit_group;" ::: "memory")
#define CP_WAIT0()  asm volatile("cp.async.wait_group 0;" ::: "memory")
#define CP_WAIT1()  asm volatile("cp.async.wait_group 1;" ::: "memory")

#define LDX4(r0, r1, r2, r3, addr) \
    asm volatile("ldmatrix.sync.aligned.m8n8.x4.shared.b16 {%0,%1,%2,%3}, [%4];" \
                 : "=r"(r0), "=r"(r1), "=r"(r2), "=r"(r3) : "r"(addr))

#define MMAH(d0, d1, d2, d3, a0, a1, a2, a3, b0, b1) \
    asm volatile("mma.sync.aligned.m16n8k16.row.col.f32.f16.f16.f32 " \
                 "{%0,%1,%2,%3}, {%4,%5,%6,%7}, {%8,%9}, {%0,%1,%2,%3};" \
                 : "+f"(d0), "+f"(d1), "+f"(d2), "+f"(d3) \
                 : "r"(a0), "r"(a1), "r"(a2), "r"(a3), "r"(b0), "r"(b1))

// ---------------------------------------------------------------------------
// fp32 -> fp16 converts (single and paired)
// ---------------------------------------------------------------------------
__global__ __launch_bounds__(256)
void cvt_fp16(const float* __restrict__ in, __half* __restrict__ out, int n4)
{
    int i = blockIdx.x * blockDim.x + threadIdx.x;
    if (i >= n4) return;
    float4 v = ((const float4*)in)[i];
    __half2 a = __halves2half2(__float2half(v.x), __float2half(v.y));
    __half2 b = __halves2half2(__float2half(v.z), __float2half(v.w));
    uint2 o;
    o.x = *(uint32_t*)&a; o.y = *(uint32_t*)&b;
    ((uint2*)out)[i] = o;
}

__global__ __launch_bounds__(256)
void cvt2_fp16(const float* __restrict__ in0, __half* __restrict__ out0,
               const float* __restrict__ in1, __half* __restrict__ out1, int n4)
{
    int i = blockIdx.x * blockDim.x + threadIdx.x;
    if (i >= n4) return;
    const float* in = blockIdx.y ? in1 : in0;
    __half* out = blockIdx.y ? out1 : out0;
    float4 v = ((const float4*)in)[i];
    __half2 a = __halves2half2(__float2half(v.x), __float2half(v.y));
    __half2 b = __halves2half2(__float2half(v.z), __float2half(v.w));
    uint2 o;
    o.x = *(uint32_t*)&a; o.y = *(uint32_t*)&b;
    ((uint2*)out)[i] = o;
}

// ---------------------------------------------------------------------------
// 1-product fp16 NT GEMM core: CTA 128x128xBK64, 3-stage, 2 CTAs/SM,
// warp tile 64x32, single sync per K-iter.
// ---------------------------------------------------------------------------
#define BK 64
#define STG1 32768            // A 16K | B 16K
#define SMEM1 (3 * STG1)      // 96K

__device__ __forceinline__ void issue1(
    uint32_t sbase, int stage,
    const __half* __restrict__ A, const __half* __restrict__ B,
    int m0, int n0, int k0, int N, int K, int tid)
{
    uint32_t st = sbase + stage * STG1;
#pragma unroll
    for (int i = 0; i < 4; ++i) {
        int idx = tid + i * 256;
        int r = idx >> 3;
        int c = idx & 7;
        uint32_t dst = (uint32_t)(r * 128 + ((c ^ (r & 7)) << 4));
        CP16(st + dst, (const char*)(A + (size_t)(m0 + r) * K + k0 + c * 8));
        int n = n0 + r;
        int pred = (n < N) ? 16 : 0;
        int ncl = (n < N) ? n : (N - 1);
        CP16P(st + 16384 + dst, (const char*)(B + (size_t)ncl * K + k0 + c * 8), pred);
    }
    CP_COMMIT();
}

__device__ __forceinline__ void gemm1_mainloop(
    uint32_t sb, const __half* A, const __half* B,
    int m0, int n0, int N, int K, int tid, float d[4][4][4])
{
    const int l   = tid & 31;
    const int wid = tid >> 5;
    const int wm  = wid & 1;
    const int wn  = wid >> 1;
    const int niter = K / BK;

    const uint32_t aRow  = (uint32_t)(wm * 64 + (l & 15));
    const uint32_t aXor  = aRow & 7;
    const uint32_t aHalf = (uint32_t)(l >> 4);
    const uint32_t bRow  = (uint32_t)(wn * 32 + (l & 7) + ((l >> 4) << 3));
    const uint32_t bXor  = bRow & 7;
    const uint32_t bHalf = (uint32_t)((l >> 3) & 1);

    issue1(sb, 0, A, B, m0, n0, 0, N, K, tid);
    if (niter > 1) issue1(sb, 1, A, B, m0, n0, BK, N, K, tid);

    for (int it = 0; it < niter; ++it) {
        if (it + 1 < niter) CP_WAIT1(); else CP_WAIT0();
        __syncthreads();
        if (it + 2 < niter)
            issue1(sb, (it + 2) % 3, A, B, m0, n0, (it + 2) * BK, N, K, tid);

        const uint32_t st = sb + (it % 3) * STG1;
        const uint32_t sA = st;
        const uint32_t sB = st + 16384;

#pragma unroll
        for (int kk = 0; kk < 4; ++kk) {
            uint32_t ah[4][4], bh[2][4];
            const uint32_t ach = (((2 * kk + aHalf) ^ aXor) << 4);
            const uint32_t bch = (((2 * kk + bHalf) ^ bXor) << 4);
#pragma unroll
            for (int mg = 0; mg < 4; ++mg) {
                uint32_t off = (aRow + mg * 16) * 128 + ach;
                LDX4(ah[mg][0], ah[mg][1], ah[mg][2], ah[mg][3], sA + off);
            }
#pragma unroll
            for (int bq = 0; bq < 2; ++bq) {
                uint32_t off = (bRow + bq * 16) * 128 + bch;
                LDX4(bh[bq][0], bh[bq][1], bh[bq][2], bh[bq][3], sB + off);
            }
#pragma unroll
            for (int mg = 0; mg < 4; ++mg) {
#pragma unroll
                for (int bq = 0; bq < 2; ++bq) {
#pragma unroll
                    for (int hh = 0; hh < 2; ++hh) {
                        float* dd = d[mg][bq * 2 + hh];
                        MMAH(dd[0], dd[1], dd[2], dd[3],
                             ah[mg][0], ah[mg][1], ah[mg][2], ah[mg][3],
                             bh[bq][2 * hh], bh[bq][2 * hh + 1]);
                    }
                }
            }
        }
    }
}

// Merged input GEMMs: blockIdx.z=0 -> h0 fp32; z=1 -> h1 fp16.
__global__ __launch_bounds__(256, 2)
void tc_gemm_in(const __half* __restrict__ A0, const __half* __restrict__ A1,
                const __half* __restrict__ B0, const __half* __restrict__ B1,
                const float* __restrict__ bias0, const float* __restrict__ bias1,
                float* __restrict__ C0, __half* __restrict__ C1,
                int N, int K)
{
    extern __shared__ __align__(128) char smem[];
    const uint32_t sb = smem_u32(smem);
    const int tid = threadIdx.x;
    const int which = blockIdx.z;
    const int m0 = blockIdx.y * 128;
    const int n0 = blockIdx.x * 128;

    const __half* A   = which ? A1 : A0;
    const __half* B   = which ? B1 : B0;
    const float* bias = which ? bias1 : bias0;

    float d[4][4][4];
#pragma unroll
    for (int mg = 0; mg < 4; ++mg)
#pragma unroll
        for (int ng = 0; ng < 4; ++ng)
#pragma unroll
            for (int e = 0; e < 4; ++e) d[mg][ng][e] = 0.0f;

    gemm1_mainloop(sb, A, B, m0, n0, N, K, tid, d);

    const int l  = tid & 31;
    const int wm = (tid >> 5) & 1;
    const int wn = tid >> 6;
#pragma unroll
    for (int mg = 0; mg < 4; ++mg) {
#pragma unroll
        for (int ng = 0; ng < 4; ++ng) {
            int m = m0 + wm * 64 + mg * 16 + (l >> 2);
            int n = n0 + wn * 32 + ng * 8 + 2 * (l & 3);
            if (n < N) {
                float v0 = d[mg][ng][0] + bias[n];
                float v1 = d[mg][ng][1] + bias[n + 1];
                float v2 = d[mg][ng][2] + bias[n];
                float v3 = d[mg][ng][3] + bias[n + 1];
                if (!which) {
                    *(float2*)&C0[(size_t)m * N + n] = make_float2(v0, v1);
                    *(float2*)&C0[(size_t)(m + 8) * N + n] = make_float2(v2, v3);
                } else {
                    *(__half2*)&C1[(size_t)m * N + n] =
                        __halves2half2(__float2half(v0), __float2half(v1));
                    *(__half2*)&C1[(size_t)(m + 8) * N + n] =
                        __halves2half2(__float2half(v2), __float2half(v3));
                }
            }
        }
    }
}

// Out GEMM: fp32 output
__global__ __launch_bounds__(256, 2)
void tc_gemm_out(const __half* __restrict__ A, const __half* __restrict__ B,
                 const float* __restrict__ bias, float* __restrict__ C,
                 int N, int K)
{
    extern __shared__ __align__(128) char smem[];
    const uint32_t sb = smem_u32(smem);
    const int tid = threadIdx.x;
    const int m0 = blockIdx.y * 128;
    const int n0 = blockIdx.x * 128;

    float d[4][4][4];
#pragma unroll
    for (int mg = 0; mg < 4; ++mg)
#pragma unroll
        for (int ng = 0; ng < 4; ++ng)
#pragma unroll
            for (int e = 0; e < 4; ++e) d[mg][ng][e] = 0.0f;

    gemm1_mainloop(sb, A, B, m0, n0, N, K, tid, d);

    const int l  = tid & 31;
    const int wm = (tid >> 5) & 1;
    const int wn = tid >> 6;
#pragma unroll
    for (int mg = 0; mg < 4; ++mg) {
#pragma unroll
        for (int ng = 0; ng < 4; ++ng) {
            int m = m0 + wm * 64 + mg * 16 + (l >> 2);
            int n = n0 + wn * 32 + ng * 8 + 2 * (l & 3);
            if (n < N) {
                float v0 = d[mg][ng][0] + bias[n];
                float v1 = d[mg][ng][1] + bias[n + 1];
                float v2 = d[mg][ng][2] + bias[n];
                float v3 = d[mg][ng][3] + bias[n + 1];
                *(float2*)&C[(size_t)m * N + n] = make_float2(v0, v1);
                *(float2*)&C[(size_t)(m + 8) * N + n] = make_float2(v2, v3);
            }
        }
    }
}

// ---------------------------------------------------------------------------
// Fused bilinear (fp16 1-product):
// zT[c*80+q][b] = sum_s h0[b,s] * (Wb[c,q,s,:] . h1[b,:])
// ---------------------------------------------------------------------------
#define A_PITCH 176
#define B_PITCH 176
#define H0_PITCHF 84
#define SB_BASE 28160
#define SB_STAGE 22528
#define SH0_BASE 73216
#define SH0_STAGE 43008
#define BIL_SMEM 159232
#define BSPLIT 2

__global__ __launch_bounds__(256, 1)
void bilq_kernel(const __half* __restrict__ Wbh,
                 const __half* __restrict__ h1h,
                 const float* __restrict__ h0g,
                 float* __restrict__ zT)
{
    extern __shared__ __align__(128) char smem[];
    const uint32_t sb = smem_u32(smem);
    const int tid = threadIdx.x;
    const int l   = tid & 31;
    const int wid = tid >> 5;
    const int wm  = wid >> 2;
    const int wn  = wid & 3;
    const int c     = blockIdx.z;
    const int q0    = blockIdx.y * 2;
    const int bhalf = blockIdx.x;
    const int NB = 64 / BSPLIT;

    {
        const size_t wb_base = (size_t)c * (SS * SS * SS) + (size_t)q0 * (SS * SS);
#pragma unroll
        for (int i = 0; i < 7; ++i) {
            int idx = tid + i * 256;
            if (idx < 1600) {
                int row = idx / 10, ch = idx % 10;
                size_t src = wb_base + (size_t)(row / 80) * (SS * SS)
                           + (size_t)(row % 80) * SS + ch * 8;
                CP16(sb + row * A_PITCH + ch * 16, (const char*)(Wbh + src));
            }
        }
    }

    auto issue_bt = [&](int st, int b0) {
        uint32_t sB = sb + SB_BASE + st * SB_STAGE;
#pragma unroll
        for (int i = 0; i < 5; ++i) {
            int idx = tid + i * 256;
            int r = idx / 10, ch = idx % 10;
            size_t src = (size_t)(b0 + r) * MM + c * SS + ch * 8;
            CP16(sB + r * B_PITCH + ch * 16, (const char*)(h1h + src));
        }
        uint32_t sH = sb + SH0_BASE + st * SH0_STAGE;
#pragma unroll
        for (int i = 0; i < 10; ++i) {
            int idx = tid + i * 256;
            int r = idx / 20, ch = idx % 20;
            size_t src = (size_t)(b0 + r) * MM + c * SS + ch * 4;
            CP16(sH + r * (H0_PITCHF * 4) + ch * 16, (const char*)(h0g + src));
        }
        CP_COMMIT();
    };

    issue_bt(0, (bhalf * NB + 0) * 128);

    const uint32_t aRowOff  = (uint32_t)(wm * 80 + (l & 15)) * A_PITCH;
    const uint32_t aHalf    = (uint32_t)(l >> 4);
    const uint32_t bRowOff  = (uint32_t)((l & 7) + ((l >> 4) << 3)) * B_PITCH;
    const uint32_t bHalf    = (uint32_t)((l >> 3) & 1);

    for (int nIt = 0; nIt < NB; ++nIt) {
        const int b0 = (bhalf * NB + nIt) * 128;
        if (nIt + 1 < NB) {
            issue_bt((nIt + 1) & 1, (bhalf * NB + nIt + 1) * 128);
            CP_WAIT1();
        } else {
            CP_WAIT0();
        }
        __syncthreads();

        const int st = nIt & 1;
        const uint32_t sA = sb;
        const uint32_t sBhi = sb + SB_BASE + st * SB_STAGE;
        const float* h0s = (const float*)(smem + SH0_BASE + st * SH0_STAGE);

        float d[5][4][4];
#pragma unroll
        for (int mt = 0; mt < 5; ++mt)
#pragma unroll
            for (int nt = 0; nt < 4; ++nt)
#pragma unroll
                for (int e = 0; e < 4; ++e) d[mt][nt][e] = 0.0f;

#pragma unroll
        for (int kk = 0; kk < 5; ++kk) {
            uint32_t ah[5][4], bh[2][4];
            const uint32_t aco = ((2 * kk + aHalf) << 4);
            const uint32_t bco = ((2 * kk + bHalf) << 4);
#pragma unroll
            for (int mt = 0; mt < 5; ++mt) {
                uint32_t off = aRowOff + mt * 16 * A_PITCH + aco;
                LDX4(ah[mt][0], ah[mt][1], ah[mt][2], ah[mt][3], sA + off);
            }
#pragma unroll
            for (int pr = 0; pr < 2; ++pr) {
                uint32_t off = (uint32_t)(wn * 32 + pr * 16) * B_PITCH + bRowOff + bco;
                LDX4(bh[pr][0], bh[pr][1], bh[pr][2], bh[pr][3], sBhi + off);
            }
#pragma unroll
            for (int mt = 0; mt < 5; ++mt) {
#pragma unroll
                for (int pr = 0; pr < 2; ++pr) {
#pragma unroll
                    for (int hh = 0; hh < 2; ++hh) {
                        int nt = pr * 2 + hh;
                        float* dd = d[mt][nt];
                        MMAH(dd[0], dd[1], dd[2], dd[3],
                             ah[mt][0], ah[mt][1], ah[mt][2], ah[mt][3],
                             bh[pr][2 * hh], bh[pr][2 * hh + 1]);
                    }
                }
            }
        }

        float p8[8];
#pragma unroll
        for (int i = 0; i < 8; ++i) p8[i] = 0.0f;
#pragma unroll
        for (int mt = 0; mt < 5; ++mt) {
#pragma unroll
            for (int e = 0; e < 4; ++e) {
                int s = mt * 16 + (l >> 2) + 8 * (e >> 1);
#pragma unroll
                for (int nt = 0; nt < 4; ++nt) {
                    int bl_ = wn * 32 + nt * 8 + 2 * (l & 3) + (e & 1);
                    p8[nt * 2 + (e & 1)] += d[mt][nt][e] * h0s[bl_ * H0_PITCHF + s];
                }
            }
        }
#pragma unroll
        for (int pi = 0; pi < 8; ++pi) {
            float v = p8[pi];
            v += __shfl_xor_sync(0xffffffffu, v, 4);
            v += __shfl_xor_sync(0xffffffffu, v, 8);
            v += __shfl_xor_sync(0xffffffffu, v, 16);
            p8[pi] = v;
        }
        if (l < 4) {
            int feat = c * SS + q0 + wm;
            float* dst = zT + (size_t)feat * BB + b0 + wn * 32 + 2 * l;
#pragma unroll
            for (int nt = 0; nt < 4; ++nt)
                *(float2*)(dst + nt * 8) = make_float2(p8[nt * 2], p8[nt * 2 + 1]);
        }
        __syncthreads();
    }
}

// ---------------------------------------------------------------------------
// norm: z = signed_sqrt(zT + bb); per-chunk L2 normalize; emit fp16.
// ---------------------------------------------------------------------------
__global__ __launch_bounds__(256)
void norm_kernel(const float* __restrict__ zT, const float* __restrict__ bbv,
                 __half* __restrict__ zh)
{
    __shared__ float zs[80 * 129];
    __shared__ float bbs[80];
    __shared__ float scl[128];
    const int tid = threadIdx.x;
    const int c = blockIdx.y;
    const int b0 = blockIdx.x * 128;

    if (tid < 80) bbs[tid] = bbv[c * SS + tid];
#pragma unroll
    for (int i = 0; i < 40; ++i) {
        int idx = tid + i * 256;
        int q = idx >> 7, col = idx & 127;
        zs[q * 129 + col] = zT[(size_t)(c * SS + q) * BB + b0 + col];
    }
    __syncthreads();
    if (tid < 128) {
        float s = 0.0f;
#pragma unroll 4
        for (int q = 0; q < 80; ++q) s += fabsf(zs[q * 129 + tid] + bbs[q]);
        scl[tid] = 1.0f / fmaxf(sqrtf(s), 1e-12f);
    }
    __syncthreads();
#pragma unroll
    for (int i = 0; i < 40; ++i) {
        int idx = tid + i * 256;
        int b = idx / 80, q = idx % 80;
        float v = zs[q * 129 + b] + bbs[q];
        float sv = copysignf(sqrtf(fabsf(v)), v) * scl[b];
        zh[(size_t)(b0 + b) * MM + c * SS + q] = __float2half(sv);
    }
}

// ---------------------------------------------------------------------------
// launch
// ---------------------------------------------------------------------------
extern "C" void kernel_launch(void* const* d_in, const int* in_sizes, int n_in,
                              void* d_out, int out_size)
{
    (void)in_sizes; (void)n_in; (void)out_size;
    const float* x0   = (const float*)d_in[0];
    const float* x1   = (const float*)d_in[1];
    const float* W0   = (const float*)d_in[2];
    const float* b0   = (const float*)d_in[3];
    const float* W1   = (const float*)d_in[4];
    const float* b1   = (const float*)d_in[5];
    const float* Wb   = (const float*)d_in[6];
    const float* bb   = (const float*)d_in[7];
    const float* Wout = (const float*)d_in[8];
    const float* bout = (const float*)d_in[9];
    float* out = (float*)d_out;

    float *h0p, *zTp;
    cudaGetSymbolAddress((void**)&h0p, g_h0);
    cudaGetSymbolAddress((void**)&zTp, g_zT);
    void *x0h, *x1h, *W0h, *W1h, *Woh, *Wbh, *h1h, *zh;
    cudaGetSymbolAddress(&x0h, g_x0h);  cudaGetSymbolAddress(&x1h, g_x1h);
    cudaGetSymbolAddress(&W0h, g_W0h);  cudaGetSymbolAddress(&W1h, g_W1h);
    cudaGetSymbolAddress(&Woh, g_Wouth);
    cudaGetSymbolAddress(&Wbh, g_Wbh);
    cudaGetSymbolAddress(&h1h, g_h1h);
    cudaGetSymbolAddress(&zh, g_zh);

    cudaFuncSetAttribute(tc_gemm_in, cudaFuncAttributeMaxDynamicSharedMemorySize, SMEM1);
    cudaFuncSetAttribute(tc_gemm_out, cudaFuncAttributeMaxDynamicSharedMemorySize, SMEM1);
    cudaFuncSetAttribute(bilq_kernel, cudaFuncAttributeMaxDynamicSharedMemorySize, BIL_SMEM);

    // converts
    {
        int n4 = BB * DIN / 4;
        dim3 g((n4 + 255) / 256, 2);
        cvt2_fp16<<<g, 256>>>(x0, (__half*)x0h, x1, (__half*)x1h, n4);
        n4 = MM * DIN / 4;
        dim3 g2((n4 + 255) / 256, 2);
        cvt2_fp16<<<g2, 256>>>(W0, (__half*)W0h, W1, (__half*)W1h, n4);
        n4 = CC * SS * SS * SS / 4;
        cvt_fp16<<<(n4 + 255) / 256, 256>>>(Wb, (__half*)Wbh, n4);
        n4 = OUTN * MM / 4;
        cvt_fp16<<<(n4 + 255) / 256, 256>>>(Wout, (__half*)Woh, n4);
    }

    // merged input GEMMs (1-product)
    {
        dim3 grid((MM + 127) / 128, BB / 128, 2);
        tc_gemm_in<<<grid, 256, SMEM1>>>(
            (const __half*)x0h, (const __half*)x1h,
            (const __half*)W0h, (const __half*)W1h,
            b0, b1, h0p, (__half*)h1h, MM, DIN);
    }

    // fused bilinear -> zT
    {
        dim3 grid(BSPLIT, SS / 2, CC);
        bilq_kernel<<<grid, 256, BIL_SMEM>>>(
            (const __half*)Wbh, (const __half*)h1h, h0p, zTp);
    }

    // bias + signed sqrt + normalize -> fp16 z
    {
        dim3 grid(BB / 128, CC);
        norm_kernel<<<grid, 256>>>(zTp, bb, (__half*)zh);
    }

    // out = z @ Wout^T + bout (1-product)
    {
        dim3 grid((OUTN + 127) / 128, BB / 128);
        tc_gemm_out<<<grid, 256, SMEM1>>>(
            (const __half*)zh, (const __half*)Woh, bout, out, OUTN, MM);
    }
}